// round 7
// baseline (speedup 1.0000x reference)
#include <cuda_runtime.h>
#include <cuda_bf16.h>
#include <math.h>
#include <stdint.h>

// ---------------------------------------------------------------------------
// DSFDecoder: B=16, C=128, H=W=64, OUT=64, CR=16, RE=8
// Upconv + refine convs via mma.sync bf16 (split hi/lo, 3 terms). Rest FFMA2.
// ---------------------------------------------------------------------------

#define PLANE 4096
#define CH    128
#define BATCH 16

typedef unsigned long long ull;

__device__ __forceinline__ void ffma2(ull& d, ull a, ull b) {
    asm("fma.rn.f32x2 %0, %1, %2, %0;" : "+l"(d) : "l"(a), "l"(b));
}
__device__ __forceinline__ ull splat2(float v) {
    ull r; asm("mov.b64 %0, {%1, %1};" : "=l"(r) : "f"(v)); return r;
}
__device__ __forceinline__ float2 unpk(ull v) {
    float2 f; asm("mov.b64 {%0, %1}, %2;" : "=f"(f.x), "=f"(f.y) : "l"(v)); return f;
}
__device__ __forceinline__ unsigned smaddr(const void* p) {
    return (unsigned)__cvta_generic_to_shared(p);
}
__device__ __forceinline__ void cp16(unsigned d, const void* s) {
    asm volatile("cp.async.cg.shared.global [%0], [%1], 16;" :: "r"(d), "l"(s) : "memory");
}
__device__ __forceinline__ void cp_commit() {
    asm volatile("cp.async.commit_group;" ::: "memory");
}
__device__ __forceinline__ void cp_wait0() {
    asm volatile("cp.async.wait_group 0;" ::: "memory");
}
__device__ __forceinline__ unsigned prmt(unsigned a, unsigned b, unsigned sel) {
    unsigned r; asm("prmt.b32 %0, %1, %2, %3;" : "=r"(r) : "r"(a), "r"(b), "r"(sel));
    return r;
}
__device__ __forceinline__ void ldsm4(unsigned* r, unsigned addr) {
    asm volatile("ldmatrix.sync.aligned.m8n8.x4.shared.b16 {%0,%1,%2,%3}, [%4];"
                 : "=r"(r[0]), "=r"(r[1]), "=r"(r[2]), "=r"(r[3]) : "r"(addr));
}
__device__ __forceinline__ void mma_bf16(float* d, const unsigned* a, unsigned b0, unsigned b1) {
    asm volatile(
        "mma.sync.aligned.m16n8k16.row.col.f32.bf16.bf16.f32 "
        "{%0,%1,%2,%3}, {%4,%5,%6,%7}, {%8,%9}, {%0,%1,%2,%3};"
        : "+f"(d[0]), "+f"(d[1]), "+f"(d[2]), "+f"(d[3])
        : "r"(a[0]), "r"(a[1]), "r"(a[2]), "r"(a[3]), "r"(b0), "r"(b1));
}
__device__ __forceinline__ unsigned packbf(float v) {
    __nv_bfloat16 h = __float2bfloat16(v);
    __nv_bfloat16 l = __float2bfloat16(v - __bfloat162float(h));
    return (unsigned)__bfloat16_as_ushort(l) | ((unsigned)__bfloat16_as_ushort(h) << 16);
}

__device__ float g_t[2][BATCH * CH * PLANE];
__device__ float g_ab[2][BATCH * CH * PLANE];
__device__ unsigned g_fu[BATCH * PLANE * CH];            // [b][pix][c] packed (lo|hi<<16) bf16
__device__ __align__(16) unsigned char g_wpack[18 * 8 * 8192]; // upconv weights
__device__ unsigned g_upb[BATCH * 16384 * 64];           // [b][y][x][o] packed up
__device__ unsigned g_treb[BATCH * 16384 * 8];           // [b][y][x][r] packed tre
__device__ __align__(16) unsigned char g_w1pack[9 * 4096];   // [tap][16rows x 128B sw] hi|+2048 lo
__device__ __align__(16) unsigned char g_w2pack[2 * 11264];  // [64 rows x 176B] hi | lo
__device__ float g_pool[2][BATCH * CH];
__device__ float g_wk[2][BATCH * CH * 9];

// ---------------- pool + mlp1 fused ----------------
__global__ void poolmlp_kernel(const float* __restrict__ x1, const float* __restrict__ x2,
                               const float* __restrict__ w1, const float* __restrict__ w2) {
    int slot = blockIdx.x >> 4;
    int b = blockIdx.x & 15;
    int tid = threadIdx.x;
    int wid = tid >> 5, lane = tid & 31;
    const float* xb = (slot ? x2 : x1) + (size_t)b * CH * PLANE;
    __shared__ float sp[128], sh[16];
    for (int k = 0; k < 16; k++) {
        int c = wid * 16 + k;
        const float4* v = (const float4*)(xb + (size_t)c * PLANE);
        float s = 0.f;
        #pragma unroll 4
        for (int i = lane; i < 1024; i += 32) {
            float4 q = v[i];
            s += q.x + q.y + q.z + q.w;
        }
        for (int off = 16; off; off >>= 1) s += __shfl_xor_sync(0xffffffffu, s, off);
        if (lane == 0) sp[c] = s * (1.f / 4096.f);
    }
    __syncthreads();
    if (tid < 16) {
        float acc = 0.f;
        #pragma unroll 8
        for (int c = 0; c < 128; c++) acc += sp[c] * w1[tid * 128 + c];
        sh[tid] = 0.5f * acc * (1.f + erff(acc * 0.70710678118654752f));
    }
    __syncthreads();
    if (tid < 128) {
        int c = tid;
        float lg[9];
        float mx = -1e30f;
        #pragma unroll
        for (int k = 0; k < 9; k++) {
            float acc = 0.f;
            #pragma unroll
            for (int r = 0; r < 16; r++) acc += sh[r] * w2[(c * 9 + k) * 16 + r];
            lg[k] = acc;
            mx = fmaxf(mx, acc);
        }
        float ss = 0.f;
        #pragma unroll
        for (int k = 0; k < 9; k++) { lg[k] = expf(lg[k] - mx); ss += lg[k]; }
        float inv = 1.f / ss;
        #pragma unroll
        for (int k = 0; k < 9; k++) g_wk[slot][(b * 128 + c) * 9 + k] = lg[k] * inv;
    }
}

// ---------------- mlp2 ----------------
__global__ void mlp_kernel(const float* __restrict__ w1, const float* __restrict__ w2) {
    int slot = blockIdx.x >> 4;
    int b = blockIdx.x & 15;
    int tid = threadIdx.x;
    __shared__ float sp[128], sh[16];
    sp[tid] = g_pool[slot][b * 128 + tid];
    __syncthreads();
    if (tid < 16) {
        float acc = 0.f;
        #pragma unroll 8
        for (int c = 0; c < 128; c++) acc += sp[c] * w1[tid * 128 + c];
        sh[tid] = 0.5f * acc * (1.f + erff(acc * 0.70710678118654752f));
    }
    __syncthreads();
    int c = tid;
    float lg[9];
    float mx = -1e30f;
    #pragma unroll
    for (int k = 0; k < 9; k++) {
        float acc = 0.f;
        #pragma unroll
        for (int r = 0; r < 16; r++) acc += sh[r] * w2[(c * 9 + k) * 16 + r];
        lg[k] = acc;
        mx = fmaxf(mx, acc);
    }
    float ss = 0.f;
    #pragma unroll
    for (int k = 0; k < 9; k++) { lg[k] = expf(lg[k] - mx); ss += lg[k]; }
    float inv = 1.f / ss;
    #pragma unroll
    for (int k = 0; k < 9; k++) g_wk[slot][(b * 128 + c) * 9 + k] = lg[k] * inv;
}

// ---------------- dsc: depthwise 3x3 + residual ----------------
__global__ void __launch_bounds__(256, 3) dsc_kernel(const float* __restrict__ x1,
                                                     const float* __restrict__ x2,
                                                     int phase) {
    int slot = blockIdx.x >> 11;
    int bc = blockIdx.x & 2047;
    const float* xext = slot ? x2 : x1;
    const float* src = phase ? &g_t[slot][(size_t)bc * PLANE]
                             : xext + (size_t)bc * PLANE;
    float* dst = phase ? &g_ab[slot][(size_t)bc * PLANE]
                       : &g_t[slot][(size_t)bc * PLANE];
    float wk[9];
    #pragma unroll
    for (int k = 0; k < 9; k++) wk[k] = g_wk[slot][bc * 9 + k];
    __shared__ float sp[66][68];
    int tid = threadIdx.x;
    if (tid < 68) { sp[0][tid] = 0.f; sp[65][tid] = 0.f; }
    if (tid < 64) { sp[tid + 1][0] = 0.f; sp[tid + 1][65] = 0.f; }
    {
        int p = tid * 16;
        int h = p >> 6, w = p & 63;
        const float4* s4 = (const float4*)(src + p);
        float4 q0 = s4[0], q1 = s4[1], q2 = s4[2], q3 = s4[3];
        float* d = &sp[h + 1][w + 1];
        d[0] = q0.x; d[1] = q0.y; d[2] = q0.z; d[3] = q0.w;
        d[4] = q1.x; d[5] = q1.y; d[6] = q1.z; d[7] = q1.w;
        d[8] = q2.x; d[9] = q2.y; d[10] = q2.z; d[11] = q2.w;
        d[12] = q3.x; d[13] = q3.y; d[14] = q3.z; d[15] = q3.w;
    }
    __syncthreads();
    int h = tid >> 2, xb = (tid & 3) * 16;
    float r0[20], r1[20], r2[20];
    #pragma unroll
    for (int k = 0; k < 5; k++) {
        *(float4*)&r0[k * 4] = *(const float4*)&sp[h + 0][xb + k * 4];
        *(float4*)&r1[k * 4] = *(const float4*)&sp[h + 1][xb + k * 4];
        *(float4*)&r2[k * 4] = *(const float4*)&sp[h + 2][xb + k * 4];
    }
    float acc[16];
    #pragma unroll
    for (int j = 0; j < 16; j++) {
        float a = r1[j + 1];
        a += wk[0] * r0[j];     a += wk[1] * r0[j + 1]; a += wk[2] * r0[j + 2];
        a += wk[3] * r1[j];     a += wk[4] * r1[j + 1]; a += wk[5] * r1[j + 2];
        a += wk[6] * r2[j];     a += wk[7] * r2[j + 1]; a += wk[8] * r2[j + 2];
        acc[j] = a;
    }
    int p = tid * 16;
    if (phase) {
        #pragma unroll
        for (int k = 0; k < 4; k++)
            *(float4*)&dst[p + k * 4] = make_float4(acc[k*4], acc[k*4+1], acc[k*4+2], acc[k*4+3]);
    } else {
        float psum = 0.f;
        #pragma unroll
        for (int j = 0; j < 16; j++) { acc[j] = fmaxf(acc[j], 0.f); psum += acc[j]; }
        #pragma unroll
        for (int k = 0; k < 4; k++)
            *(float4*)&dst[p + k * 4] = make_float4(acc[k*4], acc[k*4+1], acc[k*4+2], acc[k*4+3]);
        for (int off = 16; off; off >>= 1) psum += __shfl_xor_sync(0xffffffffu, psum, off);
        __shared__ float red[8];
        if ((tid & 31) == 0) red[tid >> 5] = psum;
        __syncthreads();
        if (tid < 32) {
            float r = (tid < 8) ? red[tid] : 0.f;
            for (int off = 4; off; off >>= 1) r += __shfl_xor_sync(0xffffffffu, r, off);
            if (tid == 0) g_pool[slot][bc] = r * (1.f / 4096.f);
        }
    }
}

// ---------------- align + weight packing ----------------
__global__ void __launch_bounds__(256, 2) alignweff_kernel(const float* __restrict__ aw,
                                                           const float* __restrict__ w1,
                                                           const float* __restrict__ w2,
                                                           const float* __restrict__ rw1,
                                                           const float* __restrict__ rw2) {
    __shared__ float smem_u[4096];
    int tid = threadIdx.x;
    if (blockIdx.x == 1024) {
        // pack re_w1 -> [tap][16 rows x 64c] sw128, hi|lo
        for (int i = tid; i < 9216; i += 256) {
            int t = i >> 10, rem = i & 1023;
            int row = rem >> 6, c = rem & 63;
            float v = (row < 8) ? rw1[(row * 64 + c) * 9 + t] : 0.f;
            unsigned off = row * 128 + c * 2;
            unsigned sw = off ^ ((off >> 3) & 0x70);
            __nv_bfloat16 hb = __float2bfloat16(v);
            __nv_bfloat16 lb = __float2bfloat16(v - __bfloat162float(hb));
            *(__nv_bfloat16*)(g_w1pack + t * 4096 + sw) = hb;
            *(__nv_bfloat16*)(g_w1pack + t * 4096 + 2048 + sw) = lb;
        }
        return;
    }
    if (blockIdx.x == 1025) {
        // pack re_w2 -> [64 rows x 88 cols (k=t*8+r, pad)] stride 176B, hi|lo
        for (int i = tid; i < 64 * 88; i += 256) {
            int o = i / 88, k = i - o * 88;
            float v = 0.f;
            if (k < 72) { int t = k >> 3, r = k & 7; v = rw2[(o * 8 + r) * 9 + t]; }
            __nv_bfloat16 hb = __float2bfloat16(v);
            __nv_bfloat16 lb = __float2bfloat16(v - __bfloat162float(hb));
            *(__nv_bfloat16*)(g_w2pack + o * 176 + k * 2) = hb;
            *(__nv_bfloat16*)(g_w2pack + 11264 + o * 176 + k * 2) = lb;
        }
        return;
    }
    if (blockIdx.x < 512) {
        // weff -> packed bf16 hi/lo tiles [o(64)][c(64)] SW128
        int sub = blockIdx.x >> 7, ci = blockIdx.x & 127;
        float* s1 = smem_u;
        for (int i = tid; i < 1152; i += 256) {
            int c = i / 9, t = i - c * 9;
            s1[i] = w1[((size_t)(c * 4 + sub) * 128 + ci) * 9 + t];
        }
        __syncthreads();
        if (tid < 64) {
            int o = tid;
            float acc[9] = {0.f,0.f,0.f,0.f,0.f,0.f,0.f,0.f,0.f};
            for (int c = 0; c < 128; c++) {
                float wv = w2[o * 128 + c];
                #pragma unroll
                for (int t = 0; t < 9; t++) acc[t] += wv * s1[c * 9 + t];
            }
            int g = ci >> 6, cl = ci & 63;
            unsigned off = ((o >> 3) << 10) + ((o & 7) << 7) + (cl << 1);
            unsigned sw = off ^ ((off >> 3) & 0x70);
            #pragma unroll
            for (int t = 0; t < 9; t++) {
                float v = acc[t];
                __nv_bfloat16 hb = __float2bfloat16(v);
                __nv_bfloat16 lb = __float2bfloat16(v - __bfloat162float(hb));
                unsigned char* base = g_wpack + ((size_t)((t * 2 + g) * 8 + sub * 2)) * 8192;
                *(__nv_bfloat16*)(base + sw) = hb;
                *(__nv_bfloat16*)(base + 8192 + sw) = lb;
            }
        }
        return;
    }
    // align: fused = concat(a,b) @ aw^T -> g_fu transposed + packed bf16 hi/lo
    int idx = blockIdx.x - 512;
    int q = idx & 3, og = (idx >> 2) & 7, b = idx >> 5;
    float (*sw_s)[16] = (float (*)[16])smem_u;
    for (int i = tid; i < 4096; i += 256) {
        int c = i >> 4, oo = i & 15;
        sw_s[c][oo] = aw[(og * 16 + oo) * 256 + c];
    }
    __syncthreads();
    int pix = q * 1024 + tid * 4;
    const float* ap = &g_ab[0][(size_t)b * CH * PLANE] + pix;
    const float* bp = &g_ab[1][(size_t)b * CH * PLANE] + pix;
    ull acc2[8][4];
    #pragma unroll
    for (int jo = 0; jo < 8; jo++)
        #pragma unroll
        for (int p = 0; p < 4; p++) acc2[jo][p] = 0ull;
    for (int c = 0; c < 128; c++) {
        float4 xv = *(const float4*)(ap + (size_t)c * PLANE);
        ull s0 = splat2(xv.x), s1 = splat2(xv.y), s2 = splat2(xv.z), s3 = splat2(xv.w);
        const ull* wp = (const ull*)&sw_s[c][0];
        #pragma unroll
        for (int jo = 0; jo < 8; jo++) {
            ull wv = wp[jo];
            ffma2(acc2[jo][0], s0, wv); ffma2(acc2[jo][1], s1, wv);
            ffma2(acc2[jo][2], s2, wv); ffma2(acc2[jo][3], s3, wv);
        }
    }
    for (int c = 0; c < 128; c++) {
        float4 xv = *(const float4*)(bp + (size_t)c * PLANE);
        ull s0 = splat2(xv.x), s1 = splat2(xv.y), s2 = splat2(xv.z), s3 = splat2(xv.w);
        const ull* wp = (const ull*)&sw_s[128 + c][0];
        #pragma unroll
        for (int jo = 0; jo < 8; jo++) {
            ull wv = wp[jo];
            ffma2(acc2[jo][0], s0, wv); ffma2(acc2[jo][1], s1, wv);
            ffma2(acc2[jo][2], s2, wv); ffma2(acc2[jo][3], s3, wv);
        }
    }
    unsigned* fb = g_fu + (size_t)b * PLANE * CH;
    #pragma unroll
    for (int p = 0; p < 4; p++) {
        unsigned wbuf[16];
        #pragma unroll
        for (int jo = 0; jo < 8; jo++) {
            float2 v = unpk(acc2[jo][p]);
            wbuf[2*jo]   = packbf(v.x);
            wbuf[2*jo+1] = packbf(v.y);
        }
        unsigned* dstw = fb + (size_t)(pix + p) * CH + og * 16;
        #pragma unroll
        for (int k = 0; k < 4; k++)
            *(uint4*)(dstw + k * 4) = *(uint4*)(wbuf + k * 4);
    }
}

// ---------------- upconv via mma.sync bf16 split --------------------------------
#define UPC_BUF 98304
#define UPC_SMEM (2 * UPC_BUF + 1024)
__global__ void __launch_bounds__(256, 1) upconv_mma(float* __restrict__ out) {
    extern __shared__ char dynraw[];
    char* base = (char*)((((uintptr_t)dynraw) + 1023) & ~(uintptr_t)1023);
    int tid = threadIdx.x;
    int w = tid >> 5, lane = tid & 31;
    int b = blockIdx.x >> 5;
    int y0 = (blockIdx.x & 31) * 2;

    const unsigned* fb = g_fu + (size_t)b * PLANE * CH;
    int m = tid >> 1, half = tid & 1;
    int mrow = m >> 6, mx = m & 63;

    float acc[4][8][4];
    #pragma unroll
    for (int s = 0; s < 4; s++)
        #pragma unroll
        for (int nf = 0; nf < 8; nf++)
            #pragma unroll
            for (int r = 0; r < 4; r++) acc[s][nf][r] = 0.f;

    auto fill = [&](int q, int buf) {
        char* bb = base + buf * UPC_BUF;
        int tap = q >> 1, g = q & 1;
        int kh = tap / 3, kw = tap - kh * 3;
        {
            const unsigned char* bsrc = g_wpack + (size_t)q * 65536;
            unsigned bdst = smaddr(bb + 32768);
            #pragma unroll 4
            for (int i = tid; i < 4096; i += 256)
                cp16(bdst + i * 16, bsrc + i * 16);
        }
        {
            int yy = y0 + mrow + kh - 1;
            int xx = mx + kw - 1;
            bool valid = ((unsigned)yy < 64u) && ((unsigned)xx < 64u);
            const uint4* s4 = (const uint4*)(fb + ((size_t)(yy * 64 + xx) * CH + g * 64 + half * 32));
            char* aHi = bb;
            char* aLo = bb + 16384;
            unsigned db = (unsigned)(m * 128 + half * 64);
            #pragma unroll
            for (int j = 0; j < 4; j++) {
                uint4 w0 = make_uint4(0u,0u,0u,0u), w1 = make_uint4(0u,0u,0u,0u);
                if (valid) { w0 = s4[2 * j]; w1 = s4[2 * j + 1]; }
                uint4 hi, lo;
                hi.x = prmt(w0.x, w0.y, 0x7632); hi.y = prmt(w0.z, w0.w, 0x7632);
                hi.z = prmt(w1.x, w1.y, 0x7632); hi.w = prmt(w1.z, w1.w, 0x7632);
                lo.x = prmt(w0.x, w0.y, 0x5410); lo.y = prmt(w0.z, w0.w, 0x5410);
                lo.z = prmt(w1.x, w1.y, 0x5410); lo.w = prmt(w1.z, w1.w, 0x5410);
                unsigned off = db + j * 16;
                unsigned sw = off ^ ((off >> 3) & 0x70);
                *(uint4*)(aHi + sw) = hi;
                *(uint4*)(aLo + sw) = lo;
            }
        }
    };

    fill(0, 0);
    cp_commit(); cp_wait0();
    __syncthreads();

    for (int q = 0; q < 18; q++) {
        int buf = q & 1;
        if (q < 17) { fill(q + 1, buf ^ 1); cp_commit(); }
        char* bb = base + buf * UPC_BUF;
        unsigned aHiB = smaddr(bb), aLoB = smaddr(bb + 16384);
        unsigned bB = smaddr(bb + 32768);
        #pragma unroll
        for (int kf = 0; kf < 4; kf++) {
            unsigned aH[4], aL[4];
            {
                unsigned arow = (unsigned)(16 * w + (lane & 15));
                unsigned aoff = arow * 128 + kf * 32 + ((lane >> 4) << 4);
                unsigned asw = aoff ^ ((aoff >> 3) & 0x70);
                ldsm4(aH, aHiB + asw);
                ldsm4(aL, aLoB + asw);
            }
            #pragma unroll
            for (int s = 0; s < 4; s++) {
                #pragma unroll
                for (int n0g = 0; n0g < 4; n0g++) {
                    unsigned brow = (unsigned)(16 * n0g + (lane & 15));
                    unsigned boff = brow * 128 + kf * 32 + ((lane >> 4) << 4);
                    unsigned bsw = boff ^ ((boff >> 3) & 0x70);
                    unsigned bH[4], bL[4];
                    ldsm4(bH, bB + s * 16384 + bsw);
                    ldsm4(bL, bB + s * 16384 + 8192 + bsw);
                    float* dA = acc[s][2 * n0g];
                    float* dB = acc[s][2 * n0g + 1];
                    mma_bf16(dA, aH, bH[0], bH[2]);
                    mma_bf16(dB, aH, bH[1], bH[3]);
                    mma_bf16(dA, aH, bL[0], bL[2]);
                    mma_bf16(dB, aH, bL[1], bL[3]);
                    mma_bf16(dA, aL, bH[0], bH[2]);
                    mma_bf16(dB, aL, bH[1], bH[3]);
                }
            }
        }
        if (q < 17) cp_wait0();
        __syncthreads();
    }

    // epilogue: pair subs -> float2 out + packed g_upb
    float2* s2 = (float2*)base;   // [128][65] float2
    unsigned* ub = g_upb + (size_t)b * 16384 * 64;
    int m0 = 16 * w + (lane >> 2);
    int ocol = (lane & 3) * 2;
    #pragma unroll
    for (int sp = 0; sp < 2; sp++) {
        __syncthreads();
        #pragma unroll
        for (int nf = 0; nf < 8; nf++) {
            int o = nf * 8 + ocol;
            s2[m0 * 65 + o]         = make_float2(acc[2*sp][nf][0], acc[2*sp+1][nf][0]);
            s2[m0 * 65 + o + 1]     = make_float2(acc[2*sp][nf][1], acc[2*sp+1][nf][1]);
            s2[(m0 + 8) * 65 + o]   = make_float2(acc[2*sp][nf][2], acc[2*sp+1][nf][2]);
            s2[(m0 + 8) * 65 + o+1] = make_float2(acc[2*sp][nf][3], acc[2*sp+1][nf][3]);
        }
        __syncthreads();
        for (int i = tid; i < 8192; i += 256) {
            int mr = i >> 12, o = (i >> 6) & 63, xx = i & 63;
            int y = 2 * (y0 + mr) + sp;
            *(float2*)(out + (((size_t)(b * 64 + o) * 128 + y) * 128 + 2 * xx)) =
                s2[(mr * 64 + xx) * 65 + o];
        }
        for (int i = tid; i < 16384; i += 256) {
            int mr = i >> 13, x2 = (i >> 6) & 127, o = i & 63;
            int y = 2 * (y0 + mr) + sp;
            float2 v = s2[(mr * 64 + (x2 >> 1)) * 65 + o];
            ub[(size_t)(y * 128 + x2) * 64 + o] = packbf((x2 & 1) ? v.y : v.x);
        }
    }
}

// ---------------- reconv1 via mma: tre = relu(conv3x3(up, re_w1)) ---------------
// grid 2048 = 16 b x 128 y; A window resident; N=8
#define RC1_SMEM (49920 + 49920 + 36864 + 1024)
__global__ void __launch_bounds__(256, 1) reconv1_mma() {
    extern __shared__ char dynraw[];
    char* base = (char*)((((uintptr_t)dynraw) + 1023) & ~(uintptr_t)1023);
    char* aHi = base;
    char* aLo = base + 49920;
    char* sB  = base + 99840;
    int tid = threadIdx.x;
    int w = tid >> 5, lane = tid & 31;
    int b = blockIdx.x >> 7;
    int y = blockIdx.x & 127;
    const unsigned* ub = g_upb + (size_t)b * 16384 * 64;

    // B: 9 taps x 4KB
    {
        unsigned bdst = smaddr(sB);
        for (int i = tid; i < 2304; i += 256)
            cp16(bdst + i * 16, g_w1pack + i * 16);
        cp_commit();
    }
    // A window: 3 rows x 130 x-slots x 64 ch, hi/lo
    for (int u = tid; u < 3120; u += 256) {
        int slot = u >> 3, j8 = u & 7;
        int r = slot / 130, xi = slot - r * 130;
        int gy = y + r - 1, gx = xi - 1;
        uint4 w0 = make_uint4(0u,0u,0u,0u), w1 = make_uint4(0u,0u,0u,0u);
        if (((unsigned)gy < 128u) && ((unsigned)gx < 128u)) {
            const uint4* src = (const uint4*)(ub + (size_t)(gy * 128 + gx) * 64 + j8 * 8);
            w0 = src[0]; w1 = src[1];
        }
        uint4 hi, lo;
        hi.x = prmt(w0.x, w0.y, 0x7632); hi.y = prmt(w0.z, w0.w, 0x7632);
        hi.z = prmt(w1.x, w1.y, 0x7632); hi.w = prmt(w1.z, w1.w, 0x7632);
        lo.x = prmt(w0.x, w0.y, 0x5410); lo.y = prmt(w0.z, w0.w, 0x5410);
        lo.z = prmt(w1.x, w1.y, 0x5410); lo.w = prmt(w1.z, w1.w, 0x5410);
        unsigned off = slot * 128 + j8 * 16;
        unsigned sw = off ^ ((off >> 3) & 0x70);
        *(uint4*)(aHi + sw) = hi;
        *(uint4*)(aLo + sw) = lo;
    }
    cp_wait0();
    __syncthreads();

    unsigned aHiB = smaddr(aHi), aLoB = smaddr(aLo), bB = smaddr(sB);
    float d[4] = {0.f, 0.f, 0.f, 0.f};
    int x0 = 16 * w;
    for (int t = 0; t < 9; t++) {
        int kh = t / 3, kw = t - kh * 3;
        int slot = kh * 130 + x0 + (lane & 15) + kw;
        #pragma unroll
        for (int kf = 0; kf < 4; kf++) {
            unsigned aH[4], aL[4], bH[4], bL[4];
            unsigned aoff = (unsigned)(slot * 128 + kf * 32 + ((lane >> 4) << 4));
            unsigned asw = aoff ^ ((aoff >> 3) & 0x70);
            ldsm4(aH, aHiB + asw);
            ldsm4(aL, aLoB + asw);
            unsigned boff = (unsigned)((lane & 15) * 128 + kf * 32 + ((lane >> 4) << 4));
            unsigned bsw = boff ^ ((boff >> 3) & 0x70);
            ldsm4(bH, bB + t * 4096 + bsw);
            ldsm4(bL, bB + t * 4096 + 2048 + bsw);
            mma_bf16(d, aH, bH[0], bH[2]);
            mma_bf16(d, aH, bL[0], bL[2]);
            mma_bf16(d, aL, bH[0], bH[2]);
        }
    }
    // store tre packed
    unsigned* tb = g_treb + ((size_t)b * 16384 + y * 128) * 8;
    int r = lane >> 2, c = (lane & 3) * 2;
    int px = x0 + r;
    tb[px * 8 + c]           = packbf(fmaxf(d[0], 0.f));
    tb[px * 8 + c + 1]       = packbf(fmaxf(d[1], 0.f));
    tb[(px + 8) * 8 + c]     = packbf(fmaxf(d[2], 0.f));
    tb[(px + 8) * 8 + c + 1] = packbf(fmaxf(d[3], 0.f));
}

// ---------------- reconv2 via mma: out += conv3x3(tre, re_w2) -------------------
// grid 2048 = 16 b x 128 y; im2col K=80 (72+pad), 176B rows (no swizzle)
#define RC2_SMEM (12480 + 22528 + 22528 + 22528 + 1024)
__global__ void __launch_bounds__(256, 2) reconv2_mma(float* __restrict__ out) {
    extern __shared__ char dynraw2[];
    char* base = (char*)((((uintptr_t)dynraw2) + 1023) & ~(uintptr_t)1023);
    unsigned* sTre = (unsigned*)base;            // 3*130*8 = 3120 words
    char* aHi = base + 12480;
    char* aLo = base + 12480 + 22528;
    char* sB  = base + 12480 + 45056;
    int tid = threadIdx.x;
    int w = tid >> 5, lane = tid & 31;
    int b = blockIdx.x >> 7;
    int y = blockIdx.x & 127;
    const unsigned* tb = g_treb + (size_t)b * 16384 * 8;

    {
        unsigned bdst = smaddr(sB);
        for (int i = tid; i < 1408; i += 256)
            cp16(bdst + i * 16, g_w2pack + i * 16);
        cp_commit();
    }
    for (int u = tid; u < 780; u += 256) {
        int slot = u >> 1, hf = u & 1;
        int r = slot / 130, xi = slot - r * 130;
        int gy = y + r - 1, gx = xi - 1;
        uint4 v = make_uint4(0u,0u,0u,0u);
        if (((unsigned)gy < 128u) && ((unsigned)gx < 128u))
            v = *((const uint4*)(tb + (size_t)(gy * 128 + gx) * 8) + hf);
        *((uint4*)(sTre + slot * 8) + hf) = v;
    }
    __syncthreads();
    // build im2col: 128 px x 9 taps x 8 ch
    for (int u = tid; u < 1152; u += 256) {
        int x = u / 9, t = u - x * 9;
        int kh = t / 3, kw = t - kh * 3;
        const unsigned* src = sTre + (kh * 130 + x + kw) * 8;
        uint4 w0 = *(const uint4*)src;
        uint4 w1 = *(const uint4*)(src + 4);
        uint4 hi, lo;
        hi.x = prmt(w0.x, w0.y, 0x7632); hi.y = prmt(w0.z, w0.w, 0x7632);
        hi.z = prmt(w1.x, w1.y, 0x7632); hi.w = prmt(w1.z, w1.w, 0x7632);
        lo.x = prmt(w0.x, w0.y, 0x5410); lo.y = prmt(w0.z, w0.w, 0x5410);
        lo.z = prmt(w1.x, w1.y, 0x5410); lo.w = prmt(w1.z, w1.w, 0x5410);
        *(uint4*)(aHi + x * 176 + t * 16) = hi;
        *(uint4*)(aLo + x * 176 + t * 16) = lo;
    }
    for (int u = tid; u < 128; u += 256) {
        uint4 z = make_uint4(0u,0u,0u,0u);
        *(uint4*)(aHi + u * 176 + 144) = z;
        *(uint4*)(aLo + u * 176 + 144) = z;
    }
    cp_wait0();
    __syncthreads();

    unsigned aHiB = smaddr(aHi), aLoB = smaddr(aLo), bB = smaddr(sB);
    float acc[4][2][4];
    #pragma unroll
    for (int g = 0; g < 4; g++)
        #pragma unroll
        for (int nf = 0; nf < 2; nf++)
            #pragma unroll
            for (int r = 0; r < 4; r++) acc[g][nf][r] = 0.f;
    int x0 = 16 * w;
    #pragma unroll
    for (int kf = 0; kf < 5; kf++) {
        unsigned aH[4], aL[4];
        unsigned aoff = (unsigned)((x0 + (lane & 15)) * 176 + kf * 32 + ((lane >> 4) << 4));
        ldsm4(aH, aHiB + aoff);
        ldsm4(aL, aLoB + aoff);
        #pragma unroll
        for (int n0g = 0; n0g < 4; n0g++) {
            unsigned bH[4], bL[4];
            unsigned boff = (unsigned)((16 * n0g + (lane & 15)) * 176 + kf * 32 + ((lane >> 4) << 4));
            ldsm4(bH, bB + boff);
            ldsm4(bL, bB + 11264 + boff);
            float* dA = acc[n0g][0];
            float* dB = acc[n0g][1];
            mma_bf16(dA, aH, bH[0], bH[2]);
            mma_bf16(dB, aH, bH[1], bH[3]);
            mma_bf16(dA, aH, bL[0], bL[2]);
            mma_bf16(dB, aH, bL[1], bL[3]);
            mma_bf16(dA, aL, bH[0], bH[2]);
            mma_bf16(dB, aL, bH[1], bH[3]);
        }
    }
    __syncthreads();
    float* sD = (float*)aHi;   // [128][65]
    {
        int r = lane >> 2, c = (lane & 3) * 2;
        int px = x0 + r;
        #pragma unroll
        for (int n0g = 0; n0g < 4; n0g++)
            #pragma unroll
            for (int nf = 0; nf < 2; nf++) {
                int o = n0g * 16 + nf * 8 + c;
                sD[px * 65 + o]           = acc[n0g][nf][0];
                sD[px * 65 + o + 1]       = acc[n0g][nf][1];
                sD[(px + 8) * 65 + o]     = acc[n0g][nf][2];
                sD[(px + 8) * 65 + o + 1] = acc[n0g][nf][3];
            }
    }
    __syncthreads();
    for (int i = tid; i < 8192; i += 256) {
        int o = i >> 7, x = i & 127;
        out[((size_t)(b * 64 + o) * 128 + y) * 128 + x] += sD[x * 65 + o];
    }
}

// ---------------------------------------------------------------------------
extern "C" void kernel_launch(void* const* d_in, const int* in_sizes, int n_in,
                              void* d_out, int out_size) {
    const float* x1    = (const float*)d_in[0];
    const float* x2    = (const float*)d_in[1];
    const float* d1_w1 = (const float*)d_in[2];
    const float* d1_w2 = (const float*)d_in[3];
    const float* d2_w1 = (const float*)d_in[4];
    const float* d2_w2 = (const float*)d_in[5];
    const float* align_w = (const float*)d_in[6];
    const float* up_w1 = (const float*)d_in[7];
    const float* up_w2 = (const float*)d_in[8];
    const float* re_w1 = (const float*)d_in[9];
    const float* re_w2 = (const float*)d_in[10];
    float* out = (float*)d_out;

    static int smem_set = 0;
    if (!smem_set) {
        cudaFuncSetAttribute(upconv_mma, cudaFuncAttributeMaxDynamicSharedMemorySize, UPC_SMEM);
        cudaFuncSetAttribute(reconv1_mma, cudaFuncAttributeMaxDynamicSharedMemorySize, RC1_SMEM);
        cudaFuncSetAttribute(reconv2_mma, cudaFuncAttributeMaxDynamicSharedMemorySize, RC2_SMEM);
        smem_set = 1;
    }

    poolmlp_kernel<<<32, 256>>>(x1, x2, d1_w1, d1_w2);
    dsc_kernel<<<4096, 256>>>(x1, x2, 0);
    mlp_kernel<<<32, 128>>>(d2_w1, d2_w2);
    dsc_kernel<<<4096, 256>>>(x1, x2, 1);
    alignweff_kernel<<<1026, 256>>>(align_w, up_w1, up_w2, re_w1, re_w2);
    upconv_mma<<<512, 256, UPC_SMEM>>>(out);
    reconv1_mma<<<2048, 256, RC1_SMEM>>>();
    reconv2_mma<<<2048, 256, RC2_SMEM>>>(out);
}

// round 8
// speedup vs baseline: 1.0312x; 1.0312x over previous
#include <cuda_runtime.h>
#include <cuda_bf16.h>
#include <math.h>
#include <stdint.h>

// ---------------------------------------------------------------------------
// DSFDecoder: B=16, C=128, H=W=64, OUT=64, CR=16, RE=8
// Upconv + refine convs via mma.sync bf16 (split hi/lo, 3 terms). Rest FFMA2.
// R8: fused stored as separate hi/lo bf16 planes -> upconv A fill is pure cp.async.
// ---------------------------------------------------------------------------

#define PLANE 4096
#define CH    128
#define BATCH 16

typedef unsigned long long ull;

__device__ __forceinline__ void ffma2(ull& d, ull a, ull b) {
    asm("fma.rn.f32x2 %0, %1, %2, %0;" : "+l"(d) : "l"(a), "l"(b));
}
__device__ __forceinline__ ull splat2(float v) {
    ull r; asm("mov.b64 %0, {%1, %1};" : "=l"(r) : "f"(v)); return r;
}
__device__ __forceinline__ float2 unpk(ull v) {
    float2 f; asm("mov.b64 {%0, %1}, %2;" : "=f"(f.x), "=f"(f.y) : "l"(v)); return f;
}
__device__ __forceinline__ unsigned smaddr(const void* p) {
    return (unsigned)__cvta_generic_to_shared(p);
}
__device__ __forceinline__ void cp16(unsigned d, const void* s) {
    asm volatile("cp.async.cg.shared.global [%0], [%1], 16;" :: "r"(d), "l"(s) : "memory");
}
__device__ __forceinline__ void cp16z(unsigned d, const void* s, int valid) {
    asm volatile("cp.async.cg.shared.global [%0], [%1], 16, %2;"
                 :: "r"(d), "l"(s), "r"(valid ? 16 : 0) : "memory");
}
__device__ __forceinline__ void cp_commit() {
    asm volatile("cp.async.commit_group;" ::: "memory");
}
__device__ __forceinline__ void cp_wait0() {
    asm volatile("cp.async.wait_group 0;" ::: "memory");
}
__device__ __forceinline__ unsigned prmt(unsigned a, unsigned b, unsigned sel) {
    unsigned r; asm("prmt.b32 %0, %1, %2, %3;" : "=r"(r) : "r"(a), "r"(b), "r"(sel));
    return r;
}
__device__ __forceinline__ void ldsm4(unsigned* r, unsigned addr) {
    asm volatile("ldmatrix.sync.aligned.m8n8.x4.shared.b16 {%0,%1,%2,%3}, [%4];"
                 : "=r"(r[0]), "=r"(r[1]), "=r"(r[2]), "=r"(r[3]) : "r"(addr));
}
__device__ __forceinline__ void mma_bf16(float* d, const unsigned* a, unsigned b0, unsigned b1) {
    asm volatile(
        "mma.sync.aligned.m16n8k16.row.col.f32.bf16.bf16.f32 "
        "{%0,%1,%2,%3}, {%4,%5,%6,%7}, {%8,%9}, {%0,%1,%2,%3};"
        : "+f"(d[0]), "+f"(d[1]), "+f"(d[2]), "+f"(d[3])
        : "r"(a[0]), "r"(a[1]), "r"(a[2]), "r"(a[3]), "r"(b0), "r"(b1));
}
__device__ __forceinline__ unsigned packbf(float v) {
    __nv_bfloat16 h = __float2bfloat16(v);
    __nv_bfloat16 l = __float2bfloat16(v - __bfloat162float(h));
    return (unsigned)__bfloat16_as_ushort(l) | ((unsigned)__bfloat16_as_ushort(h) << 16);
}
__device__ __forceinline__ unsigned bfhi(float v) {   // bf16 bits of hi part
    return (unsigned)__bfloat16_as_ushort(__float2bfloat16(v));
}
__device__ __forceinline__ unsigned bflo(float v) {   // bf16 bits of lo part
    __nv_bfloat16 h = __float2bfloat16(v);
    return (unsigned)__bfloat16_as_ushort(__float2bfloat16(v - __bfloat162float(h)));
}

__device__ float g_t[2][BATCH * CH * PLANE];
__device__ float g_ab[2][BATCH * CH * PLANE];
__device__ unsigned g_fuH[BATCH * PLANE * 64];           // [b][pix][c-pair] hi-plane bf16x2
__device__ unsigned g_fuL[BATCH * PLANE * 64];           // lo-plane
__device__ __align__(16) unsigned char g_wpack[18 * 8 * 8192]; // upconv weights
__device__ unsigned g_upb[BATCH * 16384 * 64];           // [b][y][x][o] packed up
__device__ unsigned g_treb[BATCH * 16384 * 8];           // [b][y][x][r] packed tre
__device__ __align__(16) unsigned char g_w1pack[9 * 4096];   // [tap][16rows x 128B sw] hi|+2048 lo
__device__ __align__(16) unsigned char g_w2pack[2 * 11264];  // [64 rows x 176B] hi | lo
__device__ float g_pool[2][BATCH * CH];
__device__ float g_wk[2][BATCH * CH * 9];

// ---------------- pool + mlp1 fused ----------------
__global__ void poolmlp_kernel(const float* __restrict__ x1, const float* __restrict__ x2,
                               const float* __restrict__ w1, const float* __restrict__ w2) {
    int slot = blockIdx.x >> 4;
    int b = blockIdx.x & 15;
    int tid = threadIdx.x;
    int wid = tid >> 5, lane = tid & 31;
    const float* xb = (slot ? x2 : x1) + (size_t)b * CH * PLANE;
    __shared__ float sp[128], sh[16];
    for (int k = 0; k < 16; k++) {
        int c = wid * 16 + k;
        const float4* v = (const float4*)(xb + (size_t)c * PLANE);
        float s = 0.f;
        #pragma unroll 4
        for (int i = lane; i < 1024; i += 32) {
            float4 q = v[i];
            s += q.x + q.y + q.z + q.w;
        }
        for (int off = 16; off; off >>= 1) s += __shfl_xor_sync(0xffffffffu, s, off);
        if (lane == 0) sp[c] = s * (1.f / 4096.f);
    }
    __syncthreads();
    if (tid < 16) {
        float acc = 0.f;
        #pragma unroll 8
        for (int c = 0; c < 128; c++) acc += sp[c] * w1[tid * 128 + c];
        sh[tid] = 0.5f * acc * (1.f + erff(acc * 0.70710678118654752f));
    }
    __syncthreads();
    if (tid < 128) {
        int c = tid;
        float lg[9];
        float mx = -1e30f;
        #pragma unroll
        for (int k = 0; k < 9; k++) {
            float acc = 0.f;
            #pragma unroll
            for (int r = 0; r < 16; r++) acc += sh[r] * w2[(c * 9 + k) * 16 + r];
            lg[k] = acc;
            mx = fmaxf(mx, acc);
        }
        float ss = 0.f;
        #pragma unroll
        for (int k = 0; k < 9; k++) { lg[k] = expf(lg[k] - mx); ss += lg[k]; }
        float inv = 1.f / ss;
        #pragma unroll
        for (int k = 0; k < 9; k++) g_wk[slot][(b * 128 + c) * 9 + k] = lg[k] * inv;
    }
}

// ---------------- mlp2 ----------------
__global__ void mlp_kernel(const float* __restrict__ w1, const float* __restrict__ w2) {
    int slot = blockIdx.x >> 4;
    int b = blockIdx.x & 15;
    int tid = threadIdx.x;
    __shared__ float sp[128], sh[16];
    sp[tid] = g_pool[slot][b * 128 + tid];
    __syncthreads();
    if (tid < 16) {
        float acc = 0.f;
        #pragma unroll 8
        for (int c = 0; c < 128; c++) acc += sp[c] * w1[tid * 128 + c];
        sh[tid] = 0.5f * acc * (1.f + erff(acc * 0.70710678118654752f));
    }
    __syncthreads();
    int c = tid;
    float lg[9];
    float mx = -1e30f;
    #pragma unroll
    for (int k = 0; k < 9; k++) {
        float acc = 0.f;
        #pragma unroll
        for (int r = 0; r < 16; r++) acc += sh[r] * w2[(c * 9 + k) * 16 + r];
        lg[k] = acc;
        mx = fmaxf(mx, acc);
    }
    float ss = 0.f;
    #pragma unroll
    for (int k = 0; k < 9; k++) { lg[k] = expf(lg[k] - mx); ss += lg[k]; }
    float inv = 1.f / ss;
    #pragma unroll
    for (int k = 0; k < 9; k++) g_wk[slot][(b * 128 + c) * 9 + k] = lg[k] * inv;
}

// ---------------- dsc: depthwise 3x3 + residual ----------------
__global__ void __launch_bounds__(256, 4) dsc_kernel(const float* __restrict__ x1,
                                                     const float* __restrict__ x2,
                                                     int phase) {
    int slot = blockIdx.x >> 11;
    int bc = blockIdx.x & 2047;
    const float* xext = slot ? x2 : x1;
    const float* src = phase ? &g_t[slot][(size_t)bc * PLANE]
                             : xext + (size_t)bc * PLANE;
    float* dst = phase ? &g_ab[slot][(size_t)bc * PLANE]
                       : &g_t[slot][(size_t)bc * PLANE];
    float wk[9];
    #pragma unroll
    for (int k = 0; k < 9; k++) wk[k] = g_wk[slot][bc * 9 + k];
    __shared__ float sp[66][68];
    int tid = threadIdx.x;
    if (tid < 68) { sp[0][tid] = 0.f; sp[65][tid] = 0.f; }
    if (tid < 64) { sp[tid + 1][0] = 0.f; sp[tid + 1][65] = 0.f; }
    {
        int p = tid * 16;
        int h = p >> 6, w = p & 63;
        const float4* s4 = (const float4*)(src + p);
        float4 q0 = s4[0], q1 = s4[1], q2 = s4[2], q3 = s4[3];
        float* d = &sp[h + 1][w + 1];
        d[0] = q0.x; d[1] = q0.y; d[2] = q0.z; d[3] = q0.w;
        d[4] = q1.x; d[5] = q1.y; d[6] = q1.z; d[7] = q1.w;
        d[8] = q2.x; d[9] = q2.y; d[10] = q2.z; d[11] = q2.w;
        d[12] = q3.x; d[13] = q3.y; d[14] = q3.z; d[15] = q3.w;
    }
    __syncthreads();
    int h = tid >> 2, xb = (tid & 3) * 16;
    float r0[20], r1[20], r2[20];
    #pragma unroll
    for (int k = 0; k < 5; k++) {
        *(float4*)&r0[k * 4] = *(const float4*)&sp[h + 0][xb + k * 4];
        *(float4*)&r1[k * 4] = *(const float4*)&sp[h + 1][xb + k * 4];
        *(float4*)&r2[k * 4] = *(const float4*)&sp[h + 2][xb + k * 4];
    }
    float acc[16];
    #pragma unroll
    for (int j = 0; j < 16; j++) {
        float a = r1[j + 1];
        a += wk[0] * r0[j];     a += wk[1] * r0[j + 1]; a += wk[2] * r0[j + 2];
        a += wk[3] * r1[j];     a += wk[4] * r1[j + 1]; a += wk[5] * r1[j + 2];
        a += wk[6] * r2[j];     a += wk[7] * r2[j + 1]; a += wk[8] * r2[j + 2];
        acc[j] = a;
    }
    int p = tid * 16;
    if (phase) {
        #pragma unroll
        for (int k = 0; k < 4; k++)
            *(float4*)&dst[p + k * 4] = make_float4(acc[k*4], acc[k*4+1], acc[k*4+2], acc[k*4+3]);
    } else {
        float psum = 0.f;
        #pragma unroll
        for (int j = 0; j < 16; j++) { acc[j] = fmaxf(acc[j], 0.f); psum += acc[j]; }
        #pragma unroll
        for (int k = 0; k < 4; k++)
            *(float4*)&dst[p + k * 4] = make_float4(acc[k*4], acc[k*4+1], acc[k*4+2], acc[k*4+3]);
        for (int off = 16; off; off >>= 1) psum += __shfl_xor_sync(0xffffffffu, psum, off);
        __shared__ float red[8];
        if ((tid & 31) == 0) red[tid >> 5] = psum;
        __syncthreads();
        if (tid < 32) {
            float r = (tid < 8) ? red[tid] : 0.f;
            for (int off = 4; off; off >>= 1) r += __shfl_xor_sync(0xffffffffu, r, off);
            if (tid == 0) g_pool[slot][bc] = r * (1.f / 4096.f);
        }
    }
}

// ---------------- align + weight packing ----------------
__global__ void __launch_bounds__(256, 2) alignweff_kernel(const float* __restrict__ aw,
                                                           const float* __restrict__ w1,
                                                           const float* __restrict__ w2,
                                                           const float* __restrict__ rw1,
                                                           const float* __restrict__ rw2) {
    __shared__ float smem_u[4096];
    int tid = threadIdx.x;
    if (blockIdx.x == 1024) {
        for (int i = tid; i < 9216; i += 256) {
            int t = i >> 10, rem = i & 1023;
            int row = rem >> 6, c = rem & 63;
            float v = (row < 8) ? rw1[(row * 64 + c) * 9 + t] : 0.f;
            unsigned off = row * 128 + c * 2;
            unsigned sw = off ^ ((off >> 3) & 0x70);
            __nv_bfloat16 hb = __float2bfloat16(v);
            __nv_bfloat16 lb = __float2bfloat16(v - __bfloat162float(hb));
            *(__nv_bfloat16*)(g_w1pack + t * 4096 + sw) = hb;
            *(__nv_bfloat16*)(g_w1pack + t * 4096 + 2048 + sw) = lb;
        }
        return;
    }
    if (blockIdx.x == 1025) {
        for (int i = tid; i < 64 * 88; i += 256) {
            int o = i / 88, k = i - o * 88;
            float v = 0.f;
            if (k < 72) { int t = k >> 3, r = k & 7; v = rw2[(o * 8 + r) * 9 + t]; }
            __nv_bfloat16 hb = __float2bfloat16(v);
            __nv_bfloat16 lb = __float2bfloat16(v - __bfloat162float(hb));
            *(__nv_bfloat16*)(g_w2pack + o * 176 + k * 2) = hb;
            *(__nv_bfloat16*)(g_w2pack + 11264 + o * 176 + k * 2) = lb;
        }
        return;
    }
    if (blockIdx.x < 512) {
        int sub = blockIdx.x >> 7, ci = blockIdx.x & 127;
        float* s1 = smem_u;
        for (int i = tid; i < 1152; i += 256) {
            int c = i / 9, t = i - c * 9;
            s1[i] = w1[((size_t)(c * 4 + sub) * 128 + ci) * 9 + t];
        }
        __syncthreads();
        if (tid < 64) {
            int o = tid;
            float acc[9] = {0.f,0.f,0.f,0.f,0.f,0.f,0.f,0.f,0.f};
            for (int c = 0; c < 128; c++) {
                float wv = w2[o * 128 + c];
                #pragma unroll
                for (int t = 0; t < 9; t++) acc[t] += wv * s1[c * 9 + t];
            }
            int g = ci >> 6, cl = ci & 63;
            unsigned off = ((o >> 3) << 10) + ((o & 7) << 7) + (cl << 1);
            unsigned sw = off ^ ((off >> 3) & 0x70);
            #pragma unroll
            for (int t = 0; t < 9; t++) {
                float v = acc[t];
                __nv_bfloat16 hb = __float2bfloat16(v);
                __nv_bfloat16 lb = __float2bfloat16(v - __bfloat162float(hb));
                unsigned char* base = g_wpack + ((size_t)((t * 2 + g) * 8 + sub * 2)) * 8192;
                *(__nv_bfloat16*)(base + sw) = hb;
                *(__nv_bfloat16*)(base + 8192 + sw) = lb;
            }
        }
        return;
    }
    // align: fused = concat(a,b) @ aw^T -> hi/lo bf16 planes [pix][c]
    int idx = blockIdx.x - 512;
    int q = idx & 3, og = (idx >> 2) & 7, b = idx >> 5;
    float (*sw_s)[16] = (float (*)[16])smem_u;
    for (int i = tid; i < 4096; i += 256) {
        int c = i >> 4, oo = i & 15;
        sw_s[c][oo] = aw[(og * 16 + oo) * 256 + c];
    }
    __syncthreads();
    int pix = q * 1024 + tid * 4;
    const float* ap = &g_ab[0][(size_t)b * CH * PLANE] + pix;
    const float* bp = &g_ab[1][(size_t)b * CH * PLANE] + pix;
    ull acc2[8][4];
    #pragma unroll
    for (int jo = 0; jo < 8; jo++)
        #pragma unroll
        for (int p = 0; p < 4; p++) acc2[jo][p] = 0ull;
    for (int c = 0; c < 128; c++) {
        float4 xv = *(const float4*)(ap + (size_t)c * PLANE);
        ull s0 = splat2(xv.x), s1 = splat2(xv.y), s2 = splat2(xv.z), s3 = splat2(xv.w);
        const ull* wp = (const ull*)&sw_s[c][0];
        #pragma unroll
        for (int jo = 0; jo < 8; jo++) {
            ull wv = wp[jo];
            ffma2(acc2[jo][0], s0, wv); ffma2(acc2[jo][1], s1, wv);
            ffma2(acc2[jo][2], s2, wv); ffma2(acc2[jo][3], s3, wv);
        }
    }
    for (int c = 0; c < 128; c++) {
        float4 xv = *(const float4*)(bp + (size_t)c * PLANE);
        ull s0 = splat2(xv.x), s1 = splat2(xv.y), s2 = splat2(xv.z), s3 = splat2(xv.w);
        const ull* wp = (const ull*)&sw_s[128 + c][0];
        #pragma unroll
        for (int jo = 0; jo < 8; jo++) {
            ull wv = wp[jo];
            ffma2(acc2[jo][0], s0, wv); ffma2(acc2[jo][1], s1, wv);
            ffma2(acc2[jo][2], s2, wv); ffma2(acc2[jo][3], s3, wv);
        }
    }
    // per pixel p, channels og*16..+15: 8 hi words + 8 lo words (c-pairs)
    unsigned* fH = g_fuH + (size_t)b * PLANE * 64;
    unsigned* fL = g_fuL + (size_t)b * PLANE * 64;
    #pragma unroll
    for (int p = 0; p < 4; p++) {
        unsigned hbuf[8], lbuf[8];
        #pragma unroll
        for (int jo = 0; jo < 8; jo++) {
            float2 v = unpk(acc2[jo][p]);
            hbuf[jo] = bfhi(v.x) | (bfhi(v.y) << 16);
            lbuf[jo] = bflo(v.x) | (bflo(v.y) << 16);
        }
        unsigned* dH = fH + (size_t)(pix + p) * 64 + og * 8;
        unsigned* dL = fL + (size_t)(pix + p) * 64 + og * 8;
        *(uint4*)(dH) = *(uint4*)(hbuf);
        *(uint4*)(dH + 4) = *(uint4*)(hbuf + 4);
        *(uint4*)(dL) = *(uint4*)(lbuf);
        *(uint4*)(dL + 4) = *(uint4*)(lbuf + 4);
    }
}

// ---------------- upconv via mma.sync bf16 split, fully async fills -------------
#define UPC_BUF 98304
#define UPC_SMEM (2 * UPC_BUF + 1024)
__global__ void __launch_bounds__(256, 1) upconv_mma(float* __restrict__ out) {
    extern __shared__ char dynraw[];
    char* base = (char*)((((uintptr_t)dynraw) + 1023) & ~(uintptr_t)1023);
    int tid = threadIdx.x;
    int w = tid >> 5, lane = tid & 31;
    int b = blockIdx.x >> 5;
    int y0 = (blockIdx.x & 31) * 2;

    const unsigned* fH = g_fuH + (size_t)b * PLANE * 64;
    const unsigned* fL = g_fuL + (size_t)b * PLANE * 64;
    int m = tid >> 1, plane = tid & 1;
    int mrow = m >> 6, mx = m & 63;

    float acc[4][8][4];
    #pragma unroll
    for (int s = 0; s < 4; s++)
        #pragma unroll
        for (int nf = 0; nf < 8; nf++)
            #pragma unroll
            for (int r = 0; r < 4; r++) acc[s][nf][r] = 0.f;

    auto fill = [&](int q, int buf) {
        char* bb = base + buf * UPC_BUF;
        int tap = q >> 1, g = q & 1;
        int kh = tap / 3, kw = tap - kh * 3;
        // B: 64KB
        {
            const unsigned char* bsrc = g_wpack + (size_t)q * 65536;
            unsigned bdst = smaddr(bb + 32768);
            #pragma unroll 4
            for (int i = tid; i < 4096; i += 256)
                cp16(bdst + i * 16, bsrc + i * 16);
        }
        // A: thread -> (pixel m, plane) row of 64 ch = 128B = 8 cp16
        {
            int yy = y0 + mrow + kh - 1;
            int xx = mx + kw - 1;
            int valid = (((unsigned)yy < 64u) && ((unsigned)xx < 64u)) ? 1 : 0;
            const unsigned* src = (plane ? fL : fH) + ((size_t)(yy * 64 + xx) * 64 + g * 32);
            unsigned dstb = smaddr(bb + plane * 16384);
            unsigned db = (unsigned)(m * 128);
            #pragma unroll
            for (int j = 0; j < 8; j++) {
                unsigned off = db + j * 16;
                unsigned sw = off ^ ((off >> 3) & 0x70);
                cp16z(dstb + sw, src + j * 4, valid);
            }
        }
    };

    fill(0, 0);
    cp_commit(); cp_wait0();
    __syncthreads();

    for (int q = 0; q < 18; q++) {
        int buf = q & 1;
        if (q < 17) { fill(q + 1, buf ^ 1); cp_commit(); }
        char* bb = base + buf * UPC_BUF;
        unsigned aHiB = smaddr(bb), aLoB = smaddr(bb + 16384);
        unsigned bB = smaddr(bb + 32768);
        #pragma unroll
        for (int kf = 0; kf < 4; kf++) {
            unsigned aH[4], aL[4];
            {
                unsigned arow = (unsigned)(16 * w + (lane & 15));
                unsigned aoff = arow * 128 + kf * 32 + ((lane >> 4) << 4);
                unsigned asw = aoff ^ ((aoff >> 3) & 0x70);
                ldsm4(aH, aHiB + asw);
                ldsm4(aL, aLoB + asw);
            }
            #pragma unroll
            for (int s = 0; s < 4; s++) {
                #pragma unroll
                for (int n0g = 0; n0g < 4; n0g++) {
                    unsigned brow = (unsigned)(16 * n0g + (lane & 15));
                    unsigned boff = brow * 128 + kf * 32 + ((lane >> 4) << 4);
                    unsigned bsw = boff ^ ((boff >> 3) & 0x70);
                    unsigned bH[4], bL[4];
                    ldsm4(bH, bB + s * 16384 + bsw);
                    ldsm4(bL, bB + s * 16384 + 8192 + bsw);
                    float* dA = acc[s][2 * n0g];
                    float* dB = acc[s][2 * n0g + 1];
                    mma_bf16(dA, aH, bH[0], bH[2]);
                    mma_bf16(dB, aH, bH[1], bH[3]);
                    mma_bf16(dA, aH, bL[0], bL[2]);
                    mma_bf16(dB, aH, bL[1], bL[3]);
                    mma_bf16(dA, aL, bH[0], bH[2]);
                    mma_bf16(dB, aL, bH[1], bH[3]);
                }
            }
        }
        if (q < 17) cp_wait0();
        __syncthreads();
    }

    // epilogue: pair subs -> float2 out + packed g_upb
    float2* s2 = (float2*)base;   // [128][65] float2
    unsigned* ub = g_upb + (size_t)b * 16384 * 64;
    int m0 = 16 * w + (lane >> 2);
    int ocol = (lane & 3) * 2;
    #pragma unroll
    for (int sp = 0; sp < 2; sp++) {
        __syncthreads();
        #pragma unroll
        for (int nf = 0; nf < 8; nf++) {
            int o = nf * 8 + ocol;
            s2[m0 * 65 + o]         = make_float2(acc[2*sp][nf][0], acc[2*sp+1][nf][0]);
            s2[m0 * 65 + o + 1]     = make_float2(acc[2*sp][nf][1], acc[2*sp+1][nf][1]);
            s2[(m0 + 8) * 65 + o]   = make_float2(acc[2*sp][nf][2], acc[2*sp+1][nf][2]);
            s2[(m0 + 8) * 65 + o+1] = make_float2(acc[2*sp][nf][3], acc[2*sp+1][nf][3]);
        }
        __syncthreads();
        for (int i = tid; i < 8192; i += 256) {
            int mr = i >> 12, o = (i >> 6) & 63, xx = i & 63;
            int y = 2 * (y0 + mr) + sp;
            *(float2*)(out + (((size_t)(b * 64 + o) * 128 + y) * 128 + 2 * xx)) =
                s2[(mr * 64 + xx) * 65 + o];
        }
        for (int i = tid; i < 16384; i += 256) {
            int mr = i >> 13, x2 = (i >> 6) & 127, o = i & 63;
            int y = 2 * (y0 + mr) + sp;
            float2 v = s2[(mr * 64 + (x2 >> 1)) * 65 + o];
            ub[(size_t)(y * 128 + x2) * 64 + o] = packbf((x2 & 1) ? v.y : v.x);
        }
    }
}

// ---------------- reconv1 via mma: tre = relu(conv3x3(up, re_w1)) ---------------
#define RC1_SMEM (49920 + 49920 + 36864 + 1024)
__global__ void __launch_bounds__(256, 1) reconv1_mma() {
    extern __shared__ char dynraw[];
    char* base = (char*)((((uintptr_t)dynraw) + 1023) & ~(uintptr_t)1023);
    char* aHi = base;
    char* aLo = base + 49920;
    char* sB  = base + 99840;
    int tid = threadIdx.x;
    int w = tid >> 5, lane = tid & 31;
    int b = blockIdx.x >> 7;
    int y = blockIdx.x & 127;
    const unsigned* ub = g_upb + (size_t)b * 16384 * 64;

    {
        unsigned bdst = smaddr(sB);
        for (int i = tid; i < 2304; i += 256)
            cp16(bdst + i * 16, g_w1pack + i * 16);
        cp_commit();
    }
    for (int u = tid; u < 3120; u += 256) {
        int slot = u >> 3, j8 = u & 7;
        int r = slot / 130, xi = slot - r * 130;
        int gy = y + r - 1, gx = xi - 1;
        uint4 w0 = make_uint4(0u,0u,0u,0u), w1 = make_uint4(0u,0u,0u,0u);
        if (((unsigned)gy < 128u) && ((unsigned)gx < 128u)) {
            const uint4* src = (const uint4*)(ub + (size_t)(gy * 128 + gx) * 64 + j8 * 8);
            w0 = src[0]; w1 = src[1];
        }
        uint4 hi, lo;
        hi.x = prmt(w0.x, w0.y, 0x7632); hi.y = prmt(w0.z, w0.w, 0x7632);
        hi.z = prmt(w1.x, w1.y, 0x7632); hi.w = prmt(w1.z, w1.w, 0x7632);
        lo.x = prmt(w0.x, w0.y, 0x5410); lo.y = prmt(w0.z, w0.w, 0x5410);
        lo.z = prmt(w1.x, w1.y, 0x5410); lo.w = prmt(w1.z, w1.w, 0x5410);
        unsigned off = slot * 128 + j8 * 16;
        unsigned sw = off ^ ((off >> 3) & 0x70);
        *(uint4*)(aHi + sw) = hi;
        *(uint4*)(aLo + sw) = lo;
    }
    cp_wait0();
    __syncthreads();

    unsigned aHiB = smaddr(aHi), aLoB = smaddr(aLo), bB = smaddr(sB);
    float d[4] = {0.f, 0.f, 0.f, 0.f};
    int x0 = 16 * w;
    for (int t = 0; t < 9; t++) {
        int kh = t / 3, kw = t - kh * 3;
        int slot = kh * 130 + x0 + (lane & 15) + kw;
        #pragma unroll
        for (int kf = 0; kf < 4; kf++) {
            unsigned aH[4], aL[4], bH[4], bL[4];
            unsigned aoff = (unsigned)(slot * 128 + kf * 32 + ((lane >> 4) << 4));
            unsigned asw = aoff ^ ((aoff >> 3) & 0x70);
            ldsm4(aH, aHiB + asw);
            ldsm4(aL, aLoB + asw);
            unsigned boff = (unsigned)((lane & 15) * 128 + kf * 32 + ((lane >> 4) << 4));
            unsigned bsw = boff ^ ((boff >> 3) & 0x70);
            ldsm4(bH, bB + t * 4096 + bsw);
            ldsm4(bL, bB + t * 4096 + 2048 + bsw);
            mma_bf16(d, aH, bH[0], bH[2]);
            mma_bf16(d, aH, bL[0], bL[2]);
            mma_bf16(d, aL, bH[0], bH[2]);
        }
    }
    unsigned* tb = g_treb + ((size_t)b * 16384 + y * 128) * 8;
    int r = lane >> 2, c = (lane & 3) * 2;
    int px = x0 + r;
    tb[px * 8 + c]           = packbf(fmaxf(d[0], 0.f));
    tb[px * 8 + c + 1]       = packbf(fmaxf(d[1], 0.f));
    tb[(px + 8) * 8 + c]     = packbf(fmaxf(d[2], 0.f));
    tb[(px + 8) * 8 + c + 1] = packbf(fmaxf(d[3], 0.f));
}

// ---------------- reconv2 via mma: out += conv3x3(tre, re_w2) -------------------
#define RC2_SMEM (12480 + 22528 + 22528 + 22528 + 1024)
__global__ void __launch_bounds__(256, 2) reconv2_mma(float* __restrict__ out) {
    extern __shared__ char dynraw2[];
    char* base = (char*)((((uintptr_t)dynraw2) + 1023) & ~(uintptr_t)1023);
    unsigned* sTre = (unsigned*)base;
    char* aHi = base + 12480;
    char* aLo = base + 12480 + 22528;
    char* sB  = base + 12480 + 45056;
    int tid = threadIdx.x;
    int w = tid >> 5, lane = tid & 31;
    int b = blockIdx.x >> 7;
    int y = blockIdx.x & 127;
    const unsigned* tb = g_treb + (size_t)b * 16384 * 8;

    {
        unsigned bdst = smaddr(sB);
        for (int i = tid; i < 1408; i += 256)
            cp16(bdst + i * 16, g_w2pack + i * 16);
        cp_commit();
    }
    for (int u = tid; u < 780; u += 256) {
        int slot = u >> 1, hf = u & 1;
        int r = slot / 130, xi = slot - r * 130;
        int gy = y + r - 1, gx = xi - 1;
        uint4 v = make_uint4(0u,0u,0u,0u);
        if (((unsigned)gy < 128u) && ((unsigned)gx < 128u))
            v = *((const uint4*)(tb + (size_t)(gy * 128 + gx) * 8) + hf);
        *((uint4*)(sTre + slot * 8) + hf) = v;
    }
    __syncthreads();
    for (int u = tid; u < 1152; u += 256) {
        int x = u / 9, t = u - x * 9;
        int kh = t / 3, kw = t - kh * 3;
        const unsigned* src = sTre + (kh * 130 + x + kw) * 8;
        uint4 w0 = *(const uint4*)src;
        uint4 w1 = *(const uint4*)(src + 4);
        uint4 hi, lo;
        hi.x = prmt(w0.x, w0.y, 0x7632); hi.y = prmt(w0.z, w0.w, 0x7632);
        hi.z = prmt(w1.x, w1.y, 0x7632); hi.w = prmt(w1.z, w1.w, 0x7632);
        lo.x = prmt(w0.x, w0.y, 0x5410); lo.y = prmt(w0.z, w0.w, 0x5410);
        lo.z = prmt(w1.x, w1.y, 0x5410); lo.w = prmt(w1.z, w1.w, 0x5410);
        *(uint4*)(aHi + x * 176 + t * 16) = hi;
        *(uint4*)(aLo + x * 176 + t * 16) = lo;
    }
    for (int u = tid; u < 128; u += 256) {
        uint4 z = make_uint4(0u,0u,0u,0u);
        *(uint4*)(aHi + u * 176 + 144) = z;
        *(uint4*)(aLo + u * 176 + 144) = z;
    }
    cp_wait0();
    __syncthreads();

    unsigned aHiB = smaddr(aHi), aLoB = smaddr(aLo), bB = smaddr(sB);
    float acc[4][2][4];
    #pragma unroll
    for (int g = 0; g < 4; g++)
        #pragma unroll
        for (int nf = 0; nf < 2; nf++)
            #pragma unroll
            for (int r = 0; r < 4; r++) acc[g][nf][r] = 0.f;
    int x0 = 16 * w;
    #pragma unroll
    for (int kf = 0; kf < 5; kf++) {
        unsigned aH[4], aL[4];
        unsigned aoff = (unsigned)((x0 + (lane & 15)) * 176 + kf * 32 + ((lane >> 4) << 4));
        ldsm4(aH, aHiB + aoff);
        ldsm4(aL, aLoB + aoff);
        #pragma unroll
        for (int n0g = 0; n0g < 4; n0g++) {
            unsigned bH[4], bL[4];
            unsigned boff = (unsigned)((16 * n0g + (lane & 15)) * 176 + kf * 32 + ((lane >> 4) << 4));
            ldsm4(bH, bB + boff);
            ldsm4(bL, bB + 11264 + boff);
            float* dA = acc[n0g][0];
            float* dB = acc[n0g][1];
            mma_bf16(dA, aH, bH[0], bH[2]);
            mma_bf16(dB, aH, bH[1], bH[3]);
            mma_bf16(dA, aH, bL[0], bL[2]);
            mma_bf16(dB, aH, bL[1], bL[3]);
            mma_bf16(dA, aL, bH[0], bH[2]);
            mma_bf16(dB, aL, bH[1], bH[3]);
        }
    }
    __syncthreads();
    float* sD = (float*)aHi;
    {
        int r = lane >> 2, c = (lane & 3) * 2;
        int px = x0 + r;
        #pragma unroll
        for (int n0g = 0; n0g < 4; n0g++)
            #pragma unroll
            for (int nf = 0; nf < 2; nf++) {
                int o = n0g * 16 + nf * 8 + c;
                sD[px * 65 + o]           = acc[n0g][nf][0];
                sD[px * 65 + o + 1]       = acc[n0g][nf][1];
                sD[(px + 8) * 65 + o]     = acc[n0g][nf][2];
                sD[(px + 8) * 65 + o + 1] = acc[n0g][nf][3];
            }
    }
    __syncthreads();
    for (int i = tid; i < 8192; i += 256) {
        int o = i >> 7, x = i & 127;
        out[((size_t)(b * 64 + o) * 128 + y) * 128 + x] += sD[x * 65 + o];
    }
}

// ---------------------------------------------------------------------------
extern "C" void kernel_launch(void* const* d_in, const int* in_sizes, int n_in,
                              void* d_out, int out_size) {
    const float* x1    = (const float*)d_in[0];
    const float* x2    = (const float*)d_in[1];
    const float* d1_w1 = (const float*)d_in[2];
    const float* d1_w2 = (const float*)d_in[3];
    const float* d2_w1 = (const float*)d_in[4];
    const float* d2_w2 = (const float*)d_in[5];
    const float* align_w = (const float*)d_in[6];
    const float* up_w1 = (const float*)d_in[7];
    const float* up_w2 = (const float*)d_in[8];
    const float* re_w1 = (const float*)d_in[9];
    const float* re_w2 = (const float*)d_in[10];
    float* out = (float*)d_out;

    static int smem_set = 0;
    if (!smem_set) {
        cudaFuncSetAttribute(upconv_mma, cudaFuncAttributeMaxDynamicSharedMemorySize, UPC_SMEM);
        cudaFuncSetAttribute(reconv1_mma, cudaFuncAttributeMaxDynamicSharedMemorySize, RC1_SMEM);
        cudaFuncSetAttribute(reconv2_mma, cudaFuncAttributeMaxDynamicSharedMemorySize, RC2_SMEM);
        smem_set = 1;
    }

    poolmlp_kernel<<<32, 256>>>(x1, x2, d1_w1, d1_w2);
    dsc_kernel<<<4096, 256>>>(x1, x2, 0);
    mlp_kernel<<<32, 128>>>(d2_w1, d2_w2);
    dsc_kernel<<<4096, 256>>>(x1, x2, 1);
    alignweff_kernel<<<1026, 256>>>(align_w, up_w1, up_w2, re_w1, re_w2);
    upconv_mma<<<512, 256, UPC_SMEM>>>(out);
    reconv1_mma<<<2048, 256, RC1_SMEM>>>();
    reconv2_mma<<<2048, 256, RC2_SMEM>>>(out);
}

// round 9
// speedup vs baseline: 1.1032x; 1.0697x over previous
#include <cuda_runtime.h>
#include <cuda_bf16.h>
#include <math.h>
#include <stdint.h>

// ---------------------------------------------------------------------------
// DSFDecoder: B=16, C=128, H=W=64, OUT=64, CR=16, RE=8
// Upconv + refine convs via mma.sync bf16 (split hi/lo, 3 terms). Rest FFMA2.
// R9: dsc vector STS; up stored as hi/lo planes; reconv1 async fill, 2 rows/block.
// ---------------------------------------------------------------------------

#define PLANE 4096
#define CH    128
#define BATCH 16

typedef unsigned long long ull;

__device__ __forceinline__ void ffma2(ull& d, ull a, ull b) {
    asm("fma.rn.f32x2 %0, %1, %2, %0;" : "+l"(d) : "l"(a), "l"(b));
}
__device__ __forceinline__ ull splat2(float v) {
    ull r; asm("mov.b64 %0, {%1, %1};" : "=l"(r) : "f"(v)); return r;
}
__device__ __forceinline__ float2 unpk(ull v) {
    float2 f; asm("mov.b64 {%0, %1}, %2;" : "=f"(f.x), "=f"(f.y) : "l"(v)); return f;
}
__device__ __forceinline__ unsigned smaddr(const void* p) {
    return (unsigned)__cvta_generic_to_shared(p);
}
__device__ __forceinline__ void cp16(unsigned d, const void* s) {
    asm volatile("cp.async.cg.shared.global [%0], [%1], 16;" :: "r"(d), "l"(s) : "memory");
}
__device__ __forceinline__ void cp16z(unsigned d, const void* s, int valid) {
    asm volatile("cp.async.cg.shared.global [%0], [%1], 16, %2;"
                 :: "r"(d), "l"(s), "r"(valid ? 16 : 0) : "memory");
}
__device__ __forceinline__ void cp_commit() {
    asm volatile("cp.async.commit_group;" ::: "memory");
}
__device__ __forceinline__ void cp_wait0() {
    asm volatile("cp.async.wait_group 0;" ::: "memory");
}
__device__ __forceinline__ unsigned prmt(unsigned a, unsigned b, unsigned sel) {
    unsigned r; asm("prmt.b32 %0, %1, %2, %3;" : "=r"(r) : "r"(a), "r"(b), "r"(sel));
    return r;
}
__device__ __forceinline__ void ldsm4(unsigned* r, unsigned addr) {
    asm volatile("ldmatrix.sync.aligned.m8n8.x4.shared.b16 {%0,%1,%2,%3}, [%4];"
                 : "=r"(r[0]), "=r"(r[1]), "=r"(r[2]), "=r"(r[3]) : "r"(addr));
}
__device__ __forceinline__ void mma_bf16(float* d, const unsigned* a, unsigned b0, unsigned b1) {
    asm volatile(
        "mma.sync.aligned.m16n8k16.row.col.f32.bf16.bf16.f32 "
        "{%0,%1,%2,%3}, {%4,%5,%6,%7}, {%8,%9}, {%0,%1,%2,%3};"
        : "+f"(d[0]), "+f"(d[1]), "+f"(d[2]), "+f"(d[3])
        : "r"(a[0]), "r"(a[1]), "r"(a[2]), "r"(a[3]), "r"(b0), "r"(b1));
}
__device__ __forceinline__ unsigned packbf(float v) {
    __nv_bfloat16 h = __float2bfloat16(v);
    __nv_bfloat16 l = __float2bfloat16(v - __bfloat162float(h));
    return (unsigned)__bfloat16_as_ushort(l) | ((unsigned)__bfloat16_as_ushort(h) << 16);
}
__device__ __forceinline__ unsigned bfhi(float v) {
    return (unsigned)__bfloat16_as_ushort(__float2bfloat16(v));
}
__device__ __forceinline__ unsigned bflo(float v) {
    __nv_bfloat16 h = __float2bfloat16(v);
    return (unsigned)__bfloat16_as_ushort(__float2bfloat16(v - __bfloat162float(h)));
}

__device__ float g_t[2][BATCH * CH * PLANE];
__device__ float g_ab[2][BATCH * CH * PLANE];
__device__ unsigned g_fuH[BATCH * PLANE * 64];           // [b][pix][c-pair] hi bf16x2
__device__ unsigned g_fuL[BATCH * PLANE * 64];
__device__ __align__(16) unsigned char g_wpack[18 * 8 * 8192];
__device__ unsigned g_upH[BATCH * 16384 * 32];           // [b][y][x][o-pair] hi
__device__ unsigned g_upL[BATCH * 16384 * 32];
__device__ unsigned g_treb[BATCH * 16384 * 8];           // [b][y][x][r] packed tre
__device__ __align__(16) unsigned char g_w1pack[9 * 4096];
__device__ __align__(16) unsigned char g_w2pack[2 * 11264];
__device__ float g_pool[2][BATCH * CH];
__device__ float g_wk[2][BATCH * CH * 9];

// ---------------- pool + mlp1 fused ----------------
__global__ void poolmlp_kernel(const float* __restrict__ x1, const float* __restrict__ x2,
                               const float* __restrict__ w1, const float* __restrict__ w2) {
    int slot = blockIdx.x >> 4;
    int b = blockIdx.x & 15;
    int tid = threadIdx.x;
    int wid = tid >> 5, lane = tid & 31;
    const float* xb = (slot ? x2 : x1) + (size_t)b * CH * PLANE;
    __shared__ float sp[128], sh[16];
    for (int k = 0; k < 16; k++) {
        int c = wid * 16 + k;
        const float4* v = (const float4*)(xb + (size_t)c * PLANE);
        float s = 0.f;
        #pragma unroll 4
        for (int i = lane; i < 1024; i += 32) {
            float4 q = v[i];
            s += q.x + q.y + q.z + q.w;
        }
        for (int off = 16; off; off >>= 1) s += __shfl_xor_sync(0xffffffffu, s, off);
        if (lane == 0) sp[c] = s * (1.f / 4096.f);
    }
    __syncthreads();
    if (tid < 16) {
        float acc = 0.f;
        #pragma unroll 8
        for (int c = 0; c < 128; c++) acc += sp[c] * w1[tid * 128 + c];
        sh[tid] = 0.5f * acc * (1.f + erff(acc * 0.70710678118654752f));
    }
    __syncthreads();
    if (tid < 128) {
        int c = tid;
        float lg[9];
        float mx = -1e30f;
        #pragma unroll
        for (int k = 0; k < 9; k++) {
            float acc = 0.f;
            #pragma unroll
            for (int r = 0; r < 16; r++) acc += sh[r] * w2[(c * 9 + k) * 16 + r];
            lg[k] = acc;
            mx = fmaxf(mx, acc);
        }
        float ss = 0.f;
        #pragma unroll
        for (int k = 0; k < 9; k++) { lg[k] = expf(lg[k] - mx); ss += lg[k]; }
        float inv = 1.f / ss;
        #pragma unroll
        for (int k = 0; k < 9; k++) g_wk[slot][(b * 128 + c) * 9 + k] = lg[k] * inv;
    }
}

// ---------------- mlp2 ----------------
__global__ void mlp_kernel(const float* __restrict__ w1, const float* __restrict__ w2) {
    int slot = blockIdx.x >> 4;
    int b = blockIdx.x & 15;
    int tid = threadIdx.x;
    __shared__ float sp[128], sh[16];
    sp[tid] = g_pool[slot][b * 128 + tid];
    __syncthreads();
    if (tid < 16) {
        float acc = 0.f;
        #pragma unroll 8
        for (int c = 0; c < 128; c++) acc += sp[c] * w1[tid * 128 + c];
        sh[tid] = 0.5f * acc * (1.f + erff(acc * 0.70710678118654752f));
    }
    __syncthreads();
    int c = tid;
    float lg[9];
    float mx = -1e30f;
    #pragma unroll
    for (int k = 0; k < 9; k++) {
        float acc = 0.f;
        #pragma unroll
        for (int r = 0; r < 16; r++) acc += sh[r] * w2[(c * 9 + k) * 16 + r];
        lg[k] = acc;
        mx = fmaxf(mx, acc);
    }
    float ss = 0.f;
    #pragma unroll
    for (int k = 0; k < 9; k++) { lg[k] = expf(lg[k] - mx); ss += lg[k]; }
    float inv = 1.f / ss;
    #pragma unroll
    for (int k = 0; k < 9; k++) g_wk[slot][(b * 128 + c) * 9 + k] = lg[k] * inv;
}

// ---------------- dsc: depthwise 3x3 + residual, vector STS (pad-left-4) --------
__global__ void __launch_bounds__(256, 3) dsc_kernel(const float* __restrict__ x1,
                                                     const float* __restrict__ x2,
                                                     int phase) {
    int slot = blockIdx.x >> 11;
    int bc = blockIdx.x & 2047;
    const float* xext = slot ? x2 : x1;
    const float* src = phase ? &g_t[slot][(size_t)bc * PLANE]
                             : xext + (size_t)bc * PLANE;
    float* dst = phase ? &g_ab[slot][(size_t)bc * PLANE]
                       : &g_t[slot][(size_t)bc * PLANE];
    float wk[9];
    #pragma unroll
    for (int k = 0; k < 9; k++) wk[k] = g_wk[slot][bc * 9 + k];
    // layout: interior x at col x+4; halos at cols 3 and 68; rows 1..64
    __shared__ float sp[66][72];
    int tid = threadIdx.x;
    if (tid < 72) { sp[0][tid] = 0.f; sp[65][tid] = 0.f; }
    if (tid < 64) { sp[tid + 1][3] = 0.f; sp[tid + 1][68] = 0.f; }
    {
        int p = tid * 16;
        int h = p >> 6, w = p & 63;
        const float4* s4 = (const float4*)(src + p);
        float4* d = (float4*)&sp[h + 1][w + 4];
        d[0] = s4[0]; d[1] = s4[1]; d[2] = s4[2]; d[3] = s4[3];
    }
    __syncthreads();
    int h = tid >> 2, xb = (tid & 3) * 16;
    float r0[24], r1[24], r2[24];
    #pragma unroll
    for (int k = 0; k < 6; k++) {
        *(float4*)&r0[k * 4] = *(const float4*)&sp[h + 0][xb + k * 4];
        *(float4*)&r1[k * 4] = *(const float4*)&sp[h + 1][xb + k * 4];
        *(float4*)&r2[k * 4] = *(const float4*)&sp[h + 2][xb + k * 4];
    }
    float acc[16];
    #pragma unroll
    for (int j = 0; j < 16; j++) {
        float a = r1[j + 4];
        a += wk[0] * r0[j + 3]; a += wk[1] * r0[j + 4]; a += wk[2] * r0[j + 5];
        a += wk[3] * r1[j + 3]; a += wk[4] * r1[j + 4]; a += wk[5] * r1[j + 5];
        a += wk[6] * r2[j + 3]; a += wk[7] * r2[j + 4]; a += wk[8] * r2[j + 5];
        acc[j] = a;
    }
    int p = tid * 16;
    if (phase) {
        #pragma unroll
        for (int k = 0; k < 4; k++)
            *(float4*)&dst[p + k * 4] = make_float4(acc[k*4], acc[k*4+1], acc[k*4+2], acc[k*4+3]);
    } else {
        float psum = 0.f;
        #pragma unroll
        for (int j = 0; j < 16; j++) { acc[j] = fmaxf(acc[j], 0.f); psum += acc[j]; }
        #pragma unroll
        for (int k = 0; k < 4; k++)
            *(float4*)&dst[p + k * 4] = make_float4(acc[k*4], acc[k*4+1], acc[k*4+2], acc[k*4+3]);
        for (int off = 16; off; off >>= 1) psum += __shfl_xor_sync(0xffffffffu, psum, off);
        __shared__ float red[8];
        if ((tid & 31) == 0) red[tid >> 5] = psum;
        __syncthreads();
        if (tid < 32) {
            float r = (tid < 8) ? red[tid] : 0.f;
            for (int off = 4; off; off >>= 1) r += __shfl_xor_sync(0xffffffffu, r, off);
            if (tid == 0) g_pool[slot][bc] = r * (1.f / 4096.f);
        }
    }
}

// ---------------- align + weight packing ----------------
__global__ void __launch_bounds__(256, 2) alignweff_kernel(const float* __restrict__ aw,
                                                           const float* __restrict__ w1,
                                                           const float* __restrict__ w2,
                                                           const float* __restrict__ rw1,
                                                           const float* __restrict__ rw2) {
    __shared__ float smem_u[4096];
    int tid = threadIdx.x;
    if (blockIdx.x == 1024) {
        for (int i = tid; i < 9216; i += 256) {
            int t = i >> 10, rem = i & 1023;
            int row = rem >> 6, c = rem & 63;
            float v = (row < 8) ? rw1[(row * 64 + c) * 9 + t] : 0.f;
            unsigned off = row * 128 + c * 2;
            unsigned sw = off ^ ((off >> 3) & 0x70);
            __nv_bfloat16 hb = __float2bfloat16(v);
            __nv_bfloat16 lb = __float2bfloat16(v - __bfloat162float(hb));
            *(__nv_bfloat16*)(g_w1pack + t * 4096 + sw) = hb;
            *(__nv_bfloat16*)(g_w1pack + t * 4096 + 2048 + sw) = lb;
        }
        return;
    }
    if (blockIdx.x == 1025) {
        for (int i = tid; i < 64 * 88; i += 256) {
            int o = i / 88, k = i - o * 88;
            float v = 0.f;
            if (k < 72) { int t = k >> 3, r = k & 7; v = rw2[(o * 8 + r) * 9 + t]; }
            __nv_bfloat16 hb = __float2bfloat16(v);
            __nv_bfloat16 lb = __float2bfloat16(v - __bfloat162float(hb));
            *(__nv_bfloat16*)(g_w2pack + o * 176 + k * 2) = hb;
            *(__nv_bfloat16*)(g_w2pack + 11264 + o * 176 + k * 2) = lb;
        }
        return;
    }
    if (blockIdx.x < 512) {
        int sub = blockIdx.x >> 7, ci = blockIdx.x & 127;
        float* s1 = smem_u;
        for (int i = tid; i < 1152; i += 256) {
            int c = i / 9, t = i - c * 9;
            s1[i] = w1[((size_t)(c * 4 + sub) * 128 + ci) * 9 + t];
        }
        __syncthreads();
        if (tid < 64) {
            int o = tid;
            float acc[9] = {0.f,0.f,0.f,0.f,0.f,0.f,0.f,0.f,0.f};
            for (int c = 0; c < 128; c++) {
                float wv = w2[o * 128 + c];
                #pragma unroll
                for (int t = 0; t < 9; t++) acc[t] += wv * s1[c * 9 + t];
            }
            int g = ci >> 6, cl = ci & 63;
            unsigned off = ((o >> 3) << 10) + ((o & 7) << 7) + (cl << 1);
            unsigned sw = off ^ ((off >> 3) & 0x70);
            #pragma unroll
            for (int t = 0; t < 9; t++) {
                float v = acc[t];
                __nv_bfloat16 hb = __float2bfloat16(v);
                __nv_bfloat16 lb = __float2bfloat16(v - __bfloat162float(hb));
                unsigned char* base = g_wpack + ((size_t)((t * 2 + g) * 8 + sub * 2)) * 8192;
                *(__nv_bfloat16*)(base + sw) = hb;
                *(__nv_bfloat16*)(base + 8192 + sw) = lb;
            }
        }
        return;
    }
    // align: fused = concat(a,b) @ aw^T -> hi/lo bf16 planes [pix][c]
    int idx = blockIdx.x - 512;
    int q = idx & 3, og = (idx >> 2) & 7, b = idx >> 5;
    float (*sw_s)[16] = (float (*)[16])smem_u;
    for (int i = tid; i < 4096; i += 256) {
        int c = i >> 4, oo = i & 15;
        sw_s[c][oo] = aw[(og * 16 + oo) * 256 + c];
    }
    __syncthreads();
    int pix = q * 1024 + tid * 4;
    const float* ap = &g_ab[0][(size_t)b * CH * PLANE] + pix;
    const float* bp = &g_ab[1][(size_t)b * CH * PLANE] + pix;
    ull acc2[8][4];
    #pragma unroll
    for (int jo = 0; jo < 8; jo++)
        #pragma unroll
        for (int p = 0; p < 4; p++) acc2[jo][p] = 0ull;
    for (int c = 0; c < 128; c++) {
        float4 xv = *(const float4*)(ap + (size_t)c * PLANE);
        ull s0 = splat2(xv.x), s1 = splat2(xv.y), s2 = splat2(xv.z), s3 = splat2(xv.w);
        const ull* wp = (const ull*)&sw_s[c][0];
        #pragma unroll
        for (int jo = 0; jo < 8; jo++) {
            ull wv = wp[jo];
            ffma2(acc2[jo][0], s0, wv); ffma2(acc2[jo][1], s1, wv);
            ffma2(acc2[jo][2], s2, wv); ffma2(acc2[jo][3], s3, wv);
        }
    }
    for (int c = 0; c < 128; c++) {
        float4 xv = *(const float4*)(bp + (size_t)c * PLANE);
        ull s0 = splat2(xv.x), s1 = splat2(xv.y), s2 = splat2(xv.z), s3 = splat2(xv.w);
        const ull* wp = (const ull*)&sw_s[128 + c][0];
        #pragma unroll
        for (int jo = 0; jo < 8; jo++) {
            ull wv = wp[jo];
            ffma2(acc2[jo][0], s0, wv); ffma2(acc2[jo][1], s1, wv);
            ffma2(acc2[jo][2], s2, wv); ffma2(acc2[jo][3], s3, wv);
        }
    }
    unsigned* fH = g_fuH + (size_t)b * PLANE * 64;
    unsigned* fL = g_fuL + (size_t)b * PLANE * 64;
    #pragma unroll
    for (int p = 0; p < 4; p++) {
        unsigned hbuf[8], lbuf[8];
        #pragma unroll
        for (int jo = 0; jo < 8; jo++) {
            float2 v = unpk(acc2[jo][p]);
            hbuf[jo] = bfhi(v.x) | (bfhi(v.y) << 16);
            lbuf[jo] = bflo(v.x) | (bflo(v.y) << 16);
        }
        unsigned* dH = fH + (size_t)(pix + p) * 64 + og * 8;
        unsigned* dL = fL + (size_t)(pix + p) * 64 + og * 8;
        *(uint4*)(dH) = *(uint4*)(hbuf);
        *(uint4*)(dH + 4) = *(uint4*)(hbuf + 4);
        *(uint4*)(dL) = *(uint4*)(lbuf);
        *(uint4*)(dL + 4) = *(uint4*)(lbuf + 4);
    }
}

// ---------------- upconv via mma.sync bf16 split, fully async fills -------------
#define UPC_BUF 98304
#define UPC_SMEM (2 * UPC_BUF + 1024)
__global__ void __launch_bounds__(256, 1) upconv_mma(float* __restrict__ out) {
    extern __shared__ char dynraw[];
    char* base = (char*)((((uintptr_t)dynraw) + 1023) & ~(uintptr_t)1023);
    int tid = threadIdx.x;
    int w = tid >> 5, lane = tid & 31;
    int b = blockIdx.x >> 5;
    int y0 = (blockIdx.x & 31) * 2;

    const unsigned* fH = g_fuH + (size_t)b * PLANE * 64;
    const unsigned* fL = g_fuL + (size_t)b * PLANE * 64;
    int m = tid >> 1, plane = tid & 1;
    int mrow = m >> 6, mx = m & 63;

    float acc[4][8][4];
    #pragma unroll
    for (int s = 0; s < 4; s++)
        #pragma unroll
        for (int nf = 0; nf < 8; nf++)
            #pragma unroll
            for (int r = 0; r < 4; r++) acc[s][nf][r] = 0.f;

    auto fill = [&](int q, int buf) {
        char* bb = base + buf * UPC_BUF;
        int tap = q >> 1, g = q & 1;
        int kh = tap / 3, kw = tap - kh * 3;
        {
            const unsigned char* bsrc = g_wpack + (size_t)q * 65536;
            unsigned bdst = smaddr(bb + 32768);
            #pragma unroll 4
            for (int i = tid; i < 4096; i += 256)
                cp16(bdst + i * 16, bsrc + i * 16);
        }
        {
            int yy = y0 + mrow + kh - 1;
            int xx = mx + kw - 1;
            int valid = (((unsigned)yy < 64u) && ((unsigned)xx < 64u)) ? 1 : 0;
            const unsigned* src = (plane ? fL : fH) + ((size_t)(yy * 64 + xx) * 64 + g * 32);
            unsigned dstb = smaddr(bb + plane * 16384);
            unsigned db = (unsigned)(m * 128);
            #pragma unroll
            for (int j = 0; j < 8; j++) {
                unsigned off = db + j * 16;
                unsigned sw = off ^ ((off >> 3) & 0x70);
                cp16z(dstb + sw, src + j * 4, valid);
            }
        }
    };

    fill(0, 0);
    cp_commit(); cp_wait0();
    __syncthreads();

    for (int q = 0; q < 18; q++) {
        int buf = q & 1;
        if (q < 17) { fill(q + 1, buf ^ 1); cp_commit(); }
        char* bb = base + buf * UPC_BUF;
        unsigned aHiB = smaddr(bb), aLoB = smaddr(bb + 16384);
        unsigned bB = smaddr(bb + 32768);
        #pragma unroll
        for (int kf = 0; kf < 4; kf++) {
            unsigned aH[4], aL[4];
            {
                unsigned arow = (unsigned)(16 * w + (lane & 15));
                unsigned aoff = arow * 128 + kf * 32 + ((lane >> 4) << 4);
                unsigned asw = aoff ^ ((aoff >> 3) & 0x70);
                ldsm4(aH, aHiB + asw);
                ldsm4(aL, aLoB + asw);
            }
            #pragma unroll
            for (int s = 0; s < 4; s++) {
                #pragma unroll
                for (int n0g = 0; n0g < 4; n0g++) {
                    unsigned brow = (unsigned)(16 * n0g + (lane & 15));
                    unsigned boff = brow * 128 + kf * 32 + ((lane >> 4) << 4);
                    unsigned bsw = boff ^ ((boff >> 3) & 0x70);
                    unsigned bH[4], bL[4];
                    ldsm4(bH, bB + s * 16384 + bsw);
                    ldsm4(bL, bB + s * 16384 + 8192 + bsw);
                    float* dA = acc[s][2 * n0g];
                    float* dB = acc[s][2 * n0g + 1];
                    mma_bf16(dA, aH, bH[0], bH[2]);
                    mma_bf16(dB, aH, bH[1], bH[3]);
                    mma_bf16(dA, aH, bL[0], bL[2]);
                    mma_bf16(dB, aH, bL[1], bL[3]);
                    mma_bf16(dA, aL, bH[0], bH[2]);
                    mma_bf16(dB, aL, bH[1], bH[3]);
                }
            }
        }
        if (q < 17) cp_wait0();
        __syncthreads();
    }

    // epilogue: float out + split hi/lo planes for reconv1
    float2* s2 = (float2*)base;   // [128][65] float2
    unsigned* uH = g_upH + (size_t)b * 16384 * 32;
    unsigned* uL = g_upL + (size_t)b * 16384 * 32;
    int m0 = 16 * w + (lane >> 2);
    int ocol = (lane & 3) * 2;
    #pragma unroll
    for (int sp = 0; sp < 2; sp++) {
        __syncthreads();
        #pragma unroll
        for (int nf = 0; nf < 8; nf++) {
            int o = nf * 8 + ocol;
            s2[m0 * 65 + o]         = make_float2(acc[2*sp][nf][0], acc[2*sp+1][nf][0]);
            s2[m0 * 65 + o + 1]     = make_float2(acc[2*sp][nf][1], acc[2*sp+1][nf][1]);
            s2[(m0 + 8) * 65 + o]   = make_float2(acc[2*sp][nf][2], acc[2*sp+1][nf][2]);
            s2[(m0 + 8) * 65 + o+1] = make_float2(acc[2*sp][nf][3], acc[2*sp+1][nf][3]);
        }
        __syncthreads();
        for (int i = tid; i < 8192; i += 256) {
            int mr = i >> 12, o = (i >> 6) & 63, xx = i & 63;
            int y = 2 * (y0 + mr) + sp;
            *(float2*)(out + (((size_t)(b * 64 + o) * 128 + y) * 128 + 2 * xx)) =
                s2[(mr * 64 + xx) * 65 + o];
        }
        for (int i = tid; i < 8192; i += 256) {
            int mr = i >> 12, x2 = (i >> 5) & 127, op = i & 31;
            int y = 2 * (y0 + mr) + sp;
            float2 va = s2[(mr * 64 + (x2 >> 1)) * 65 + 2 * op];
            float2 vb = s2[(mr * 64 + (x2 >> 1)) * 65 + 2 * op + 1];
            float v0 = (x2 & 1) ? va.y : va.x;
            float v1 = (x2 & 1) ? vb.y : vb.x;
            uH[(size_t)(y * 128 + x2) * 32 + op] = bfhi(v0) | (bfhi(v1) << 16);
            uL[(size_t)(y * 128 + x2) * 32 + op] = bflo(v0) | (bflo(v1) << 16);
        }
    }
}

// ---------------- reconv1 via mma: tre = relu(conv3x3(up, re_w1)), 2 rows/block --
#define RC1_SMEM (66560 * 2 + 36864 + 1024)
__global__ void __launch_bounds__(256, 1) reconv1_mma() {
    extern __shared__ char dynraw[];
    char* base = (char*)((((uintptr_t)dynraw) + 1023) & ~(uintptr_t)1023);
    char* aHi = base;
    char* aLo = base + 66560;
    char* sB  = base + 133120;
    int tid = threadIdx.x;
    int w = tid >> 5, lane = tid & 31;
    int b = blockIdx.x >> 6;
    int y0 = (blockIdx.x & 63) * 2;
    const unsigned* uH = g_upH + (size_t)b * 16384 * 32;
    const unsigned* uL = g_upL + (size_t)b * 16384 * 32;

    {
        unsigned bdst = smaddr(sB);
        for (int i = tid; i < 2304; i += 256)
            cp16(bdst + i * 16, g_w1pack + i * 16);
    }
    // A window: 4 rows x 130 slots x 64 ch, pure cp.async
    unsigned aHiB = smaddr(aHi), aLoB = smaddr(aLo);
    for (int u = tid; u < 4160; u += 256) {
        int slot = u >> 3, j = u & 7;
        int r = slot / 130, xi = slot - r * 130;
        int gy = y0 + r - 1, gx = xi - 1;
        int valid = (((unsigned)gy < 128u) && ((unsigned)gx < 128u)) ? 1 : 0;
        size_t sidx = (size_t)(gy * 128 + gx) * 32 + j * 4;
        unsigned off = (unsigned)(slot * 128 + j * 16);
        unsigned sw = off ^ ((off >> 3) & 0x70);
        cp16z(aHiB + sw, uH + sidx, valid);
        cp16z(aLoB + sw, uL + sidx, valid);
    }
    cp_commit(); cp_wait0();
    __syncthreads();

    unsigned bB = smaddr(sB);
    float d[2][4];
    #pragma unroll
    for (int ys = 0; ys < 2; ys++)
        #pragma unroll
        for (int r = 0; r < 4; r++) d[ys][r] = 0.f;
    int x0 = 16 * w;
    for (int t = 0; t < 9; t++) {
        int kh = t / 3, kw = t - kh * 3;
        #pragma unroll
        for (int kf = 0; kf < 4; kf++) {
            unsigned bH[4], bL[4];
            unsigned boff = (unsigned)((lane & 15) * 128 + kf * 32 + ((lane >> 4) << 4));
            unsigned bsw = boff ^ ((boff >> 3) & 0x70);
            ldsm4(bH, bB + t * 4096 + bsw);
            ldsm4(bL, bB + t * 4096 + 2048 + bsw);
            #pragma unroll
            for (int ys = 0; ys < 2; ys++) {
                int slot = (ys + kh) * 130 + x0 + (lane & 15) + kw;
                unsigned aoff = (unsigned)(slot * 128 + kf * 32 + ((lane >> 4) << 4));
                unsigned asw = aoff ^ ((aoff >> 3) & 0x70);
                unsigned aH[4], aL[4];
                ldsm4(aH, aHiB + asw);
                ldsm4(aL, aLoB + asw);
                mma_bf16(d[ys], aH, bH[0], bH[2]);
                mma_bf16(d[ys], aH, bL[0], bL[2]);
                mma_bf16(d[ys], aL, bH[0], bH[2]);
            }
        }
    }
    int r = lane >> 2, c = (lane & 3) * 2;
    int px = x0 + r;
    #pragma unroll
    for (int ys = 0; ys < 2; ys++) {
        unsigned* tb = g_treb + ((size_t)b * 16384 + (y0 + ys) * 128) * 8;
        tb[px * 8 + c]           = packbf(fmaxf(d[ys][0], 0.f));
        tb[px * 8 + c + 1]       = packbf(fmaxf(d[ys][1], 0.f));
        tb[(px + 8) * 8 + c]     = packbf(fmaxf(d[ys][2], 0.f));
        tb[(px + 8) * 8 + c + 1] = packbf(fmaxf(d[ys][3], 0.f));
    }
}

// ---------------- reconv2 via mma: out += conv3x3(tre, re_w2) -------------------
#define RC2_SMEM (12480 + 22528 + 22528 + 22528 + 1024)
__global__ void __launch_bounds__(256, 2) reconv2_mma(float* __restrict__ out) {
    extern __shared__ char dynraw2[];
    char* base = (char*)((((uintptr_t)dynraw2) + 1023) & ~(uintptr_t)1023);
    unsigned* sTre = (unsigned*)base;
    char* aHi = base + 12480;
    char* aLo = base + 12480 + 22528;
    char* sB  = base + 12480 + 45056;
    int tid = threadIdx.x;
    int w = tid >> 5, lane = tid & 31;
    int b = blockIdx.x >> 7;
    int y = blockIdx.x & 127;
    const unsigned* tb = g_treb + (size_t)b * 16384 * 8;

    {
        unsigned bdst = smaddr(sB);
        for (int i = tid; i < 1408; i += 256)
            cp16(bdst + i * 16, g_w2pack + i * 16);
        cp_commit();
    }
    for (int u = tid; u < 780; u += 256) {
        int slot = u >> 1, hf = u & 1;
        int r = slot / 130, xi = slot - r * 130;
        int gy = y + r - 1, gx = xi - 1;
        uint4 v = make_uint4(0u,0u,0u,0u);
        if (((unsigned)gy < 128u) && ((unsigned)gx < 128u))
            v = *((const uint4*)(tb + (size_t)(gy * 128 + gx) * 8) + hf);
        *((uint4*)(sTre + slot * 8) + hf) = v;
    }
    __syncthreads();
    for (int u = tid; u < 1152; u += 256) {
        int x = u / 9, t = u - x * 9;
        int kh = t / 3, kw = t - kh * 3;
        const unsigned* src = sTre + (kh * 130 + x + kw) * 8;
        uint4 w0 = *(const uint4*)src;
        uint4 w1 = *(const uint4*)(src + 4);
        uint4 hi, lo;
        hi.x = prmt(w0.x, w0.y, 0x7632); hi.y = prmt(w0.z, w0.w, 0x7632);
        hi.z = prmt(w1.x, w1.y, 0x7632); hi.w = prmt(w1.z, w1.w, 0x7632);
        lo.x = prmt(w0.x, w0.y, 0x5410); lo.y = prmt(w0.z, w0.w, 0x5410);
        lo.z = prmt(w1.x, w1.y, 0x5410); lo.w = prmt(w1.z, w1.w, 0x5410);
        *(uint4*)(aHi + x * 176 + t * 16) = hi;
        *(uint4*)(aLo + x * 176 + t * 16) = lo;
    }
    for (int u = tid; u < 128; u += 256) {
        uint4 z = make_uint4(0u,0u,0u,0u);
        *(uint4*)(aHi + u * 176 + 144) = z;
        *(uint4*)(aLo + u * 176 + 144) = z;
    }
    cp_wait0();
    __syncthreads();

    unsigned aHiB = smaddr(aHi), aLoB = smaddr(aLo), bB = smaddr(sB);
    float acc[4][2][4];
    #pragma unroll
    for (int g = 0; g < 4; g++)
        #pragma unroll
        for (int nf = 0; nf < 2; nf++)
            #pragma unroll
            for (int r = 0; r < 4; r++) acc[g][nf][r] = 0.f;
    int x0 = 16 * w;
    #pragma unroll
    for (int kf = 0; kf < 5; kf++) {
        unsigned aH[4], aL[4];
        unsigned aoff = (unsigned)((x0 + (lane & 15)) * 176 + kf * 32 + ((lane >> 4) << 4));
        ldsm4(aH, aHiB + aoff);
        ldsm4(aL, aLoB + aoff);
        #pragma unroll
        for (int n0g = 0; n0g < 4; n0g++) {
            unsigned bH[4], bL[4];
            unsigned boff = (unsigned)((16 * n0g + (lane & 15)) * 176 + kf * 32 + ((lane >> 4) << 4));
            ldsm4(bH, bB + boff);
            ldsm4(bL, bB + 11264 + boff);
            float* dA = acc[n0g][0];
            float* dB = acc[n0g][1];
            mma_bf16(dA, aH, bH[0], bH[2]);
            mma_bf16(dB, aH, bH[1], bH[3]);
            mma_bf16(dA, aH, bL[0], bL[2]);
            mma_bf16(dB, aH, bL[1], bL[3]);
            mma_bf16(dA, aL, bH[0], bH[2]);
            mma_bf16(dB, aL, bH[1], bH[3]);
        }
    }
    __syncthreads();
    float* sD = (float*)aHi;
    {
        int r = lane >> 2, c = (lane & 3) * 2;
        int px = x0 + r;
        #pragma unroll
        for (int n0g = 0; n0g < 4; n0g++)
            #pragma unroll
            for (int nf = 0; nf < 2; nf++) {
                int o = n0g * 16 + nf * 8 + c;
                sD[px * 65 + o]           = acc[n0g][nf][0];
                sD[px * 65 + o + 1]       = acc[n0g][nf][1];
                sD[(px + 8) * 65 + o]     = acc[n0g][nf][2];
                sD[(px + 8) * 65 + o + 1] = acc[n0g][nf][3];
            }
    }
    __syncthreads();
    for (int i = tid; i < 8192; i += 256) {
        int o = i >> 7, x = i & 127;
        out[((size_t)(b * 64 + o) * 128 + y) * 128 + x] += sD[x * 65 + o];
    }
}

// ---------------------------------------------------------------------------
extern "C" void kernel_launch(void* const* d_in, const int* in_sizes, int n_in,
                              void* d_out, int out_size) {
    const float* x1    = (const float*)d_in[0];
    const float* x2    = (const float*)d_in[1];
    const float* d1_w1 = (const float*)d_in[2];
    const float* d1_w2 = (const float*)d_in[3];
    const float* d2_w1 = (const float*)d_in[4];
    const float* d2_w2 = (const float*)d_in[5];
    const float* align_w = (const float*)d_in[6];
    const float* up_w1 = (const float*)d_in[7];
    const float* up_w2 = (const float*)d_in[8];
    const float* re_w1 = (const float*)d_in[9];
    const float* re_w2 = (const float*)d_in[10];
    float* out = (float*)d_out;

    static int smem_set = 0;
    if (!smem_set) {
        cudaFuncSetAttribute(upconv_mma, cudaFuncAttributeMaxDynamicSharedMemorySize, UPC_SMEM);
        cudaFuncSetAttribute(reconv1_mma, cudaFuncAttributeMaxDynamicSharedMemorySize, RC1_SMEM);
        cudaFuncSetAttribute(reconv2_mma, cudaFuncAttributeMaxDynamicSharedMemorySize, RC2_SMEM);
        smem_set = 1;
    }

    poolmlp_kernel<<<32, 256>>>(x1, x2, d1_w1, d1_w2);
    dsc_kernel<<<4096, 256>>>(x1, x2, 0);
    mlp_kernel<<<32, 128>>>(d2_w1, d2_w2);
    dsc_kernel<<<4096, 256>>>(x1, x2, 1);
    alignweff_kernel<<<1026, 256>>>(align_w, up_w1, up_w2, re_w1, re_w2);
    upconv_mma<<<512, 256, UPC_SMEM>>>(out);
    reconv1_mma<<<1024, 256, RC1_SMEM>>>();
    reconv2_mma<<<2048, 256, RC2_SMEM>>>(out);
}

// round 10
// speedup vs baseline: 1.1374x; 1.0311x over previous
#include <cuda_runtime.h>
#include <cuda_bf16.h>
#include <math.h>
#include <stdint.h>

// ---------------------------------------------------------------------------
// DSFDecoder: B=16, C=128, H=W=64, OUT=64, CR=16, RE=8
// All GEMM-shaped work on mma.sync bf16 (split hi/lo, 3 terms).
// R10: align -> MMA via ldmatrix.trans; dsc emits bf16 hi/lo planes.
// ---------------------------------------------------------------------------

#define PLANE 4096
#define CH    128
#define BATCH 16

typedef unsigned long long ull;

__device__ __forceinline__ unsigned smaddr(const void* p) {
    return (unsigned)__cvta_generic_to_shared(p);
}
__device__ __forceinline__ void cp16(unsigned d, const void* s) {
    asm volatile("cp.async.cg.shared.global [%0], [%1], 16;" :: "r"(d), "l"(s) : "memory");
}
__device__ __forceinline__ void cp16z(unsigned d, const void* s, int valid) {
    asm volatile("cp.async.cg.shared.global [%0], [%1], 16, %2;"
                 :: "r"(d), "l"(s), "r"(valid ? 16 : 0) : "memory");
}
__device__ __forceinline__ void cp_commit() {
    asm volatile("cp.async.commit_group;" ::: "memory");
}
__device__ __forceinline__ void cp_wait0() {
    asm volatile("cp.async.wait_group 0;" ::: "memory");
}
__device__ __forceinline__ unsigned prmt(unsigned a, unsigned b, unsigned sel) {
    unsigned r; asm("prmt.b32 %0, %1, %2, %3;" : "=r"(r) : "r"(a), "r"(b), "r"(sel));
    return r;
}
__device__ __forceinline__ void ldsm4(unsigned* r, unsigned addr) {
    asm volatile("ldmatrix.sync.aligned.m8n8.x4.shared.b16 {%0,%1,%2,%3}, [%4];"
                 : "=r"(r[0]), "=r"(r[1]), "=r"(r[2]), "=r"(r[3]) : "r"(addr));
}
__device__ __forceinline__ void ldsm4t(unsigned* r, unsigned addr) {
    asm volatile("ldmatrix.sync.aligned.m8n8.x4.trans.shared.b16 {%0,%1,%2,%3}, [%4];"
                 : "=r"(r[0]), "=r"(r[1]), "=r"(r[2]), "=r"(r[3]) : "r"(addr));
}
__device__ __forceinline__ void mma_bf16(float* d, const unsigned* a, unsigned b0, unsigned b1) {
    asm volatile(
        "mma.sync.aligned.m16n8k16.row.col.f32.bf16.bf16.f32 "
        "{%0,%1,%2,%3}, {%4,%5,%6,%7}, {%8,%9}, {%0,%1,%2,%3};"
        : "+f"(d[0]), "+f"(d[1]), "+f"(d[2]), "+f"(d[3])
        : "r"(a[0]), "r"(a[1]), "r"(a[2]), "r"(a[3]), "r"(b0), "r"(b1));
}
__device__ __forceinline__ unsigned packbf(float v) {
    __nv_bfloat16 h = __float2bfloat16(v);
    __nv_bfloat16 l = __float2bfloat16(v - __bfloat162float(h));
    return (unsigned)__bfloat16_as_ushort(l) | ((unsigned)__bfloat16_as_ushort(h) << 16);
}
__device__ __forceinline__ unsigned bfhi(float v) {
    return (unsigned)__bfloat16_as_ushort(__float2bfloat16(v));
}
__device__ __forceinline__ unsigned bflo(float v) {
    __nv_bfloat16 h = __float2bfloat16(v);
    return (unsigned)__bfloat16_as_ushort(__float2bfloat16(v - __bfloat162float(h)));
}

__device__ float g_t[2][BATCH * CH * PLANE];
__device__ unsigned g_abH[2 * BATCH * CH * 2048];        // [slot*2048+bc][2048] hi bf16x2
__device__ unsigned g_abL[2 * BATCH * CH * 2048];
__device__ unsigned g_fuH[BATCH * PLANE * 64];           // [b][pix][c-pair] hi
__device__ unsigned g_fuL[BATCH * PLANE * 64];
__device__ __align__(16) unsigned char g_wpack[18 * 8 * 8192];
__device__ __align__(16) unsigned char g_awpk[8 * 2 * 128 * 80];  // [chunk][hl][o][80B]
__device__ unsigned g_upH[BATCH * 16384 * 32];
__device__ unsigned g_upL[BATCH * 16384 * 32];
__device__ unsigned g_treb[BATCH * 16384 * 8];
__device__ __align__(16) unsigned char g_w1pack[9 * 4096];
__device__ __align__(16) unsigned char g_w2pack[2 * 11264];
__device__ float g_pool[2][BATCH * CH];
__device__ float g_wk[2][BATCH * CH * 9];

// ---------------- pool + mlp1 fused ----------------
__global__ void poolmlp_kernel(const float* __restrict__ x1, const float* __restrict__ x2,
                               const float* __restrict__ w1, const float* __restrict__ w2) {
    int slot = blockIdx.x >> 4;
    int b = blockIdx.x & 15;
    int tid = threadIdx.x;
    int wid = tid >> 5, lane = tid & 31;
    const float* xb = (slot ? x2 : x1) + (size_t)b * CH * PLANE;
    __shared__ float sp[128], sh[16];
    for (int k = 0; k < 16; k++) {
        int c = wid * 16 + k;
        const float4* v = (const float4*)(xb + (size_t)c * PLANE);
        float s = 0.f;
        #pragma unroll 4
        for (int i = lane; i < 1024; i += 32) {
            float4 q = v[i];
            s += q.x + q.y + q.z + q.w;
        }
        for (int off = 16; off; off >>= 1) s += __shfl_xor_sync(0xffffffffu, s, off);
        if (lane == 0) sp[c] = s * (1.f / 4096.f);
    }
    __syncthreads();
    if (tid < 16) {
        float acc = 0.f;
        #pragma unroll 8
        for (int c = 0; c < 128; c++) acc += sp[c] * w1[tid * 128 + c];
        sh[tid] = 0.5f * acc * (1.f + erff(acc * 0.70710678118654752f));
    }
    __syncthreads();
    if (tid < 128) {
        int c = tid;
        float lg[9];
        float mx = -1e30f;
        #pragma unroll
        for (int k = 0; k < 9; k++) {
            float acc = 0.f;
            #pragma unroll
            for (int r = 0; r < 16; r++) acc += sh[r] * w2[(c * 9 + k) * 16 + r];
            lg[k] = acc;
            mx = fmaxf(mx, acc);
        }
        float ss = 0.f;
        #pragma unroll
        for (int k = 0; k < 9; k++) { lg[k] = expf(lg[k] - mx); ss += lg[k]; }
        float inv = 1.f / ss;
        #pragma unroll
        for (int k = 0; k < 9; k++) g_wk[slot][(b * 128 + c) * 9 + k] = lg[k] * inv;
    }
}

// ---------------- mlp2 ----------------
__global__ void mlp_kernel(const float* __restrict__ w1, const float* __restrict__ w2) {
    int slot = blockIdx.x >> 4;
    int b = blockIdx.x & 15;
    int tid = threadIdx.x;
    __shared__ float sp[128], sh[16];
    sp[tid] = g_pool[slot][b * 128 + tid];
    __syncthreads();
    if (tid < 16) {
        float acc = 0.f;
        #pragma unroll 8
        for (int c = 0; c < 128; c++) acc += sp[c] * w1[tid * 128 + c];
        sh[tid] = 0.5f * acc * (1.f + erff(acc * 0.70710678118654752f));
    }
    __syncthreads();
    int c = tid;
    float lg[9];
    float mx = -1e30f;
    #pragma unroll
    for (int k = 0; k < 9; k++) {
        float acc = 0.f;
        #pragma unroll
        for (int r = 0; r < 16; r++) acc += sh[r] * w2[(c * 9 + k) * 16 + r];
        lg[k] = acc;
        mx = fmaxf(mx, acc);
    }
    float ss = 0.f;
    #pragma unroll
    for (int k = 0; k < 9; k++) { lg[k] = expf(lg[k] - mx); ss += lg[k]; }
    float inv = 1.f / ss;
    #pragma unroll
    for (int k = 0; k < 9; k++) g_wk[slot][(b * 128 + c) * 9 + k] = lg[k] * inv;
}

// ---------------- dsc: depthwise 3x3 + residual; phase1 -> bf16 hi/lo planes ----
__global__ void __launch_bounds__(256, 4) dsc_kernel(const float* __restrict__ x1,
                                                     const float* __restrict__ x2,
                                                     int phase) {
    int slot = blockIdx.x >> 11;
    int bc = blockIdx.x & 2047;
    const float* xext = slot ? x2 : x1;
    const float* src = phase ? &g_t[slot][(size_t)bc * PLANE]
                             : xext + (size_t)bc * PLANE;
    float wk[9];
    #pragma unroll
    for (int k = 0; k < 9; k++) wk[k] = g_wk[slot][bc * 9 + k];
    __shared__ float sp[66][72];
    int tid = threadIdx.x;
    if (tid < 72) { sp[0][tid] = 0.f; sp[65][tid] = 0.f; }
    if (tid < 64) { sp[tid + 1][3] = 0.f; sp[tid + 1][68] = 0.f; }
    {
        int p = tid * 16;
        int h = p >> 6, w = p & 63;
        const float4* s4 = (const float4*)(src + p);
        float4* d = (float4*)&sp[h + 1][w + 4];
        d[0] = s4[0]; d[1] = s4[1]; d[2] = s4[2]; d[3] = s4[3];
    }
    __syncthreads();
    int h = tid >> 2, xb = (tid & 3) * 16;
    float r0[24], r1[24], r2[24];
    #pragma unroll
    for (int k = 0; k < 6; k++) {
        *(float4*)&r0[k * 4] = *(const float4*)&sp[h + 0][xb + k * 4];
        *(float4*)&r1[k * 4] = *(const float4*)&sp[h + 1][xb + k * 4];
        *(float4*)&r2[k * 4] = *(const float4*)&sp[h + 2][xb + k * 4];
    }
    float acc[16];
    #pragma unroll
    for (int j = 0; j < 16; j++) {
        float a = r1[j + 4];
        a += wk[0] * r0[j + 3]; a += wk[1] * r0[j + 4]; a += wk[2] * r0[j + 5];
        a += wk[3] * r1[j + 3]; a += wk[4] * r1[j + 4]; a += wk[5] * r1[j + 5];
        a += wk[6] * r2[j + 3]; a += wk[7] * r2[j + 4]; a += wk[8] * r2[j + 5];
        acc[j] = a;
    }
    if (phase) {
        unsigned hbuf[8], lbuf[8];
        #pragma unroll
        for (int j = 0; j < 8; j++) {
            hbuf[j] = bfhi(acc[2 * j]) | (bfhi(acc[2 * j + 1]) << 16);
            lbuf[j] = bflo(acc[2 * j]) | (bflo(acc[2 * j + 1]) << 16);
        }
        size_t rowoff = ((size_t)slot * 2048 + bc) * 2048 + tid * 8;
        *(uint4*)(g_abH + rowoff) = *(uint4*)hbuf;
        *(uint4*)(g_abH + rowoff + 4) = *(uint4*)(hbuf + 4);
        *(uint4*)(g_abL + rowoff) = *(uint4*)lbuf;
        *(uint4*)(g_abL + rowoff + 4) = *(uint4*)(lbuf + 4);
    } else {
        float* dst = &g_t[slot][(size_t)bc * PLANE];
        int p = tid * 16;
        float psum = 0.f;
        #pragma unroll
        for (int j = 0; j < 16; j++) { acc[j] = fmaxf(acc[j], 0.f); psum += acc[j]; }
        #pragma unroll
        for (int k = 0; k < 4; k++)
            *(float4*)&dst[p + k * 4] = make_float4(acc[k*4], acc[k*4+1], acc[k*4+2], acc[k*4+3]);
        for (int off = 16; off; off >>= 1) psum += __shfl_xor_sync(0xffffffffu, psum, off);
        __shared__ float red[8];
        if ((tid & 31) == 0) red[tid >> 5] = psum;
        __syncthreads();
        if (tid < 32) {
            float r = (tid < 8) ? red[tid] : 0.f;
            for (int off = 4; off; off >>= 1) r += __shfl_xor_sync(0xffffffffu, r, off);
            if (tid == 0) g_pool[slot][bc] = r * (1.f / 4096.f);
        }
    }
}

// ---------------- weight packing (weff + re_w1 + re_w2 + align_w) ----------------
__global__ void __launch_bounds__(256, 2) pack_kernel(const float* __restrict__ aw,
                                                      const float* __restrict__ w1,
                                                      const float* __restrict__ w2,
                                                      const float* __restrict__ rw1,
                                                      const float* __restrict__ rw2) {
    __shared__ float smem_u[2048];
    int tid = threadIdx.x;
    if (blockIdx.x == 512) {
        for (int i = tid; i < 9216; i += 256) {
            int t = i >> 10, rem = i & 1023;
            int row = rem >> 6, c = rem & 63;
            float v = (row < 8) ? rw1[(row * 64 + c) * 9 + t] : 0.f;
            unsigned off = row * 128 + c * 2;
            unsigned sw = off ^ ((off >> 3) & 0x70);
            *(__nv_bfloat16*)(g_w1pack + t * 4096 + sw) = __ushort_as_bfloat16((unsigned short)bfhi(v));
            *(__nv_bfloat16*)(g_w1pack + t * 4096 + 2048 + sw) = __ushort_as_bfloat16((unsigned short)bflo(v));
        }
        return;
    }
    if (blockIdx.x == 513) {
        for (int i = tid; i < 64 * 88; i += 256) {
            int o = i / 88, k = i - o * 88;
            float v = 0.f;
            if (k < 72) { int t = k >> 3, r = k & 7; v = rw2[(o * 8 + r) * 9 + t]; }
            *(__nv_bfloat16*)(g_w2pack + o * 176 + k * 2) = __ushort_as_bfloat16((unsigned short)bfhi(v));
            *(__nv_bfloat16*)(g_w2pack + 11264 + o * 176 + k * 2) = __ushort_as_bfloat16((unsigned short)bflo(v));
        }
        return;
    }
    if (blockIdx.x >= 514) {
        // align_w pack: [chunk8][hl2][o128][cc32] rows stride 80B
        int bi = blockIdx.x - 514;   // 0..3
        for (int e = bi * 16384 + tid; e < (bi + 1) * 16384; e += 256) {
            int cc = e & 31, rem = e >> 5;
            int o = rem & 127, rem2 = rem >> 7;
            int pl = rem2 & 1, chunk = rem2 >> 1;
            float v = aw[o * 256 + chunk * 32 + cc];
            unsigned bits = pl ? bflo(v) : bfhi(v);
            *(__nv_bfloat16*)(g_awpk + ((chunk * 2 + pl) * 128 + o) * 80 + cc * 2) =
                __ushort_as_bfloat16((unsigned short)bits);
        }
        return;
    }
    // weff: W_eff[sub][o][ci][t] -> packed bf16 hi/lo tiles [o][c64] SW128
    int sub = blockIdx.x >> 7, ci = blockIdx.x & 127;
    float* s1 = smem_u;   // 1152 floats
    for (int i = tid; i < 1152; i += 256) {
        int c = i / 9, t = i - c * 9;
        s1[i] = w1[((size_t)(c * 4 + sub) * 128 + ci) * 9 + t];
    }
    __syncthreads();
    if (tid < 64) {
        int o = tid;
        float acc[9] = {0.f,0.f,0.f,0.f,0.f,0.f,0.f,0.f,0.f};
        for (int c = 0; c < 128; c++) {
            float wv = w2[o * 128 + c];
            #pragma unroll
            for (int t = 0; t < 9; t++) acc[t] += wv * s1[c * 9 + t];
        }
        int g = ci >> 6, cl = ci & 63;
        unsigned off = ((o >> 3) << 10) + ((o & 7) << 7) + (cl << 1);
        unsigned sw = off ^ ((off >> 3) & 0x70);
        #pragma unroll
        for (int t = 0; t < 9; t++) {
            float v = acc[t];
            unsigned char* base = g_wpack + ((size_t)((t * 2 + g) * 8 + sub * 2)) * 8192;
            *(__nv_bfloat16*)(base + sw) = __ushort_as_bfloat16((unsigned short)bfhi(v));
            *(__nv_bfloat16*)(base + 8192 + sw) = __ushort_as_bfloat16((unsigned short)bflo(v));
        }
    }
}

// ---------------- align via mma.sync: fused = concat(ab) @ aw^T ----------------
// grid 512 = 16 b x 32 ptiles; M=128 px, N=128 o, K=256; ldmatrix.trans for A
#define ALN_BUF 36864
#define ALN_SMEM (2 * ALN_BUF + 1024)
__global__ void __launch_bounds__(256, 1) align_mma() {
    extern __shared__ char dynraw[];
    char* base = (char*)((((uintptr_t)dynraw) + 1023) & ~(uintptr_t)1023);
    int tid = threadIdx.x;
    int w = tid >> 5, lane = tid & 31;
    int b = blockIdx.x >> 5;
    int pix0 = (blockIdx.x & 31) * 128;

    float acc[4][4][4];
    #pragma unroll
    for (int mt = 0; mt < 4; mt++)
        #pragma unroll
        for (int nt = 0; nt < 4; nt++)
            #pragma unroll
            for (int r = 0; r < 4; r++) acc[mt][nt][r] = 0.f;

    auto fill = [&](int chunk, int buf) {
        char* bb = base + buf * ALN_BUF;
        // A: 2 planes x 32 c x 16 chunks of 16B; smem rows 256B swizzled
        for (int i = tid; i < 1024; i += 256) {
            int pl = i >> 9, r = i & 511;
            int cc = r >> 4, j = r & 15;
            int gc = chunk * 32 + cc;
            size_t row = (size_t)((gc >> 7) * 2048 + b * 128 + (gc & 127));
            const unsigned* src = (pl ? g_abL : g_abH) + row * 2048 + (pix0 >> 1) + j * 4;
            unsigned off = (unsigned)(cc * 256 + j * 16);
            unsigned sw = off ^ ((off >> 4) & 0xF0);
            cp16(smaddr(bb + pl * 8192) + sw, src);
        }
        // B: 2 planes x 128 o x 5 chunks of 16B (80B rows)
        for (int i = tid; i < 1280; i += 256) {
            int pl = i >= 640, r = pl ? i - 640 : i;
            int o = r / 5, j = r - o * 5;
            const unsigned char* src = g_awpk + (size_t)chunk * 20480 + pl * 10240 + o * 80 + j * 16;
            cp16(smaddr(bb + 16384 + pl * 10240) + o * 80 + j * 16, src);
        }
    };

    fill(0, 0);
    cp_commit(); cp_wait0();
    __syncthreads();

    int m0 = (w & 1) * 64, n0 = (w >> 1) * 32;
    for (int chunk = 0; chunk < 8; chunk++) {
        int buf = chunk & 1;
        if (chunk < 7) { fill(chunk + 1, buf ^ 1); cp_commit(); }
        char* bb = base + buf * ALN_BUF;
        unsigned aHiB = smaddr(bb), aLoB = smaddr(bb + 8192);
        unsigned bHiB = smaddr(bb + 16384), bLoB = smaddr(bb + 26624);
        #pragma unroll
        for (int kt = 0; kt < 2; kt++) {
            int c0 = kt * 16;
            unsigned bH[2][4], bL[2][4];
            #pragma unroll
            for (int nh = 0; nh < 2; nh++) {
                unsigned boff = (unsigned)((n0 + nh * 16 + (lane & 15)) * 80 + c0 * 2 + ((lane >> 4) << 4));
                ldsm4(bH[nh], bHiB + boff);
                ldsm4(bL[nh], bLoB + boff);
            }
            #pragma unroll
            for (int mt = 0; mt < 4; mt++) {
                unsigned aoff = (unsigned)(((lane & 7) + ((lane >> 4) << 3) + c0) * 256
                                           + (m0 + mt * 16 + (((lane >> 3) & 1) << 3)) * 2);
                unsigned asw = aoff ^ ((aoff >> 4) & 0xF0);
                unsigned aH[4], aL[4];
                ldsm4t(aH, aHiB + asw);
                ldsm4t(aL, aLoB + asw);
                #pragma unroll
                for (int nh = 0; nh < 2; nh++) {
                    float* dA = acc[mt][2 * nh];
                    float* dB = acc[mt][2 * nh + 1];
                    mma_bf16(dA, aH, bH[nh][0], bH[nh][2]);
                    mma_bf16(dB, aH, bH[nh][1], bH[nh][3]);
                    mma_bf16(dA, aH, bL[nh][0], bL[nh][2]);
                    mma_bf16(dB, aH, bL[nh][1], bL[nh][3]);
                    mma_bf16(dA, aL, bH[nh][0], bH[nh][2]);
                    mma_bf16(dB, aL, bH[nh][1], bH[nh][3]);
                }
            }
        }
        if (chunk < 7) cp_wait0();
        __syncthreads();
    }

    // epilogue: d0/d1 are adjacent o -> one hi word + one lo word per pair
    unsigned* fH = g_fuH + (size_t)b * PLANE * 64;
    unsigned* fL = g_fuL + (size_t)b * PLANE * 64;
    #pragma unroll
    for (int mt = 0; mt < 4; mt++) {
        #pragma unroll
        for (int nt = 0; nt < 4; nt++) {
            float* d = acc[mt][nt];
            int row = pix0 + m0 + mt * 16 + (lane >> 2);
            int op = ((n0 + nt * 8) >> 1) + (lane & 3);
            fH[(size_t)row * 64 + op] = bfhi(d[0]) | (bfhi(d[1]) << 16);
            fL[(size_t)row * 64 + op] = bflo(d[0]) | (bflo(d[1]) << 16);
            fH[(size_t)(row + 8) * 64 + op] = bfhi(d[2]) | (bfhi(d[3]) << 16);
            fL[(size_t)(row + 8) * 64 + op] = bflo(d[2]) | (bflo(d[3]) << 16);
        }
    }
}

// ---------------- upconv via mma.sync bf16 split, fully async fills -------------
#define UPC_BUF 98304
#define UPC_SMEM (2 * UPC_BUF + 1024)
__global__ void __launch_bounds__(256, 1) upconv_mma(float* __restrict__ out) {
    extern __shared__ char dynraw[];
    char* base = (char*)((((uintptr_t)dynraw) + 1023) & ~(uintptr_t)1023);
    int tid = threadIdx.x;
    int w = tid >> 5, lane = tid & 31;
    int b = blockIdx.x >> 5;
    int y0 = (blockIdx.x & 31) * 2;

    const unsigned* fH = g_fuH + (size_t)b * PLANE * 64;
    const unsigned* fL = g_fuL + (size_t)b * PLANE * 64;
    int m = tid >> 1, plane = tid & 1;
    int mrow = m >> 6, mx = m & 63;

    float acc[4][8][4];
    #pragma unroll
    for (int s = 0; s < 4; s++)
        #pragma unroll
        for (int nf = 0; nf < 8; nf++)
            #pragma unroll
            for (int r = 0; r < 4; r++) acc[s][nf][r] = 0.f;

    auto fill = [&](int q, int buf) {
        char* bb = base + buf * UPC_BUF;
        int tap = q >> 1, g = q & 1;
        int kh = tap / 3, kw = tap - kh * 3;
        {
            const unsigned char* bsrc = g_wpack + (size_t)q * 65536;
            unsigned bdst = smaddr(bb + 32768);
            #pragma unroll 4
            for (int i = tid; i < 4096; i += 256)
                cp16(bdst + i * 16, bsrc + i * 16);
        }
        {
            int yy = y0 + mrow + kh - 1;
            int xx = mx + kw - 1;
            int valid = (((unsigned)yy < 64u) && ((unsigned)xx < 64u)) ? 1 : 0;
            const unsigned* src = (plane ? fL : fH) + ((size_t)(yy * 64 + xx) * 64 + g * 32);
            unsigned dstb = smaddr(bb + plane * 16384);
            unsigned db = (unsigned)(m * 128);
            #pragma unroll
            for (int j = 0; j < 8; j++) {
                unsigned off = db + j * 16;
                unsigned sw = off ^ ((off >> 3) & 0x70);
                cp16z(dstb + sw, src + j * 4, valid);
            }
        }
    };

    fill(0, 0);
    cp_commit(); cp_wait0();
    __syncthreads();

    for (int q = 0; q < 18; q++) {
        int buf = q & 1;
        if (q < 17) { fill(q + 1, buf ^ 1); cp_commit(); }
        char* bb = base + buf * UPC_BUF;
        unsigned aHiB = smaddr(bb), aLoB = smaddr(bb + 16384);
        unsigned bB = smaddr(bb + 32768);
        #pragma unroll
        for (int kf = 0; kf < 4; kf++) {
            unsigned aH[4], aL[4];
            {
                unsigned arow = (unsigned)(16 * w + (lane & 15));
                unsigned aoff = arow * 128 + kf * 32 + ((lane >> 4) << 4);
                unsigned asw = aoff ^ ((aoff >> 3) & 0x70);
                ldsm4(aH, aHiB + asw);
                ldsm4(aL, aLoB + asw);
            }
            #pragma unroll
            for (int s = 0; s < 4; s++) {
                #pragma unroll
                for (int n0g = 0; n0g < 4; n0g++) {
                    unsigned brow = (unsigned)(16 * n0g + (lane & 15));
                    unsigned boff = brow * 128 + kf * 32 + ((lane >> 4) << 4);
                    unsigned bsw = boff ^ ((boff >> 3) & 0x70);
                    unsigned bH[4], bL[4];
                    ldsm4(bH, bB + s * 16384 + bsw);
                    ldsm4(bL, bB + s * 16384 + 8192 + bsw);
                    float* dA = acc[s][2 * n0g];
                    float* dB = acc[s][2 * n0g + 1];
                    mma_bf16(dA, aH, bH[0], bH[2]);
                    mma_bf16(dB, aH, bH[1], bH[3]);
                    mma_bf16(dA, aH, bL[0], bL[2]);
                    mma_bf16(dB, aH, bL[1], bL[3]);
                    mma_bf16(dA, aL, bH[0], bH[2]);
                    mma_bf16(dB, aL, bH[1], bH[3]);
                }
            }
        }
        if (q < 17) cp_wait0();
        __syncthreads();
    }

    float2* s2 = (float2*)base;
    unsigned* uH = g_upH + (size_t)b * 16384 * 32;
    unsigned* uL = g_upL + (size_t)b * 16384 * 32;
    int m0 = 16 * w + (lane >> 2);
    int ocol = (lane & 3) * 2;
    #pragma unroll
    for (int sp = 0; sp < 2; sp++) {
        __syncthreads();
        #pragma unroll
        for (int nf = 0; nf < 8; nf++) {
            int o = nf * 8 + ocol;
            s2[m0 * 65 + o]         = make_float2(acc[2*sp][nf][0], acc[2*sp+1][nf][0]);
            s2[m0 * 65 + o + 1]     = make_float2(acc[2*sp][nf][1], acc[2*sp+1][nf][1]);
            s2[(m0 + 8) * 65 + o]   = make_float2(acc[2*sp][nf][2], acc[2*sp+1][nf][2]);
            s2[(m0 + 8) * 65 + o+1] = make_float2(acc[2*sp][nf][3], acc[2*sp+1][nf][3]);
        }
        __syncthreads();
        for (int i = tid; i < 8192; i += 256) {
            int mr = i >> 12, o = (i >> 6) & 63, xx = i & 63;
            int y = 2 * (y0 + mr) + sp;
            *(float2*)(out + (((size_t)(b * 64 + o) * 128 + y) * 128 + 2 * xx)) =
                s2[(mr * 64 + xx) * 65 + o];
        }
        for (int i = tid; i < 8192; i += 256) {
            int mr = i >> 12, x2 = (i >> 5) & 127, op = i & 31;
            int y = 2 * (y0 + mr) + sp;
            float2 va = s2[(mr * 64 + (x2 >> 1)) * 65 + 2 * op];
            float2 vb = s2[(mr * 64 + (x2 >> 1)) * 65 + 2 * op + 1];
            float v0 = (x2 & 1) ? va.y : va.x;
            float v1 = (x2 & 1) ? vb.y : vb.x;
            uH[(size_t)(y * 128 + x2) * 32 + op] = bfhi(v0) | (bfhi(v1) << 16);
            uL[(size_t)(y * 128 + x2) * 32 + op] = bflo(v0) | (bflo(v1) << 16);
        }
    }
}

// ---------------- reconv1 via mma: tre = relu(conv3x3(up, re_w1)), 2 rows/block --
#define RC1_SMEM (66560 * 2 + 36864 + 1024)
__global__ void __launch_bounds__(256, 1) reconv1_mma() {
    extern __shared__ char dynraw[];
    char* base = (char*)((((uintptr_t)dynraw) + 1023) & ~(uintptr_t)1023);
    char* aHi = base;
    char* aLo = base + 66560;
    char* sB  = base + 133120;
    int tid = threadIdx.x;
    int w = tid >> 5, lane = tid & 31;
    int b = blockIdx.x >> 6;
    int y0 = (blockIdx.x & 63) * 2;
    const unsigned* uH = g_upH + (size_t)b * 16384 * 32;
    const unsigned* uL = g_upL + (size_t)b * 16384 * 32;

    {
        unsigned bdst = smaddr(sB);
        for (int i = tid; i < 2304; i += 256)
            cp16(bdst + i * 16, g_w1pack + i * 16);
    }
    unsigned aHiB = smaddr(aHi), aLoB = smaddr(aLo);
    for (int u = tid; u < 4160; u += 256) {
        int slot = u >> 3, j = u & 7;
        int r = slot / 130, xi = slot - r * 130;
        int gy = y0 + r - 1, gx = xi - 1;
        int valid = (((unsigned)gy < 128u) && ((unsigned)gx < 128u)) ? 1 : 0;
        size_t sidx = (size_t)(gy * 128 + gx) * 32 + j * 4;
        unsigned off = (unsigned)(slot * 128 + j * 16);
        unsigned sw = off ^ ((off >> 3) & 0x70);
        cp16z(aHiB + sw, uH + sidx, valid);
        cp16z(aLoB + sw, uL + sidx, valid);
    }
    cp_commit(); cp_wait0();
    __syncthreads();

    unsigned bB = smaddr(sB);
    float d[2][4];
    #pragma unroll
    for (int ys = 0; ys < 2; ys++)
        #pragma unroll
        for (int r = 0; r < 4; r++) d[ys][r] = 0.f;
    int x0 = 16 * w;
    for (int t = 0; t < 9; t++) {
        int kh = t / 3, kw = t - kh * 3;
        #pragma unroll
        for (int kf = 0; kf < 4; kf++) {
            unsigned bH[4], bL[4];
            unsigned boff = (unsigned)((lane & 15) * 128 + kf * 32 + ((lane >> 4) << 4));
            unsigned bsw = boff ^ ((boff >> 3) & 0x70);
            ldsm4(bH, bB + t * 4096 + bsw);
            ldsm4(bL, bB + t * 4096 + 2048 + bsw);
            #pragma unroll
            for (int ys = 0; ys < 2; ys++) {
                int slot = (ys + kh) * 130 + x0 + (lane & 15) + kw;
                unsigned aoff = (unsigned)(slot * 128 + kf * 32 + ((lane >> 4) << 4));
                unsigned asw = aoff ^ ((aoff >> 3) & 0x70);
                unsigned aH[4], aL[4];
                ldsm4(aH, aHiB + asw);
                ldsm4(aL, aLoB + asw);
                mma_bf16(d[ys], aH, bH[0], bH[2]);
                mma_bf16(d[ys], aH, bL[0], bL[2]);
                mma_bf16(d[ys], aL, bH[0], bH[2]);
            }
        }
    }
    int r = lane >> 2, c = (lane & 3) * 2;
    int px = x0 + r;
    #pragma unroll
    for (int ys = 0; ys < 2; ys++) {
        unsigned* tb = g_treb + ((size_t)b * 16384 + (y0 + ys) * 128) * 8;
        tb[px * 8 + c]           = packbf(fmaxf(d[ys][0], 0.f));
        tb[px * 8 + c + 1]       = packbf(fmaxf(d[ys][1], 0.f));
        tb[(px + 8) * 8 + c]     = packbf(fmaxf(d[ys][2], 0.f));
        tb[(px + 8) * 8 + c + 1] = packbf(fmaxf(d[ys][3], 0.f));
    }
}

// ---------------- reconv2 via mma: out += conv3x3(tre, re_w2) -------------------
#define RC2_SMEM (12480 + 22528 + 22528 + 22528 + 1024)
__global__ void __launch_bounds__(256, 2) reconv2_mma(float* __restrict__ out) {
    extern __shared__ char dynraw2[];
    char* base = (char*)((((uintptr_t)dynraw2) + 1023) & ~(uintptr_t)1023);
    unsigned* sTre = (unsigned*)base;
    char* aHi = base + 12480;
    char* aLo = base + 12480 + 22528;
    char* sB  = base + 12480 + 45056;
    int tid = threadIdx.x;
    int w = tid >> 5, lane = tid & 31;
    int b = blockIdx.x >> 7;
    int y = blockIdx.x & 127;
    const unsigned* tb = g_treb + (size_t)b * 16384 * 8;

    {
        unsigned bdst = smaddr(sB);
        for (int i = tid; i < 1408; i += 256)
            cp16(bdst + i * 16, g_w2pack + i * 16);
        cp_commit();
    }
    for (int u = tid; u < 780; u += 256) {
        int slot = u >> 1, hf = u & 1;
        int r = slot / 130, xi = slot - r * 130;
        int gy = y + r - 1, gx = xi - 1;
        uint4 v = make_uint4(0u,0u,0u,0u);
        if (((unsigned)gy < 128u) && ((unsigned)gx < 128u))
            v = *((const uint4*)(tb + (size_t)(gy * 128 + gx) * 8) + hf);
        *((uint4*)(sTre + slot * 8) + hf) = v;
    }
    __syncthreads();
    for (int u = tid; u < 1152; u += 256) {
        int x = u / 9, t = u - x * 9;
        int kh = t / 3, kw = t - kh * 3;
        const unsigned* src = sTre + (kh * 130 + x + kw) * 8;
        uint4 w0 = *(const uint4*)src;
        uint4 w1 = *(const uint4*)(src + 4);
        uint4 hi, lo;
        hi.x = prmt(w0.x, w0.y, 0x7632); hi.y = prmt(w0.z, w0.w, 0x7632);
        hi.z = prmt(w1.x, w1.y, 0x7632); hi.w = prmt(w1.z, w1.w, 0x7632);
        lo.x = prmt(w0.x, w0.y, 0x5410); lo.y = prmt(w0.z, w0.w, 0x5410);
        lo.z = prmt(w1.x, w1.y, 0x5410); lo.w = prmt(w1.z, w1.w, 0x5410);
        *(uint4*)(aHi + x * 176 + t * 16) = hi;
        *(uint4*)(aLo + x * 176 + t * 16) = lo;
    }
    for (int u = tid; u < 128; u += 256) {
        uint4 z = make_uint4(0u,0u,0u,0u);
        *(uint4*)(aHi + u * 176 + 144) = z;
        *(uint4*)(aLo + u * 176 + 144) = z;
    }
    cp_wait0();
    __syncthreads();

    unsigned aHiB = smaddr(aHi), aLoB = smaddr(aLo), bB = smaddr(sB);
    float acc[4][2][4];
    #pragma unroll
    for (int g = 0; g < 4; g++)
        #pragma unroll
        for (int nf = 0; nf < 2; nf++)
            #pragma unroll
            for (int r = 0; r < 4; r++) acc[g][nf][r] = 0.f;
    int x0 = 16 * w;
    #pragma unroll
    for (int kf = 0; kf < 5; kf++) {
        unsigned aH[4], aL[4];
        unsigned aoff = (unsigned)((x0 + (lane & 15)) * 176 + kf * 32 + ((lane >> 4) << 4));
        ldsm4(aH, aHiB + aoff);
        ldsm4(aL, aLoB + aoff);
        #pragma unroll
        for (int n0g = 0; n0g < 4; n0g++) {
            unsigned bH[4], bL[4];
            unsigned boff = (unsigned)((16 * n0g + (lane & 15)) * 176 + kf * 32 + ((lane >> 4) << 4));
            ldsm4(bH, bB + boff);
            ldsm4(bL, bB + 11264 + boff);
            float* dA = acc[n0g][0];
            float* dB = acc[n0g][1];
            mma_bf16(dA, aH, bH[0], bH[2]);
            mma_bf16(dB, aH, bH[1], bH[3]);
            mma_bf16(dA, aH, bL[0], bL[2]);
            mma_bf16(dB, aH, bL[1], bL[3]);
            mma_bf16(dA, aL, bH[0], bH[2]);
            mma_bf16(dB, aL, bH[1], bH[3]);
        }
    }
    __syncthreads();
    float* sD = (float*)aHi;
    {
        int r = lane >> 2, c = (lane & 3) * 2;
        int px = x0 + r;
        #pragma unroll
        for (int n0g = 0; n0g < 4; n0g++)
            #pragma unroll
            for (int nf = 0; nf < 2; nf++) {
                int o = n0g * 16 + nf * 8 + c;
                sD[px * 65 + o]           = acc[n0g][nf][0];
                sD[px * 65 + o + 1]       = acc[n0g][nf][1];
                sD[(px + 8) * 65 + o]     = acc[n0g][nf][2];
                sD[(px + 8) * 65 + o + 1] = acc[n0g][nf][3];
            }
    }
    __syncthreads();
    for (int i = tid; i < 8192; i += 256) {
        int o = i >> 7, x = i & 127;
        out[((size_t)(b * 64 + o) * 128 + y) * 128 + x] += sD[x * 65 + o];
    }
}

// ---------------------------------------------------------------------------
extern "C" void kernel_launch(void* const* d_in, const int* in_sizes, int n_in,
                              void* d_out, int out_size) {
    const float* x1    = (const float*)d_in[0];
    const float* x2    = (const float*)d_in[1];
    const float* d1_w1 = (const float*)d_in[2];
    const float* d1_w2 = (const float*)d_in[3];
    const float* d2_w1 = (const float*)d_in[4];
    const float* d2_w2 = (const float*)d_in[5];
    const float* align_w = (const float*)d_in[6];
    const float* up_w1 = (const float*)d_in[7];
    const float* up_w2 = (const float*)d_in[8];
    const float* re_w1 = (const float*)d_in[9];
    const float* re_w2 = (const float*)d_in[10];
    float* out = (float*)d_out;

    static int smem_set = 0;
    if (!smem_set) {
        cudaFuncSetAttribute(align_mma, cudaFuncAttributeMaxDynamicSharedMemorySize, ALN_SMEM);
        cudaFuncSetAttribute(upconv_mma, cudaFuncAttributeMaxDynamicSharedMemorySize, UPC_SMEM);
        cudaFuncSetAttribute(reconv1_mma, cudaFuncAttributeMaxDynamicSharedMemorySize, RC1_SMEM);
        cudaFuncSetAttribute(reconv2_mma, cudaFuncAttributeMaxDynamicSharedMemorySize, RC2_SMEM);
        smem_set = 1;
    }

    pack_kernel<<<518, 256>>>(align_w, up_w1, up_w2, re_w1, re_w2);
    poolmlp_kernel<<<32, 256>>>(x1, x2, d1_w1, d1_w2);
    dsc_kernel<<<4096, 256>>>(x1, x2, 0);
    mlp_kernel<<<32, 128>>>(d2_w1, d2_w2);
    dsc_kernel<<<4096, 256>>>(x1, x2, 1);
    align_mma<<<512, 256, ALN_SMEM>>>();
    upconv_mma<<<512, 256, UPC_SMEM>>>(out);
    reconv1_mma<<<1024, 256, RC1_SMEM>>>();
    reconv2_mma<<<2048, 256, RC2_SMEM>>>(out);
}

// round 11
// speedup vs baseline: 1.1962x; 1.0517x over previous
#include <cuda_runtime.h>
#include <cuda_bf16.h>
#include <math.h>
#include <stdint.h>

// ---------------------------------------------------------------------------
// DSFDecoder: B=16, C=128, H=W=64, OUT=64, CR=16, RE=8
// All GEMM-shaped work on mma.sync bf16 (split hi/lo, 3 terms).
// R11: pack+poolmlp merged; mlp ILP; align occupancy 2.
// ---------------------------------------------------------------------------

#define PLANE 4096
#define CH    128
#define BATCH 16

typedef unsigned long long ull;

__device__ __forceinline__ unsigned smaddr(const void* p) {
    return (unsigned)__cvta_generic_to_shared(p);
}
__device__ __forceinline__ void cp16(unsigned d, const void* s) {
    asm volatile("cp.async.cg.shared.global [%0], [%1], 16;" :: "r"(d), "l"(s) : "memory");
}
__device__ __forceinline__ void cp16z(unsigned d, const void* s, int valid) {
    asm volatile("cp.async.cg.shared.global [%0], [%1], 16, %2;"
                 :: "r"(d), "l"(s), "r"(valid ? 16 : 0) : "memory");
}
__device__ __forceinline__ void cp_commit() {
    asm volatile("cp.async.commit_group;" ::: "memory");
}
__device__ __forceinline__ void cp_wait0() {
    asm volatile("cp.async.wait_group 0;" ::: "memory");
}
__device__ __forceinline__ unsigned prmt(unsigned a, unsigned b, unsigned sel) {
    unsigned r; asm("prmt.b32 %0, %1, %2, %3;" : "=r"(r) : "r"(a), "r"(b), "r"(sel));
    return r;
}
__device__ __forceinline__ void ldsm4(unsigned* r, unsigned addr) {
    asm volatile("ldmatrix.sync.aligned.m8n8.x4.shared.b16 {%0,%1,%2,%3}, [%4];"
                 : "=r"(r[0]), "=r"(r[1]), "=r"(r[2]), "=r"(r[3]) : "r"(addr));
}
__device__ __forceinline__ void ldsm4t(unsigned* r, unsigned addr) {
    asm volatile("ldmatrix.sync.aligned.m8n8.x4.trans.shared.b16 {%0,%1,%2,%3}, [%4];"
                 : "=r"(r[0]), "=r"(r[1]), "=r"(r[2]), "=r"(r[3]) : "r"(addr));
}
__device__ __forceinline__ void mma_bf16(float* d, const unsigned* a, unsigned b0, unsigned b1) {
    asm volatile(
        "mma.sync.aligned.m16n8k16.row.col.f32.bf16.bf16.f32 "
        "{%0,%1,%2,%3}, {%4,%5,%6,%7}, {%8,%9}, {%0,%1,%2,%3};"
        : "+f"(d[0]), "+f"(d[1]), "+f"(d[2]), "+f"(d[3])
        : "r"(a[0]), "r"(a[1]), "r"(a[2]), "r"(a[3]), "r"(b0), "r"(b1));
}
__device__ __forceinline__ unsigned packbf(float v) {
    __nv_bfloat16 h = __float2bfloat16(v);
    __nv_bfloat16 l = __float2bfloat16(v - __bfloat162float(h));
    return (unsigned)__bfloat16_as_ushort(l) | ((unsigned)__bfloat16_as_ushort(h) << 16);
}
__device__ __forceinline__ unsigned bfhi(float v) {
    return (unsigned)__bfloat16_as_ushort(__float2bfloat16(v));
}
__device__ __forceinline__ unsigned bflo(float v) {
    __nv_bfloat16 h = __float2bfloat16(v);
    return (unsigned)__bfloat16_as_ushort(__float2bfloat16(v - __bfloat162float(h)));
}

__device__ float g_t[2][BATCH * CH * PLANE];
__device__ unsigned g_abH[2 * BATCH * CH * 2048];
__device__ unsigned g_abL[2 * BATCH * CH * 2048];
__device__ unsigned g_fuH[BATCH * PLANE * 64];
__device__ unsigned g_fuL[BATCH * PLANE * 64];
__device__ __align__(16) unsigned char g_wpack[18 * 8 * 8192];
__device__ __align__(16) unsigned char g_awpk[8 * 2 * 128 * 80];
__device__ unsigned g_upH[BATCH * 16384 * 32];
__device__ unsigned g_upL[BATCH * 16384 * 32];
__device__ unsigned g_treb[BATCH * 16384 * 8];
__device__ __align__(16) unsigned char g_w1pack[9 * 4096];
__device__ __align__(16) unsigned char g_w2pack[2 * 11264];
__device__ float g_pool[2][BATCH * CH];
__device__ float g_wk[2][BATCH * CH * 9];

// ---------------- pack (0..517) + poolmlp (518..549) merged ----------------
__global__ void __launch_bounds__(256, 2) packpool_kernel(
        const float* __restrict__ aw, const float* __restrict__ w1,
        const float* __restrict__ w2, const float* __restrict__ rw1,
        const float* __restrict__ rw2,
        const float* __restrict__ x1, const float* __restrict__ x2,
        const float* __restrict__ m1w1, const float* __restrict__ m1w2) {
    __shared__ float smem_u[2048];
    int tid = threadIdx.x;
    if (blockIdx.x >= 518) {
        // ---- poolmlp: pool(x) -> mlp1 -> wk1
        int bi = blockIdx.x - 518;
        int slot = bi >> 4;
        int b = bi & 15;
        int wid = tid >> 5, lane = tid & 31;
        const float* xb = (slot ? x2 : x1) + (size_t)b * CH * PLANE;
        float* sp = smem_u;
        float* sh = smem_u + 128;
        for (int k = 0; k < 16; k++) {
            int c = wid * 16 + k;
            const float4* v = (const float4*)(xb + (size_t)c * PLANE);
            float s = 0.f;
            #pragma unroll 4
            for (int i = lane; i < 1024; i += 32) {
                float4 q = v[i];
                s += q.x + q.y + q.z + q.w;
            }
            for (int off = 16; off; off >>= 1) s += __shfl_xor_sync(0xffffffffu, s, off);
            if (lane == 0) sp[c] = s * (1.f / 4096.f);
        }
        __syncthreads();
        if (tid < 16) {
            float acc = 0.f;
            const float4* w1v = (const float4*)(m1w1 + tid * 128);
            #pragma unroll
            for (int j = 0; j < 32; j++) {
                float4 q = w1v[j];
                acc += sp[4*j] * q.x + sp[4*j+1] * q.y + sp[4*j+2] * q.z + sp[4*j+3] * q.w;
            }
            sh[tid] = 0.5f * acc * (1.f + erff(acc * 0.70710678118654752f));
        }
        __syncthreads();
        if (tid < 128) {
            int c = tid;
            const float4* w2v = (const float4*)(m1w2 + c * 144);
            float lg[9];
            float mx = -1e30f;
            #pragma unroll
            for (int k = 0; k < 9; k++) {
                float4 a0 = w2v[k*4], a1 = w2v[k*4+1], a2 = w2v[k*4+2], a3 = w2v[k*4+3];
                float acc = a0.x*sh[0] + a0.y*sh[1] + a0.z*sh[2] + a0.w*sh[3]
                          + a1.x*sh[4] + a1.y*sh[5] + a1.z*sh[6] + a1.w*sh[7]
                          + a2.x*sh[8] + a2.y*sh[9] + a2.z*sh[10] + a2.w*sh[11]
                          + a3.x*sh[12] + a3.y*sh[13] + a3.z*sh[14] + a3.w*sh[15];
                lg[k] = acc;
                mx = fmaxf(mx, acc);
            }
            float ss = 0.f;
            #pragma unroll
            for (int k = 0; k < 9; k++) { lg[k] = expf(lg[k] - mx); ss += lg[k]; }
            float inv = 1.f / ss;
            #pragma unroll
            for (int k = 0; k < 9; k++) g_wk[slot][(b * 128 + c) * 9 + k] = lg[k] * inv;
        }
        return;
    }
    if (blockIdx.x == 512) {
        for (int i = tid; i < 9216; i += 256) {
            int t = i >> 10, rem = i & 1023;
            int row = rem >> 6, c = rem & 63;
            float v = (row < 8) ? rw1[(row * 64 + c) * 9 + t] : 0.f;
            unsigned off = row * 128 + c * 2;
            unsigned sw = off ^ ((off >> 3) & 0x70);
            *(__nv_bfloat16*)(g_w1pack + t * 4096 + sw) = __ushort_as_bfloat16((unsigned short)bfhi(v));
            *(__nv_bfloat16*)(g_w1pack + t * 4096 + 2048 + sw) = __ushort_as_bfloat16((unsigned short)bflo(v));
        }
        return;
    }
    if (blockIdx.x == 513) {
        for (int i = tid; i < 64 * 88; i += 256) {
            int o = i / 88, k = i - o * 88;
            float v = 0.f;
            if (k < 72) { int t = k >> 3, r = k & 7; v = rw2[(o * 8 + r) * 9 + t]; }
            *(__nv_bfloat16*)(g_w2pack + o * 176 + k * 2) = __ushort_as_bfloat16((unsigned short)bfhi(v));
            *(__nv_bfloat16*)(g_w2pack + 11264 + o * 176 + k * 2) = __ushort_as_bfloat16((unsigned short)bflo(v));
        }
        return;
    }
    if (blockIdx.x >= 514) {
        int bi = blockIdx.x - 514;
        for (int e = bi * 16384 + tid; e < (bi + 1) * 16384; e += 256) {
            int cc = e & 31, rem = e >> 5;
            int o = rem & 127, rem2 = rem >> 7;
            int pl = rem2 & 1, chunk = rem2 >> 1;
            float v = aw[o * 256 + chunk * 32 + cc];
            unsigned bits = pl ? bflo(v) : bfhi(v);
            *(__nv_bfloat16*)(g_awpk + ((chunk * 2 + pl) * 128 + o) * 80 + cc * 2) =
                __ushort_as_bfloat16((unsigned short)bits);
        }
        return;
    }
    // weff
    int sub = blockIdx.x >> 7, ci = blockIdx.x & 127;
    float* s1 = smem_u;
    for (int i = tid; i < 1152; i += 256) {
        int c = i / 9, t = i - c * 9;
        s1[i] = w1[((size_t)(c * 4 + sub) * 128 + ci) * 9 + t];
    }
    __syncthreads();
    if (tid < 64) {
        int o = tid;
        float acc[9] = {0.f,0.f,0.f,0.f,0.f,0.f,0.f,0.f,0.f};
        for (int c = 0; c < 128; c++) {
            float wv = w2[o * 128 + c];
            #pragma unroll
            for (int t = 0; t < 9; t++) acc[t] += wv * s1[c * 9 + t];
        }
        int g = ci >> 6, cl = ci & 63;
        unsigned off = ((o >> 3) << 10) + ((o & 7) << 7) + (cl << 1);
        unsigned sw = off ^ ((off >> 3) & 0x70);
        #pragma unroll
        for (int t = 0; t < 9; t++) {
            float v = acc[t];
            unsigned char* base = g_wpack + ((size_t)((t * 2 + g) * 8 + sub * 2)) * 8192;
            *(__nv_bfloat16*)(base + sw) = __ushort_as_bfloat16((unsigned short)bfhi(v));
            *(__nv_bfloat16*)(base + 8192 + sw) = __ushort_as_bfloat16((unsigned short)bflo(v));
        }
    }
}

// ---------------- mlp2: ILP-optimized ----------------
__global__ void mlp_kernel(const float* __restrict__ w1, const float* __restrict__ w2) {
    int slot = blockIdx.x >> 4;
    int b = blockIdx.x & 15;
    int tid = threadIdx.x;
    __shared__ float sp[128], sh[16];
    sp[tid] = g_pool[slot][b * 128 + tid];
    __syncthreads();
    if (tid < 16) {
        float acc = 0.f;
        const float4* w1v = (const float4*)(w1 + tid * 128);
        #pragma unroll
        for (int j = 0; j < 32; j++) {
            float4 q = w1v[j];
            acc += sp[4*j] * q.x + sp[4*j+1] * q.y + sp[4*j+2] * q.z + sp[4*j+3] * q.w;
        }
        sh[tid] = 0.5f * acc * (1.f + erff(acc * 0.70710678118654752f));
    }
    __syncthreads();
    int c = tid;
    const float4* w2v = (const float4*)(w2 + c * 144);
    float lg[9];
    float mx = -1e30f;
    #pragma unroll
    for (int k = 0; k < 9; k++) {
        float4 a0 = w2v[k*4], a1 = w2v[k*4+1], a2 = w2v[k*4+2], a3 = w2v[k*4+3];
        float acc = a0.x*sh[0] + a0.y*sh[1] + a0.z*sh[2] + a0.w*sh[3]
                  + a1.x*sh[4] + a1.y*sh[5] + a1.z*sh[6] + a1.w*sh[7]
                  + a2.x*sh[8] + a2.y*sh[9] + a2.z*sh[10] + a2.w*sh[11]
                  + a3.x*sh[12] + a3.y*sh[13] + a3.z*sh[14] + a3.w*sh[15];
        lg[k] = acc;
        mx = fmaxf(mx, acc);
    }
    float ss = 0.f;
    #pragma unroll
    for (int k = 0; k < 9; k++) { lg[k] = expf(lg[k] - mx); ss += lg[k]; }
    float inv = 1.f / ss;
    #pragma unroll
    for (int k = 0; k < 9; k++) g_wk[slot][(b * 128 + c) * 9 + k] = lg[k] * inv;
}

// ---------------- dsc: depthwise 3x3 + residual; phase1 -> bf16 hi/lo planes ----
__global__ void __launch_bounds__(256, 4) dsc_kernel(const float* __restrict__ x1,
                                                     const float* __restrict__ x2,
                                                     int phase) {
    int slot = blockIdx.x >> 11;
    int bc = blockIdx.x & 2047;
    const float* xext = slot ? x2 : x1;
    const float* src = phase ? &g_t[slot][(size_t)bc * PLANE]
                             : xext + (size_t)bc * PLANE;
    float wk[9];
    #pragma unroll
    for (int k = 0; k < 9; k++) wk[k] = g_wk[slot][bc * 9 + k];
    __shared__ float sp[66][72];
    int tid = threadIdx.x;
    if (tid < 72) { sp[0][tid] = 0.f; sp[65][tid] = 0.f; }
    if (tid < 64) { sp[tid + 1][3] = 0.f; sp[tid + 1][68] = 0.f; }
    {
        int p = tid * 16;
        int h = p >> 6, w = p & 63;
        const float4* s4 = (const float4*)(src + p);
        float4* d = (float4*)&sp[h + 1][w + 4];
        d[0] = s4[0]; d[1] = s4[1]; d[2] = s4[2]; d[3] = s4[3];
    }
    __syncthreads();
    int h = tid >> 2, xb = (tid & 3) * 16;
    float r0[24], r1[24], r2[24];
    #pragma unroll
    for (int k = 0; k < 6; k++) {
        *(float4*)&r0[k * 4] = *(const float4*)&sp[h + 0][xb + k * 4];
        *(float4*)&r1[k * 4] = *(const float4*)&sp[h + 1][xb + k * 4];
        *(float4*)&r2[k * 4] = *(const float4*)&sp[h + 2][xb + k * 4];
    }
    float acc[16];
    #pragma unroll
    for (int j = 0; j < 16; j++) {
        float a = r1[j + 4];
        a += wk[0] * r0[j + 3]; a += wk[1] * r0[j + 4]; a += wk[2] * r0[j + 5];
        a += wk[3] * r1[j + 3]; a += wk[4] * r1[j + 4]; a += wk[5] * r1[j + 5];
        a += wk[6] * r2[j + 3]; a += wk[7] * r2[j + 4]; a += wk[8] * r2[j + 5];
        acc[j] = a;
    }
    if (phase) {
        unsigned hbuf[8], lbuf[8];
        #pragma unroll
        for (int j = 0; j < 8; j++) {
            hbuf[j] = bfhi(acc[2 * j]) | (bfhi(acc[2 * j + 1]) << 16);
            lbuf[j] = bflo(acc[2 * j]) | (bflo(acc[2 * j + 1]) << 16);
        }
        size_t rowoff = ((size_t)slot * 2048 + bc) * 2048 + tid * 8;
        *(uint4*)(g_abH + rowoff) = *(uint4*)hbuf;
        *(uint4*)(g_abH + rowoff + 4) = *(uint4*)(hbuf + 4);
        *(uint4*)(g_abL + rowoff) = *(uint4*)lbuf;
        *(uint4*)(g_abL + rowoff + 4) = *(uint4*)(lbuf + 4);
    } else {
        float* dst = &g_t[slot][(size_t)bc * PLANE];
        int p = tid * 16;
        float psum = 0.f;
        #pragma unroll
        for (int j = 0; j < 16; j++) { acc[j] = fmaxf(acc[j], 0.f); psum += acc[j]; }
        #pragma unroll
        for (int k = 0; k < 4; k++)
            *(float4*)&dst[p + k * 4] = make_float4(acc[k*4], acc[k*4+1], acc[k*4+2], acc[k*4+3]);
        for (int off = 16; off; off >>= 1) psum += __shfl_xor_sync(0xffffffffu, psum, off);
        __shared__ float red[8];
        if ((tid & 31) == 0) red[tid >> 5] = psum;
        __syncthreads();
        if (tid < 32) {
            float r = (tid < 8) ? red[tid] : 0.f;
            for (int off = 4; off; off >>= 1) r += __shfl_xor_sync(0xffffffffu, r, off);
            if (tid == 0) g_pool[slot][bc] = r * (1.f / 4096.f);
        }
    }
}

// ---------------- align via mma.sync ----------------
#define ALN_BUF 36864
#define ALN_SMEM (2 * ALN_BUF + 1024)
__global__ void __launch_bounds__(256, 2) align_mma() {
    extern __shared__ char dynraw[];
    char* base = (char*)((((uintptr_t)dynraw) + 1023) & ~(uintptr_t)1023);
    int tid = threadIdx.x;
    int w = tid >> 5, lane = tid & 31;
    int b = blockIdx.x >> 5;
    int pix0 = (blockIdx.x & 31) * 128;

    float acc[4][4][4];
    #pragma unroll
    for (int mt = 0; mt < 4; mt++)
        #pragma unroll
        for (int nt = 0; nt < 4; nt++)
            #pragma unroll
            for (int r = 0; r < 4; r++) acc[mt][nt][r] = 0.f;

    auto fill = [&](int chunk, int buf) {
        char* bb = base + buf * ALN_BUF;
        for (int i = tid; i < 1024; i += 256) {
            int pl = i >> 9, r = i & 511;
            int cc = r >> 4, j = r & 15;
            int gc = chunk * 32 + cc;
            size_t row = (size_t)((gc >> 7) * 2048 + b * 128 + (gc & 127));
            const unsigned* src = (pl ? g_abL : g_abH) + row * 2048 + (pix0 >> 1) + j * 4;
            unsigned off = (unsigned)(cc * 256 + j * 16);
            unsigned sw = off ^ ((off >> 4) & 0xF0);
            cp16(smaddr(bb + pl * 8192) + sw, src);
        }
        for (int i = tid; i < 1280; i += 256) {
            int pl = i >= 640, r = pl ? i - 640 : i;
            int o = r / 5, j = r - o * 5;
            const unsigned char* src = g_awpk + (size_t)chunk * 20480 + pl * 10240 + o * 80 + j * 16;
            cp16(smaddr(bb + 16384 + pl * 10240) + o * 80 + j * 16, src);
        }
    };

    fill(0, 0);
    cp_commit(); cp_wait0();
    __syncthreads();

    int m0 = (w & 1) * 64, n0 = (w >> 1) * 32;
    for (int chunk = 0; chunk < 8; chunk++) {
        int buf = chunk & 1;
        if (chunk < 7) { fill(chunk + 1, buf ^ 1); cp_commit(); }
        char* bb = base + buf * ALN_BUF;
        unsigned aHiB = smaddr(bb), aLoB = smaddr(bb + 8192);
        unsigned bHiB = smaddr(bb + 16384), bLoB = smaddr(bb + 26624);
        #pragma unroll
        for (int kt = 0; kt < 2; kt++) {
            int c0 = kt * 16;
            unsigned bH[2][4], bL[2][4];
            #pragma unroll
            for (int nh = 0; nh < 2; nh++) {
                unsigned boff = (unsigned)((n0 + nh * 16 + (lane & 15)) * 80 + c0 * 2 + ((lane >> 4) << 4));
                ldsm4(bH[nh], bHiB + boff);
                ldsm4(bL[nh], bLoB + boff);
            }
            #pragma unroll
            for (int mt = 0; mt < 4; mt++) {
                unsigned aoff = (unsigned)(((lane & 7) + ((lane >> 4) << 3) + c0) * 256
                                           + (m0 + mt * 16 + (((lane >> 3) & 1) << 3)) * 2);
                unsigned asw = aoff ^ ((aoff >> 4) & 0xF0);
                unsigned aH[4], aL[4];
                ldsm4t(aH, aHiB + asw);
                ldsm4t(aL, aLoB + asw);
                #pragma unroll
                for (int nh = 0; nh < 2; nh++) {
                    float* dA = acc[mt][2 * nh];
                    float* dB = acc[mt][2 * nh + 1];
                    mma_bf16(dA, aH, bH[nh][0], bH[nh][2]);
                    mma_bf16(dB, aH, bH[nh][1], bH[nh][3]);
                    mma_bf16(dA, aH, bL[nh][0], bL[nh][2]);
                    mma_bf16(dB, aH, bL[nh][1], bL[nh][3]);
                    mma_bf16(dA, aL, bH[nh][0], bH[nh][2]);
                    mma_bf16(dB, aL, bH[nh][1], bH[nh][3]);
                }
            }
        }
        if (chunk < 7) cp_wait0();
        __syncthreads();
    }

    unsigned* fH = g_fuH + (size_t)b * PLANE * 64;
    unsigned* fL = g_fuL + (size_t)b * PLANE * 64;
    #pragma unroll
    for (int mt = 0; mt < 4; mt++) {
        #pragma unroll
        for (int nt = 0; nt < 4; nt++) {
            float* d = acc[mt][nt];
            int row = pix0 + m0 + mt * 16 + (lane >> 2);
            int op = ((n0 + nt * 8) >> 1) + (lane & 3);
            fH[(size_t)row * 64 + op] = bfhi(d[0]) | (bfhi(d[1]) << 16);
            fL[(size_t)row * 64 + op] = bflo(d[0]) | (bflo(d[1]) << 16);
            fH[(size_t)(row + 8) * 64 + op] = bfhi(d[2]) | (bfhi(d[3]) << 16);
            fL[(size_t)(row + 8) * 64 + op] = bflo(d[2]) | (bflo(d[3]) << 16);
        }
    }
}

// ---------------- upconv via mma.sync bf16 split ----------------
#define UPC_BUF 98304
#define UPC_SMEM (2 * UPC_BUF + 1024)
__global__ void __launch_bounds__(256, 1) upconv_mma(float* __restrict__ out) {
    extern __shared__ char dynraw[];
    char* base = (char*)((((uintptr_t)dynraw) + 1023) & ~(uintptr_t)1023);
    int tid = threadIdx.x;
    int w = tid >> 5, lane = tid & 31;
    int b = blockIdx.x >> 5;
    int y0 = (blockIdx.x & 31) * 2;

    const unsigned* fH = g_fuH + (size_t)b * PLANE * 64;
    const unsigned* fL = g_fuL + (size_t)b * PLANE * 64;
    int m = tid >> 1, plane = tid & 1;
    int mrow = m >> 6, mx = m & 63;

    float acc[4][8][4];
    #pragma unroll
    for (int s = 0; s < 4; s++)
        #pragma unroll
        for (int nf = 0; nf < 8; nf++)
            #pragma unroll
            for (int r = 0; r < 4; r++) acc[s][nf][r] = 0.f;

    auto fill = [&](int q, int buf) {
        char* bb = base + buf * UPC_BUF;
        int tap = q >> 1, g = q & 1;
        int kh = tap / 3, kw = tap - kh * 3;
        {
            const unsigned char* bsrc = g_wpack + (size_t)q * 65536;
            unsigned bdst = smaddr(bb + 32768);
            #pragma unroll 4
            for (int i = tid; i < 4096; i += 256)
                cp16(bdst + i * 16, bsrc + i * 16);
        }
        {
            int yy = y0 + mrow + kh - 1;
            int xx = mx + kw - 1;
            int valid = (((unsigned)yy < 64u) && ((unsigned)xx < 64u)) ? 1 : 0;
            const unsigned* src = (plane ? fL : fH) + ((size_t)(yy * 64 + xx) * 64 + g * 32);
            unsigned dstb = smaddr(bb + plane * 16384);
            unsigned db = (unsigned)(m * 128);
            #pragma unroll
            for (int j = 0; j < 8; j++) {
                unsigned off = db + j * 16;
                unsigned sw = off ^ ((off >> 3) & 0x70);
                cp16z(dstb + sw, src + j * 4, valid);
            }
        }
    };

    fill(0, 0);
    cp_commit(); cp_wait0();
    __syncthreads();

    for (int q = 0; q < 18; q++) {
        int buf = q & 1;
        if (q < 17) { fill(q + 1, buf ^ 1); cp_commit(); }
        char* bb = base + buf * UPC_BUF;
        unsigned aHiB = smaddr(bb), aLoB = smaddr(bb + 16384);
        unsigned bB = smaddr(bb + 32768);
        #pragma unroll
        for (int kf = 0; kf < 4; kf++) {
            unsigned aH[4], aL[4];
            {
                unsigned arow = (unsigned)(16 * w + (lane & 15));
                unsigned aoff = arow * 128 + kf * 32 + ((lane >> 4) << 4);
                unsigned asw = aoff ^ ((aoff >> 3) & 0x70);
                ldsm4(aH, aHiB + asw);
                ldsm4(aL, aLoB + asw);
            }
            #pragma unroll
            for (int s = 0; s < 4; s++) {
                #pragma unroll
                for (int n0g = 0; n0g < 4; n0g++) {
                    unsigned brow = (unsigned)(16 * n0g + (lane & 15));
                    unsigned boff = brow * 128 + kf * 32 + ((lane >> 4) << 4);
                    unsigned bsw = boff ^ ((boff >> 3) & 0x70);
                    unsigned bH[4], bL[4];
                    ldsm4(bH, bB + s * 16384 + bsw);
                    ldsm4(bL, bB + s * 16384 + 8192 + bsw);
                    float* dA = acc[s][2 * n0g];
                    float* dB = acc[s][2 * n0g + 1];
                    mma_bf16(dA, aH, bH[0], bH[2]);
                    mma_bf16(dB, aH, bH[1], bH[3]);
                    mma_bf16(dA, aH, bL[0], bL[2]);
                    mma_bf16(dB, aH, bL[1], bL[3]);
                    mma_bf16(dA, aL, bH[0], bH[2]);
                    mma_bf16(dB, aL, bH[1], bH[3]);
                }
            }
        }
        if (q < 17) cp_wait0();
        __syncthreads();
    }

    float2* s2 = (float2*)base;
    unsigned* uH = g_upH + (size_t)b * 16384 * 32;
    unsigned* uL = g_upL + (size_t)b * 16384 * 32;
    int m0 = 16 * w + (lane >> 2);
    int ocol = (lane & 3) * 2;
    #pragma unroll
    for (int sp = 0; sp < 2; sp++) {
        __syncthreads();
        #pragma unroll
        for (int nf = 0; nf < 8; nf++) {
            int o = nf * 8 + ocol;
            s2[m0 * 65 + o]         = make_float2(acc[2*sp][nf][0], acc[2*sp+1][nf][0]);
            s2[m0 * 65 + o + 1]     = make_float2(acc[2*sp][nf][1], acc[2*sp+1][nf][1]);
            s2[(m0 + 8) * 65 + o]   = make_float2(acc[2*sp][nf][2], acc[2*sp+1][nf][2]);
            s2[(m0 + 8) * 65 + o+1] = make_float2(acc[2*sp][nf][3], acc[2*sp+1][nf][3]);
        }
        __syncthreads();
        for (int i = tid; i < 8192; i += 256) {
            int mr = i >> 12, o = (i >> 6) & 63, xx = i & 63;
            int y = 2 * (y0 + mr) + sp;
            *(float2*)(out + (((size_t)(b * 64 + o) * 128 + y) * 128 + 2 * xx)) =
                s2[(mr * 64 + xx) * 65 + o];
        }
        for (int i = tid; i < 8192; i += 256) {
            int mr = i >> 12, x2 = (i >> 5) & 127, op = i & 31;
            int y = 2 * (y0 + mr) + sp;
            float2 va = s2[(mr * 64 + (x2 >> 1)) * 65 + 2 * op];
            float2 vb = s2[(mr * 64 + (x2 >> 1)) * 65 + 2 * op + 1];
            float v0 = (x2 & 1) ? va.y : va.x;
            float v1 = (x2 & 1) ? vb.y : vb.x;
            uH[(size_t)(y * 128 + x2) * 32 + op] = bfhi(v0) | (bfhi(v1) << 16);
            uL[(size_t)(y * 128 + x2) * 32 + op] = bflo(v0) | (bflo(v1) << 16);
        }
    }
}

// ---------------- reconv1 via mma, 2 rows/block ----------------
#define RC1_SMEM (66560 * 2 + 36864 + 1024)
__global__ void __launch_bounds__(256, 1) reconv1_mma() {
    extern __shared__ char dynraw[];
    char* base = (char*)((((uintptr_t)dynraw) + 1023) & ~(uintptr_t)1023);
    char* aHi = base;
    char* aLo = base + 66560;
    char* sB  = base + 133120;
    int tid = threadIdx.x;
    int w = tid >> 5, lane = tid & 31;
    int b = blockIdx.x >> 6;
    int y0 = (blockIdx.x & 63) * 2;
    const unsigned* uH = g_upH + (size_t)b * 16384 * 32;
    const unsigned* uL = g_upL + (size_t)b * 16384 * 32;

    {
        unsigned bdst = smaddr(sB);
        for (int i = tid; i < 2304; i += 256)
            cp16(bdst + i * 16, g_w1pack + i * 16);
    }
    unsigned aHiB = smaddr(aHi), aLoB = smaddr(aLo);
    for (int u = tid; u < 4160; u += 256) {
        int slot = u >> 3, j = u & 7;
        int r = slot / 130, xi = slot - r * 130;
        int gy = y0 + r - 1, gx = xi - 1;
        int valid = (((unsigned)gy < 128u) && ((unsigned)gx < 128u)) ? 1 : 0;
        size_t sidx = (size_t)(gy * 128 + gx) * 32 + j * 4;
        unsigned off = (unsigned)(slot * 128 + j * 16);
        unsigned sw = off ^ ((off >> 3) & 0x70);
        cp16z(aHiB + sw, uH + sidx, valid);
        cp16z(aLoB + sw, uL + sidx, valid);
    }
    cp_commit(); cp_wait0();
    __syncthreads();

    unsigned bB = smaddr(sB);
    float d[2][4];
    #pragma unroll
    for (int ys = 0; ys < 2; ys++)
        #pragma unroll
        for (int r = 0; r < 4; r++) d[ys][r] = 0.f;
    int x0 = 16 * w;
    for (int t = 0; t < 9; t++) {
        int kh = t / 3, kw = t - kh * 3;
        #pragma unroll
        for (int kf = 0; kf < 4; kf++) {
            unsigned bH[4], bL[4];
            unsigned boff = (unsigned)((lane & 15) * 128 + kf * 32 + ((lane >> 4) << 4));
            unsigned bsw = boff ^ ((boff >> 3) & 0x70);
            ldsm4(bH, bB + t * 4096 + bsw);
            ldsm4(bL, bB + t * 4096 + 2048 + bsw);
            #pragma unroll
            for (int ys = 0; ys < 2; ys++) {
                int slot = (ys + kh) * 130 + x0 + (lane & 15) + kw;
                unsigned aoff = (unsigned)(slot * 128 + kf * 32 + ((lane >> 4) << 4));
                unsigned asw = aoff ^ ((aoff >> 3) & 0x70);
                unsigned aH[4], aL[4];
                ldsm4(aH, aHiB + asw);
                ldsm4(aL, aLoB + asw);
                mma_bf16(d[ys], aH, bH[0], bH[2]);
                mma_bf16(d[ys], aH, bL[0], bL[2]);
                mma_bf16(d[ys], aL, bH[0], bH[2]);
            }
        }
    }
    int r = lane >> 2, c = (lane & 3) * 2;
    int px = x0 + r;
    #pragma unroll
    for (int ys = 0; ys < 2; ys++) {
        unsigned* tb = g_treb + ((size_t)b * 16384 + (y0 + ys) * 128) * 8;
        tb[px * 8 + c]           = packbf(fmaxf(d[ys][0], 0.f));
        tb[px * 8 + c + 1]       = packbf(fmaxf(d[ys][1], 0.f));
        tb[(px + 8) * 8 + c]     = packbf(fmaxf(d[ys][2], 0.f));
        tb[(px + 8) * 8 + c + 1] = packbf(fmaxf(d[ys][3], 0.f));
    }
}

// ---------------- reconv2 via mma ----------------
#define RC2_SMEM (12480 + 22528 + 22528 + 22528 + 1024)
__global__ void __launch_bounds__(256, 2) reconv2_mma(float* __restrict__ out) {
    extern __shared__ char dynraw2[];
    char* base = (char*)((((uintptr_t)dynraw2) + 1023) & ~(uintptr_t)1023);
    unsigned* sTre = (unsigned*)base;
    char* aHi = base + 12480;
    char* aLo = base + 12480 + 22528;
    char* sB  = base + 12480 + 45056;
    int tid = threadIdx.x;
    int w = tid >> 5, lane = tid & 31;
    int b = blockIdx.x >> 7;
    int y = blockIdx.x & 127;
    const unsigned* tb = g_treb + (size_t)b * 16384 * 8;

    {
        unsigned bdst = smaddr(sB);
        for (int i = tid; i < 1408; i += 256)
            cp16(bdst + i * 16, g_w2pack + i * 16);
        cp_commit();
    }
    for (int u = tid; u < 780; u += 256) {
        int slot = u >> 1, hf = u & 1;
        int r = slot / 130, xi = slot - r * 130;
        int gy = y + r - 1, gx = xi - 1;
        uint4 v = make_uint4(0u,0u,0u,0u);
        if (((unsigned)gy < 128u) && ((unsigned)gx < 128u))
            v = *((const uint4*)(tb + (size_t)(gy * 128 + gx) * 8) + hf);
        *((uint4*)(sTre + slot * 8) + hf) = v;
    }
    __syncthreads();
    for (int u = tid; u < 1152; u += 256) {
        int x = u / 9, t = u - x * 9;
        int kh = t / 3, kw = t - kh * 3;
        const unsigned* src = sTre + (kh * 130 + x + kw) * 8;
        uint4 w0 = *(const uint4*)src;
        uint4 w1 = *(const uint4*)(src + 4);
        uint4 hi, lo;
        hi.x = prmt(w0.x, w0.y, 0x7632); hi.y = prmt(w0.z, w0.w, 0x7632);
        hi.z = prmt(w1.x, w1.y, 0x7632); hi.w = prmt(w1.z, w1.w, 0x7632);
        lo.x = prmt(w0.x, w0.y, 0x5410); lo.y = prmt(w0.z, w0.w, 0x5410);
        lo.z = prmt(w1.x, w1.y, 0x5410); lo.w = prmt(w1.z, w1.w, 0x5410);
        *(uint4*)(aHi + x * 176 + t * 16) = hi;
        *(uint4*)(aLo + x * 176 + t * 16) = lo;
    }
    for (int u = tid; u < 128; u += 256) {
        uint4 z = make_uint4(0u,0u,0u,0u);
        *(uint4*)(aHi + u * 176 + 144) = z;
        *(uint4*)(aLo + u * 176 + 144) = z;
    }
    cp_wait0();
    __syncthreads();

    unsigned aHiB = smaddr(aHi), aLoB = smaddr(aLo), bB = smaddr(sB);
    float acc[4][2][4];
    #pragma unroll
    for (int g = 0; g < 4; g++)
        #pragma unroll
        for (int nf = 0; nf < 2; nf++)
            #pragma unroll
            for (int r = 0; r < 4; r++) acc[g][nf][r] = 0.f;
    int x0 = 16 * w;
    #pragma unroll
    for (int kf = 0; kf < 5; kf++) {
        unsigned aH[4], aL[4];
        unsigned aoff = (unsigned)((x0 + (lane & 15)) * 176 + kf * 32 + ((lane >> 4) << 4));
        ldsm4(aH, aHiB + aoff);
        ldsm4(aL, aLoB + aoff);
        #pragma unroll
        for (int n0g = 0; n0g < 4; n0g++) {
            unsigned bH[4], bL[4];
            unsigned boff = (unsigned)((16 * n0g + (lane & 15)) * 176 + kf * 32 + ((lane >> 4) << 4));
            ldsm4(bH, bB + boff);
            ldsm4(bL, bB + 11264 + boff);
            float* dA = acc[n0g][0];
            float* dB = acc[n0g][1];
            mma_bf16(dA, aH, bH[0], bH[2]);
            mma_bf16(dB, aH, bH[1], bH[3]);
            mma_bf16(dA, aH, bL[0], bL[2]);
            mma_bf16(dB, aH, bL[1], bL[3]);
            mma_bf16(dA, aL, bH[0], bH[2]);
            mma_bf16(dB, aL, bH[1], bH[3]);
        }
    }
    __syncthreads();
    float* sD = (float*)aHi;
    {
        int r = lane >> 2, c = (lane & 3) * 2;
        int px = x0 + r;
        #pragma unroll
        for (int n0g = 0; n0g < 4; n0g++)
            #pragma unroll
            for (int nf = 0; nf < 2; nf++) {
                int o = n0g * 16 + nf * 8 + c;
                sD[px * 65 + o]           = acc[n0g][nf][0];
                sD[px * 65 + o + 1]       = acc[n0g][nf][1];
                sD[(px + 8) * 65 + o]     = acc[n0g][nf][2];
                sD[(px + 8) * 65 + o + 1] = acc[n0g][nf][3];
            }
    }
    __syncthreads();
    for (int i = tid; i < 8192; i += 256) {
        int o = i >> 7, x = i & 127;
        out[((size_t)(b * 64 + o) * 128 + y) * 128 + x] += sD[x * 65 + o];
    }
}

// ---------------------------------------------------------------------------
extern "C" void kernel_launch(void* const* d_in, const int* in_sizes, int n_in,
                              void* d_out, int out_size) {
    const float* x1    = (const float*)d_in[0];
    const float* x2    = (const float*)d_in[1];
    const float* d1_w1 = (const float*)d_in[2];
    const float* d1_w2 = (const float*)d_in[3];
    const float* d2_w1 = (const float*)d_in[4];
    const float* d2_w2 = (const float*)d_in[5];
    const float* align_w = (const float*)d_in[6];
    const float* up_w1 = (const float*)d_in[7];
    const float* up_w2 = (const float*)d_in[8];
    const float* re_w1 = (const float*)d_in[9];
    const float* re_w2 = (const float*)d_in[10];
    float* out = (float*)d_out;

    static int smem_set = 0;
    if (!smem_set) {
        cudaFuncSetAttribute(align_mma, cudaFuncAttributeMaxDynamicSharedMemorySize, ALN_SMEM);
        cudaFuncSetAttribute(upconv_mma, cudaFuncAttributeMaxDynamicSharedMemorySize, UPC_SMEM);
        cudaFuncSetAttribute(reconv1_mma, cudaFuncAttributeMaxDynamicSharedMemorySize, RC1_SMEM);
        cudaFuncSetAttribute(reconv2_mma, cudaFuncAttributeMaxDynamicSharedMemorySize, RC2_SMEM);
        smem_set = 1;
    }

    packpool_kernel<<<550, 256>>>(align_w, up_w1, up_w2, re_w1, re_w2,
                                  x1, x2, d1_w1, d1_w2);
    dsc_kernel<<<4096, 256>>>(x1, x2, 0);
    mlp_kernel<<<32, 128>>>(d2_w1, d2_w2);
    dsc_kernel<<<4096, 256>>>(x1, x2, 1);
    align_mma<<<512, 256, ALN_SMEM>>>();
    upconv_mma<<<512, 256, UPC_SMEM>>>(out);
    reconv1_mma<<<1024, 256, RC1_SMEM>>>();
    reconv2_mma<<<2048, 256, RC2_SMEM>>>(out);
}

// round 12
// speedup vs baseline: 1.2442x; 1.0401x over previous
#include <cuda_runtime.h>
#include <cuda_bf16.h>
#include <math.h>
#include <stdint.h>

// ---------------------------------------------------------------------------
// DSFDecoder: B=16, C=128, H=W=64, OUT=64, CR=16, RE=8
// All GEMM-shaped work on mma.sync bf16 (split hi/lo, 3 terms).
// R12: upconv + reconv1 at 512 threads (4 warps/SMSP) for latency hiding.
// ---------------------------------------------------------------------------

#define PLANE 4096
#define CH    128
#define BATCH 16

typedef unsigned long long ull;

__device__ __forceinline__ unsigned smaddr(const void* p) {
    return (unsigned)__cvta_generic_to_shared(p);
}
__device__ __forceinline__ void cp16(unsigned d, const void* s) {
    asm volatile("cp.async.cg.shared.global [%0], [%1], 16;" :: "r"(d), "l"(s) : "memory");
}
__device__ __forceinline__ void cp16z(unsigned d, const void* s, int valid) {
    asm volatile("cp.async.cg.shared.global [%0], [%1], 16, %2;"
                 :: "r"(d), "l"(s), "r"(valid ? 16 : 0) : "memory");
}
__device__ __forceinline__ void cp_commit() {
    asm volatile("cp.async.commit_group;" ::: "memory");
}
__device__ __forceinline__ void cp_wait0() {
    asm volatile("cp.async.wait_group 0;" ::: "memory");
}
__device__ __forceinline__ unsigned prmt(unsigned a, unsigned b, unsigned sel) {
    unsigned r; asm("prmt.b32 %0, %1, %2, %3;" : "=r"(r) : "r"(a), "r"(b), "r"(sel));
    return r;
}
__device__ __forceinline__ void ldsm4(unsigned* r, unsigned addr) {
    asm volatile("ldmatrix.sync.aligned.m8n8.x4.shared.b16 {%0,%1,%2,%3}, [%4];"
                 : "=r"(r[0]), "=r"(r[1]), "=r"(r[2]), "=r"(r[3]) : "r"(addr));
}
__device__ __forceinline__ void ldsm4t(unsigned* r, unsigned addr) {
    asm volatile("ldmatrix.sync.aligned.m8n8.x4.trans.shared.b16 {%0,%1,%2,%3}, [%4];"
                 : "=r"(r[0]), "=r"(r[1]), "=r"(r[2]), "=r"(r[3]) : "r"(addr));
}
__device__ __forceinline__ void mma_bf16(float* d, const unsigned* a, unsigned b0, unsigned b1) {
    asm volatile(
        "mma.sync.aligned.m16n8k16.row.col.f32.bf16.bf16.f32 "
        "{%0,%1,%2,%3}, {%4,%5,%6,%7}, {%8,%9}, {%0,%1,%2,%3};"
        : "+f"(d[0]), "+f"(d[1]), "+f"(d[2]), "+f"(d[3])
        : "r"(a[0]), "r"(a[1]), "r"(a[2]), "r"(a[3]), "r"(b0), "r"(b1));
}
__device__ __forceinline__ unsigned packbf(float v) {
    __nv_bfloat16 h = __float2bfloat16(v);
    __nv_bfloat16 l = __float2bfloat16(v - __bfloat162float(h));
    return (unsigned)__bfloat16_as_ushort(l) | ((unsigned)__bfloat16_as_ushort(h) << 16);
}
__device__ __forceinline__ unsigned bfhi(float v) {
    return (unsigned)__bfloat16_as_ushort(__float2bfloat16(v));
}
__device__ __forceinline__ unsigned bflo(float v) {
    __nv_bfloat16 h = __float2bfloat16(v);
    return (unsigned)__bfloat16_as_ushort(__float2bfloat16(v - __bfloat162float(h)));
}

__device__ float g_t[2][BATCH * CH * PLANE];
__device__ unsigned g_abH[2 * BATCH * CH * 2048];
__device__ unsigned g_abL[2 * BATCH * CH * 2048];
__device__ unsigned g_fuH[BATCH * PLANE * 64];
__device__ unsigned g_fuL[BATCH * PLANE * 64];
__device__ __align__(16) unsigned char g_wpack[18 * 8 * 8192];
__device__ __align__(16) unsigned char g_awpk[8 * 2 * 128 * 80];
__device__ unsigned g_upH[BATCH * 16384 * 32];
__device__ unsigned g_upL[BATCH * 16384 * 32];
__device__ unsigned g_treb[BATCH * 16384 * 8];
__device__ __align__(16) unsigned char g_w1pack[9 * 4096];
__device__ __align__(16) unsigned char g_w2pack[2 * 11264];
__device__ float g_pool[2][BATCH * CH];
__device__ float g_wk[2][BATCH * CH * 9];

// ---------------- pack + poolmlp merged ----------------
__global__ void __launch_bounds__(256, 2) packpool_kernel(
        const float* __restrict__ aw, const float* __restrict__ w1,
        const float* __restrict__ w2, const float* __restrict__ rw1,
        const float* __restrict__ rw2,
        const float* __restrict__ x1, const float* __restrict__ x2,
        const float* __restrict__ m1w1, const float* __restrict__ m1w2) {
    __shared__ float smem_u[2048];
    int tid = threadIdx.x;
    if (blockIdx.x >= 518) {
        int bi = blockIdx.x - 518;
        int slot = bi >> 4;
        int b = bi & 15;
        int wid = tid >> 5, lane = tid & 31;
        const float* xb = (slot ? x2 : x1) + (size_t)b * CH * PLANE;
        float* sp = smem_u;
        float* sh = smem_u + 128;
        for (int k = 0; k < 16; k++) {
            int c = wid * 16 + k;
            const float4* v = (const float4*)(xb + (size_t)c * PLANE);
            float s = 0.f;
            #pragma unroll 4
            for (int i = lane; i < 1024; i += 32) {
                float4 q = v[i];
                s += q.x + q.y + q.z + q.w;
            }
            for (int off = 16; off; off >>= 1) s += __shfl_xor_sync(0xffffffffu, s, off);
            if (lane == 0) sp[c] = s * (1.f / 4096.f);
        }
        __syncthreads();
        if (tid < 16) {
            float acc = 0.f;
            const float4* w1v = (const float4*)(m1w1 + tid * 128);
            #pragma unroll
            for (int j = 0; j < 32; j++) {
                float4 q = w1v[j];
                acc += sp[4*j] * q.x + sp[4*j+1] * q.y + sp[4*j+2] * q.z + sp[4*j+3] * q.w;
            }
            sh[tid] = 0.5f * acc * (1.f + erff(acc * 0.70710678118654752f));
        }
        __syncthreads();
        if (tid < 128) {
            int c = tid;
            const float4* w2v = (const float4*)(m1w2 + c * 144);
            float lg[9];
            float mx = -1e30f;
            #pragma unroll
            for (int k = 0; k < 9; k++) {
                float4 a0 = w2v[k*4], a1 = w2v[k*4+1], a2 = w2v[k*4+2], a3 = w2v[k*4+3];
                float acc = a0.x*sh[0] + a0.y*sh[1] + a0.z*sh[2] + a0.w*sh[3]
                          + a1.x*sh[4] + a1.y*sh[5] + a1.z*sh[6] + a1.w*sh[7]
                          + a2.x*sh[8] + a2.y*sh[9] + a2.z*sh[10] + a2.w*sh[11]
                          + a3.x*sh[12] + a3.y*sh[13] + a3.z*sh[14] + a3.w*sh[15];
                lg[k] = acc;
                mx = fmaxf(mx, acc);
            }
            float ss = 0.f;
            #pragma unroll
            for (int k = 0; k < 9; k++) { lg[k] = expf(lg[k] - mx); ss += lg[k]; }
            float inv = 1.f / ss;
            #pragma unroll
            for (int k = 0; k < 9; k++) g_wk[slot][(b * 128 + c) * 9 + k] = lg[k] * inv;
        }
        return;
    }
    if (blockIdx.x == 512) {
        for (int i = tid; i < 9216; i += 256) {
            int t = i >> 10, rem = i & 1023;
            int row = rem >> 6, c = rem & 63;
            float v = (row < 8) ? rw1[(row * 64 + c) * 9 + t] : 0.f;
            unsigned off = row * 128 + c * 2;
            unsigned sw = off ^ ((off >> 3) & 0x70);
            *(__nv_bfloat16*)(g_w1pack + t * 4096 + sw) = __ushort_as_bfloat16((unsigned short)bfhi(v));
            *(__nv_bfloat16*)(g_w1pack + t * 4096 + 2048 + sw) = __ushort_as_bfloat16((unsigned short)bflo(v));
        }
        return;
    }
    if (blockIdx.x == 513) {
        for (int i = tid; i < 64 * 88; i += 256) {
            int o = i / 88, k = i - o * 88;
            float v = 0.f;
            if (k < 72) { int t = k >> 3, r = k & 7; v = rw2[(o * 8 + r) * 9 + t]; }
            *(__nv_bfloat16*)(g_w2pack + o * 176 + k * 2) = __ushort_as_bfloat16((unsigned short)bfhi(v));
            *(__nv_bfloat16*)(g_w2pack + 11264 + o * 176 + k * 2) = __ushort_as_bfloat16((unsigned short)bflo(v));
        }
        return;
    }
    if (blockIdx.x >= 514) {
        int bi = blockIdx.x - 514;
        for (int e = bi * 16384 + tid; e < (bi + 1) * 16384; e += 256) {
            int cc = e & 31, rem = e >> 5;
            int o = rem & 127, rem2 = rem >> 7;
            int pl = rem2 & 1, chunk = rem2 >> 1;
            float v = aw[o * 256 + chunk * 32 + cc];
            unsigned bits = pl ? bflo(v) : bfhi(v);
            *(__nv_bfloat16*)(g_awpk + ((chunk * 2 + pl) * 128 + o) * 80 + cc * 2) =
                __ushort_as_bfloat16((unsigned short)bits);
        }
        return;
    }
    int sub = blockIdx.x >> 7, ci = blockIdx.x & 127;
    float* s1 = smem_u;
    for (int i = tid; i < 1152; i += 256) {
        int c = i / 9, t = i - c * 9;
        s1[i] = w1[((size_t)(c * 4 + sub) * 128 + ci) * 9 + t];
    }
    __syncthreads();
    if (tid < 64) {
        int o = tid;
        float acc[9] = {0.f,0.f,0.f,0.f,0.f,0.f,0.f,0.f,0.f};
        for (int c = 0; c < 128; c++) {
            float wv = w2[o * 128 + c];
            #pragma unroll
            for (int t = 0; t < 9; t++) acc[t] += wv * s1[c * 9 + t];
        }
        int g = ci >> 6, cl = ci & 63;
        unsigned off = ((o >> 3) << 10) + ((o & 7) << 7) + (cl << 1);
        unsigned sw = off ^ ((off >> 3) & 0x70);
        #pragma unroll
        for (int t = 0; t < 9; t++) {
            float v = acc[t];
            unsigned char* base = g_wpack + ((size_t)((t * 2 + g) * 8 + sub * 2)) * 8192;
            *(__nv_bfloat16*)(base + sw) = __ushort_as_bfloat16((unsigned short)bfhi(v));
            *(__nv_bfloat16*)(base + 8192 + sw) = __ushort_as_bfloat16((unsigned short)bflo(v));
        }
    }
}

// ---------------- mlp2 ----------------
__global__ void mlp_kernel(const float* __restrict__ w1, const float* __restrict__ w2) {
    int slot = blockIdx.x >> 4;
    int b = blockIdx.x & 15;
    int tid = threadIdx.x;
    __shared__ float sp[128], sh[16];
    sp[tid] = g_pool[slot][b * 128 + tid];
    __syncthreads();
    if (tid < 16) {
        float acc = 0.f;
        const float4* w1v = (const float4*)(w1 + tid * 128);
        #pragma unroll
        for (int j = 0; j < 32; j++) {
            float4 q = w1v[j];
            acc += sp[4*j] * q.x + sp[4*j+1] * q.y + sp[4*j+2] * q.z + sp[4*j+3] * q.w;
        }
        sh[tid] = 0.5f * acc * (1.f + erff(acc * 0.70710678118654752f));
    }
    __syncthreads();
    int c = tid;
    const float4* w2v = (const float4*)(w2 + c * 144);
    float lg[9];
    float mx = -1e30f;
    #pragma unroll
    for (int k = 0; k < 9; k++) {
        float4 a0 = w2v[k*4], a1 = w2v[k*4+1], a2 = w2v[k*4+2], a3 = w2v[k*4+3];
        float acc = a0.x*sh[0] + a0.y*sh[1] + a0.z*sh[2] + a0.w*sh[3]
                  + a1.x*sh[4] + a1.y*sh[5] + a1.z*sh[6] + a1.w*sh[7]
                  + a2.x*sh[8] + a2.y*sh[9] + a2.z*sh[10] + a2.w*sh[11]
                  + a3.x*sh[12] + a3.y*sh[13] + a3.z*sh[14] + a3.w*sh[15];
        lg[k] = acc;
        mx = fmaxf(mx, acc);
    }
    float ss = 0.f;
    #pragma unroll
    for (int k = 0; k < 9; k++) { lg[k] = expf(lg[k] - mx); ss += lg[k]; }
    float inv = 1.f / ss;
    #pragma unroll
    for (int k = 0; k < 9; k++) g_wk[slot][(b * 128 + c) * 9 + k] = lg[k] * inv;
}

// ---------------- dsc ----------------
__global__ void __launch_bounds__(256, 4) dsc_kernel(const float* __restrict__ x1,
                                                     const float* __restrict__ x2,
                                                     int phase) {
    int slot = blockIdx.x >> 11;
    int bc = blockIdx.x & 2047;
    const float* xext = slot ? x2 : x1;
    const float* src = phase ? &g_t[slot][(size_t)bc * PLANE]
                             : xext + (size_t)bc * PLANE;
    float wk[9];
    #pragma unroll
    for (int k = 0; k < 9; k++) wk[k] = g_wk[slot][bc * 9 + k];
    __shared__ float sp[66][72];
    int tid = threadIdx.x;
    if (tid < 72) { sp[0][tid] = 0.f; sp[65][tid] = 0.f; }
    if (tid < 64) { sp[tid + 1][3] = 0.f; sp[tid + 1][68] = 0.f; }
    {
        int p = tid * 16;
        int h = p >> 6, w = p & 63;
        const float4* s4 = (const float4*)(src + p);
        float4* d = (float4*)&sp[h + 1][w + 4];
        d[0] = s4[0]; d[1] = s4[1]; d[2] = s4[2]; d[3] = s4[3];
    }
    __syncthreads();
    int h = tid >> 2, xb = (tid & 3) * 16;
    float r0[24], r1[24], r2[24];
    #pragma unroll
    for (int k = 0; k < 6; k++) {
        *(float4*)&r0[k * 4] = *(const float4*)&sp[h + 0][xb + k * 4];
        *(float4*)&r1[k * 4] = *(const float4*)&sp[h + 1][xb + k * 4];
        *(float4*)&r2[k * 4] = *(const float4*)&sp[h + 2][xb + k * 4];
    }
    float acc[16];
    #pragma unroll
    for (int j = 0; j < 16; j++) {
        float a = r1[j + 4];
        a += wk[0] * r0[j + 3]; a += wk[1] * r0[j + 4]; a += wk[2] * r0[j + 5];
        a += wk[3] * r1[j + 3]; a += wk[4] * r1[j + 4]; a += wk[5] * r1[j + 5];
        a += wk[6] * r2[j + 3]; a += wk[7] * r2[j + 4]; a += wk[8] * r2[j + 5];
        acc[j] = a;
    }
    if (phase) {
        unsigned hbuf[8], lbuf[8];
        #pragma unroll
        for (int j = 0; j < 8; j++) {
            hbuf[j] = bfhi(acc[2 * j]) | (bfhi(acc[2 * j + 1]) << 16);
            lbuf[j] = bflo(acc[2 * j]) | (bflo(acc[2 * j + 1]) << 16);
        }
        size_t rowoff = ((size_t)slot * 2048 + bc) * 2048 + tid * 8;
        *(uint4*)(g_abH + rowoff) = *(uint4*)hbuf;
        *(uint4*)(g_abH + rowoff + 4) = *(uint4*)(hbuf + 4);
        *(uint4*)(g_abL + rowoff) = *(uint4*)lbuf;
        *(uint4*)(g_abL + rowoff + 4) = *(uint4*)(lbuf + 4);
    } else {
        float* dst = &g_t[slot][(size_t)bc * PLANE];
        int p = tid * 16;
        float psum = 0.f;
        #pragma unroll
        for (int j = 0; j < 16; j++) { acc[j] = fmaxf(acc[j], 0.f); psum += acc[j]; }
        #pragma unroll
        for (int k = 0; k < 4; k++)
            *(float4*)&dst[p + k * 4] = make_float4(acc[k*4], acc[k*4+1], acc[k*4+2], acc[k*4+3]);
        for (int off = 16; off; off >>= 1) psum += __shfl_xor_sync(0xffffffffu, psum, off);
        __shared__ float red[8];
        if ((tid & 31) == 0) red[tid >> 5] = psum;
        __syncthreads();
        if (tid < 32) {
            float r = (tid < 8) ? red[tid] : 0.f;
            for (int off = 4; off; off >>= 1) r += __shfl_xor_sync(0xffffffffu, r, off);
            if (tid == 0) g_pool[slot][bc] = r * (1.f / 4096.f);
        }
    }
}

// ---------------- align via mma.sync ----------------
#define ALN_BUF 36864
#define ALN_SMEM (2 * ALN_BUF + 1024)
__global__ void __launch_bounds__(256, 2) align_mma() {
    extern __shared__ char dynraw[];
    char* base = (char*)((((uintptr_t)dynraw) + 1023) & ~(uintptr_t)1023);
    int tid = threadIdx.x;
    int w = tid >> 5, lane = tid & 31;
    int b = blockIdx.x >> 5;
    int pix0 = (blockIdx.x & 31) * 128;

    float acc[4][4][4];
    #pragma unroll
    for (int mt = 0; mt < 4; mt++)
        #pragma unroll
        for (int nt = 0; nt < 4; nt++)
            #pragma unroll
            for (int r = 0; r < 4; r++) acc[mt][nt][r] = 0.f;

    auto fill = [&](int chunk, int buf) {
        char* bb = base + buf * ALN_BUF;
        for (int i = tid; i < 1024; i += 256) {
            int pl = i >> 9, r = i & 511;
            int cc = r >> 4, j = r & 15;
            int gc = chunk * 32 + cc;
            size_t row = (size_t)((gc >> 7) * 2048 + b * 128 + (gc & 127));
            const unsigned* src = (pl ? g_abL : g_abH) + row * 2048 + (pix0 >> 1) + j * 4;
            unsigned off = (unsigned)(cc * 256 + j * 16);
            unsigned sw = off ^ ((off >> 4) & 0xF0);
            cp16(smaddr(bb + pl * 8192) + sw, src);
        }
        for (int i = tid; i < 1280; i += 256) {
            int pl = i >= 640, r = pl ? i - 640 : i;
            int o = r / 5, j = r - o * 5;
            const unsigned char* src = g_awpk + (size_t)chunk * 20480 + pl * 10240 + o * 80 + j * 16;
            cp16(smaddr(bb + 16384 + pl * 10240) + o * 80 + j * 16, src);
        }
    };

    fill(0, 0);
    cp_commit(); cp_wait0();
    __syncthreads();

    int m0 = (w & 1) * 64, n0 = (w >> 1) * 32;
    for (int chunk = 0; chunk < 8; chunk++) {
        int buf = chunk & 1;
        if (chunk < 7) { fill(chunk + 1, buf ^ 1); cp_commit(); }
        char* bb = base + buf * ALN_BUF;
        unsigned aHiB = smaddr(bb), aLoB = smaddr(bb + 8192);
        unsigned bHiB = smaddr(bb + 16384), bLoB = smaddr(bb + 26624);
        #pragma unroll
        for (int kt = 0; kt < 2; kt++) {
            int c0 = kt * 16;
            unsigned bH[2][4], bL[2][4];
            #pragma unroll
            for (int nh = 0; nh < 2; nh++) {
                unsigned boff = (unsigned)((n0 + nh * 16 + (lane & 15)) * 80 + c0 * 2 + ((lane >> 4) << 4));
                ldsm4(bH[nh], bHiB + boff);
                ldsm4(bL[nh], bLoB + boff);
            }
            #pragma unroll
            for (int mt = 0; mt < 4; mt++) {
                unsigned aoff = (unsigned)(((lane & 7) + ((lane >> 4) << 3) + c0) * 256
                                           + (m0 + mt * 16 + (((lane >> 3) & 1) << 3)) * 2);
                unsigned asw = aoff ^ ((aoff >> 4) & 0xF0);
                unsigned aH[4], aL[4];
                ldsm4t(aH, aHiB + asw);
                ldsm4t(aL, aLoB + asw);
                #pragma unroll
                for (int nh = 0; nh < 2; nh++) {
                    float* dA = acc[mt][2 * nh];
                    float* dB = acc[mt][2 * nh + 1];
                    mma_bf16(dA, aH, bH[nh][0], bH[nh][2]);
                    mma_bf16(dB, aH, bH[nh][1], bH[nh][3]);
                    mma_bf16(dA, aH, bL[nh][0], bL[nh][2]);
                    mma_bf16(dB, aH, bL[nh][1], bL[nh][3]);
                    mma_bf16(dA, aL, bH[nh][0], bH[nh][2]);
                    mma_bf16(dB, aL, bH[nh][1], bH[nh][3]);
                }
            }
        }
        if (chunk < 7) cp_wait0();
        __syncthreads();
    }

    unsigned* fH = g_fuH + (size_t)b * PLANE * 64;
    unsigned* fL = g_fuL + (size_t)b * PLANE * 64;
    #pragma unroll
    for (int mt = 0; mt < 4; mt++) {
        #pragma unroll
        for (int nt = 0; nt < 4; nt++) {
            float* d = acc[mt][nt];
            int row = pix0 + m0 + mt * 16 + (lane >> 2);
            int op = ((n0 + nt * 8) >> 1) + (lane & 3);
            fH[(size_t)row * 64 + op] = bfhi(d[0]) | (bfhi(d[1]) << 16);
            fL[(size_t)row * 64 + op] = bflo(d[0]) | (bflo(d[1]) << 16);
            fH[(size_t)(row + 8) * 64 + op] = bfhi(d[2]) | (bfhi(d[3]) << 16);
            fL[(size_t)(row + 8) * 64 + op] = bflo(d[2]) | (bflo(d[3]) << 16);
        }
    }
}

// ---------------- upconv via mma.sync, 512 threads ----------------
#define UPC_BUF 98304
#define UPC_SMEM (2 * UPC_BUF + 1024)
__global__ void __launch_bounds__(512, 1) upconv_mma(float* __restrict__ out) {
    extern __shared__ char dynraw[];
    char* base = (char*)((((uintptr_t)dynraw) + 1023) & ~(uintptr_t)1023);
    int tid = threadIdx.x;
    int w = tid >> 5, lane = tid & 31;
    int mi = w & 7, nh = w >> 3;          // 16 warps: m-tile x N-half
    int b = blockIdx.x >> 5;
    int y0 = (blockIdx.x & 31) * 2;

    const unsigned* fH = g_fuH + (size_t)b * PLANE * 64;
    const unsigned* fL = g_fuL + (size_t)b * PLANE * 64;
    int m = tid >> 2;                      // A fill: 128 m x 2 plane x 2 jh
    int plane = (tid >> 1) & 1;
    int jh = tid & 1;
    int mrow = m >> 6, mx = m & 63;

    float acc[4][4][4];                    // [sub][nf(4) within half][4]
    #pragma unroll
    for (int s = 0; s < 4; s++)
        #pragma unroll
        for (int nf = 0; nf < 4; nf++)
            #pragma unroll
            for (int r = 0; r < 4; r++) acc[s][nf][r] = 0.f;

    auto fill = [&](int q, int buf) {
        char* bb = base + buf * UPC_BUF;
        int tap = q >> 1, g = q & 1;
        int kh = tap / 3, kw = tap - kh * 3;
        {
            const unsigned char* bsrc = g_wpack + (size_t)q * 65536;
            unsigned bdst = smaddr(bb + 32768);
            #pragma unroll 4
            for (int i = tid; i < 4096; i += 512)
                cp16(bdst + i * 16, bsrc + i * 16);
        }
        {
            int yy = y0 + mrow + kh - 1;
            int xx = mx + kw - 1;
            int valid = (((unsigned)yy < 64u) && ((unsigned)xx < 64u)) ? 1 : 0;
            const unsigned* src = (plane ? fL : fH) + ((size_t)(yy * 64 + xx) * 64 + g * 32 + jh * 16);
            unsigned dstb = smaddr(bb + plane * 16384);
            unsigned db = (unsigned)(m * 128 + jh * 64);
            #pragma unroll
            for (int j = 0; j < 4; j++) {
                unsigned off = db + j * 16;
                unsigned sw = off ^ ((off >> 3) & 0x70);
                cp16z(dstb + sw, src + j * 4, valid);
            }
        }
    };

    fill(0, 0);
    cp_commit(); cp_wait0();
    __syncthreads();

    for (int q = 0; q < 18; q++) {
        int buf = q & 1;
        if (q < 17) { fill(q + 1, buf ^ 1); cp_commit(); }
        char* bb = base + buf * UPC_BUF;
        unsigned aHiB = smaddr(bb), aLoB = smaddr(bb + 16384);
        unsigned bB = smaddr(bb + 32768);
        #pragma unroll
        for (int kf = 0; kf < 4; kf++) {
            unsigned aH[4], aL[4];
            {
                unsigned arow = (unsigned)(16 * mi + (lane & 15));
                unsigned aoff = arow * 128 + kf * 32 + ((lane >> 4) << 4);
                unsigned asw = aoff ^ ((aoff >> 3) & 0x70);
                ldsm4(aH, aHiB + asw);
                ldsm4(aL, aLoB + asw);
            }
            #pragma unroll
            for (int s = 0; s < 4; s++) {
                #pragma unroll
                for (int ng = 0; ng < 2; ng++) {
                    unsigned brow = (unsigned)(16 * (nh * 2 + ng) + (lane & 15));
                    unsigned boff = brow * 128 + kf * 32 + ((lane >> 4) << 4);
                    unsigned bsw = boff ^ ((boff >> 3) & 0x70);
                    unsigned bH[4], bL[4];
                    ldsm4(bH, bB + s * 16384 + bsw);
                    ldsm4(bL, bB + s * 16384 + 8192 + bsw);
                    float* dA = acc[s][2 * ng];
                    float* dB = acc[s][2 * ng + 1];
                    mma_bf16(dA, aH, bH[0], bH[2]);
                    mma_bf16(dB, aH, bH[1], bH[3]);
                    mma_bf16(dA, aH, bL[0], bL[2]);
                    mma_bf16(dB, aH, bL[1], bL[3]);
                    mma_bf16(dA, aL, bH[0], bH[2]);
                    mma_bf16(dB, aL, bH[1], bH[3]);
                }
            }
        }
        if (q < 17) cp_wait0();
        __syncthreads();
    }

    float2* s2 = (float2*)base;   // [128][65] float2
    unsigned* uH = g_upH + (size_t)b * 16384 * 32;
    unsigned* uL = g_upL + (size_t)b * 16384 * 32;
    int m0 = 16 * mi + (lane >> 2);
    int ocol = (lane & 3) * 2;
    #pragma unroll
    for (int sp = 0; sp < 2; sp++) {
        __syncthreads();
        #pragma unroll
        for (int nf = 0; nf < 4; nf++) {
            int o = nh * 32 + nf * 8 + ocol;
            s2[m0 * 65 + o]         = make_float2(acc[2*sp][nf][0], acc[2*sp+1][nf][0]);
            s2[m0 * 65 + o + 1]     = make_float2(acc[2*sp][nf][1], acc[2*sp+1][nf][1]);
            s2[(m0 + 8) * 65 + o]   = make_float2(acc[2*sp][nf][2], acc[2*sp+1][nf][2]);
            s2[(m0 + 8) * 65 + o+1] = make_float2(acc[2*sp][nf][3], acc[2*sp+1][nf][3]);
        }
        __syncthreads();
        for (int i = tid; i < 8192; i += 512) {
            int mr = i >> 12, o = (i >> 6) & 63, xx = i & 63;
            int y = 2 * (y0 + mr) + sp;
            *(float2*)(out + (((size_t)(b * 64 + o) * 128 + y) * 128 + 2 * xx)) =
                s2[(mr * 64 + xx) * 65 + o];
        }
        for (int i = tid; i < 8192; i += 512) {
            int mr = i >> 12, x2 = (i >> 5) & 127, op = i & 31;
            int y = 2 * (y0 + mr) + sp;
            float2 va = s2[(mr * 64 + (x2 >> 1)) * 65 + 2 * op];
            float2 vb = s2[(mr * 64 + (x2 >> 1)) * 65 + 2 * op + 1];
            float v0 = (x2 & 1) ? va.y : va.x;
            float v1 = (x2 & 1) ? vb.y : vb.x;
            uH[(size_t)(y * 128 + x2) * 32 + op] = bfhi(v0) | (bfhi(v1) << 16);
            uL[(size_t)(y * 128 + x2) * 32 + op] = bflo(v0) | (bflo(v1) << 16);
        }
    }
}

// ---------------- reconv1 via mma, 512 threads, 2 rows/block ----------------
#define RC1_SMEM (66560 * 2 + 36864 + 1024)
__global__ void __launch_bounds__(512, 1) reconv1_mma() {
    extern __shared__ char dynraw[];
    char* base = (char*)((((uintptr_t)dynraw) + 1023) & ~(uintptr_t)1023);
    char* aHi = base;
    char* aLo = base + 66560;
    char* sB  = base + 133120;
    int tid = threadIdx.x;
    int w = tid >> 5, lane = tid & 31;
    int xt = w & 7, ys = w >> 3;          // 16 warps: x-tile x output-row
    int b = blockIdx.x >> 6;
    int y0 = (blockIdx.x & 63) * 2;
    const unsigned* uH = g_upH + (size_t)b * 16384 * 32;
    const unsigned* uL = g_upL + (size_t)b * 16384 * 32;

    {
        unsigned bdst = smaddr(sB);
        for (int i = tid; i < 2304; i += 512)
            cp16(bdst + i * 16, g_w1pack + i * 16);
    }
    unsigned aHiB = smaddr(aHi), aLoB = smaddr(aLo);
    for (int u = tid; u < 4160; u += 512) {
        int slot = u >> 3, j = u & 7;
        int r = slot / 130, xi = slot - r * 130;
        int gy = y0 + r - 1, gx = xi - 1;
        int valid = (((unsigned)gy < 128u) && ((unsigned)gx < 128u)) ? 1 : 0;
        size_t sidx = (size_t)(gy * 128 + gx) * 32 + j * 4;
        unsigned off = (unsigned)(slot * 128 + j * 16);
        unsigned sw = off ^ ((off >> 3) & 0x70);
        cp16z(aHiB + sw, uH + sidx, valid);
        cp16z(aLoB + sw, uL + sidx, valid);
    }
    cp_commit(); cp_wait0();
    __syncthreads();

    unsigned bB = smaddr(sB);
    float d[4] = {0.f, 0.f, 0.f, 0.f};
    int x0 = 16 * xt;
    for (int t = 0; t < 9; t++) {
        int kh = t / 3, kw = t - kh * 3;
        #pragma unroll
        for (int kf = 0; kf < 4; kf++) {
            unsigned bH[4], bL[4];
            unsigned boff = (unsigned)((lane & 15) * 128 + kf * 32 + ((lane >> 4) << 4));
            unsigned bsw = boff ^ ((boff >> 3) & 0x70);
            ldsm4(bH, bB + t * 4096 + bsw);
            ldsm4(bL, bB + t * 4096 + 2048 + bsw);
            int slot = (ys + kh) * 130 + x0 + (lane & 15) + kw;
            unsigned aoff = (unsigned)(slot * 128 + kf * 32 + ((lane >> 4) << 4));
            unsigned asw = aoff ^ ((aoff >> 3) & 0x70);
            unsigned aH[4], aL[4];
            ldsm4(aH, aHiB + asw);
            ldsm4(aL, aLoB + asw);
            mma_bf16(d, aH, bH[0], bH[2]);
            mma_bf16(d, aH, bL[0], bL[2]);
            mma_bf16(d, aL, bH[0], bH[2]);
        }
    }
    int r = lane >> 2, c = (lane & 3) * 2;
    int px = x0 + r;
    unsigned* tb = g_treb + ((size_t)b * 16384 + (y0 + ys) * 128) * 8;
    tb[px * 8 + c]           = packbf(fmaxf(d[0], 0.f));
    tb[px * 8 + c + 1]       = packbf(fmaxf(d[1], 0.f));
    tb[(px + 8) * 8 + c]     = packbf(fmaxf(d[2], 0.f));
    tb[(px + 8) * 8 + c + 1] = packbf(fmaxf(d[3], 0.f));
}

// ---------------- reconv2 via mma ----------------
#define RC2_SMEM (12480 + 22528 + 22528 + 22528 + 1024)
__global__ void __launch_bounds__(256, 2) reconv2_mma(float* __restrict__ out) {
    extern __shared__ char dynraw2[];
    char* base = (char*)((((uintptr_t)dynraw2) + 1023) & ~(uintptr_t)1023);
    unsigned* sTre = (unsigned*)base;
    char* aHi = base + 12480;
    char* aLo = base + 12480 + 22528;
    char* sB  = base + 12480 + 45056;
    int tid = threadIdx.x;
    int w = tid >> 5, lane = tid & 31;
    int b = blockIdx.x >> 7;
    int y = blockIdx.x & 127;
    const unsigned* tb = g_treb + (size_t)b * 16384 * 8;

    {
        unsigned bdst = smaddr(sB);
        for (int i = tid; i < 1408; i += 256)
            cp16(bdst + i * 16, g_w2pack + i * 16);
        cp_commit();
    }
    for (int u = tid; u < 780; u += 256) {
        int slot = u >> 1, hf = u & 1;
        int r = slot / 130, xi = slot - r * 130;
        int gy = y + r - 1, gx = xi - 1;
        uint4 v = make_uint4(0u,0u,0u,0u);
        if (((unsigned)gy < 128u) && ((unsigned)gx < 128u))
            v = *((const uint4*)(tb + (size_t)(gy * 128 + gx) * 8) + hf);
        *((uint4*)(sTre + slot * 8) + hf) = v;
    }
    __syncthreads();
    for (int u = tid; u < 1152; u += 256) {
        int x = u / 9, t = u - x * 9;
        int kh = t / 3, kw = t - kh * 3;
        const unsigned* src = sTre + (kh * 130 + x + kw) * 8;
        uint4 w0 = *(const uint4*)src;
        uint4 w1 = *(const uint4*)(src + 4);
        uint4 hi, lo;
        hi.x = prmt(w0.x, w0.y, 0x7632); hi.y = prmt(w0.z, w0.w, 0x7632);
        hi.z = prmt(w1.x, w1.y, 0x7632); hi.w = prmt(w1.z, w1.w, 0x7632);
        lo.x = prmt(w0.x, w0.y, 0x5410); lo.y = prmt(w0.z, w0.w, 0x5410);
        lo.z = prmt(w1.x, w1.y, 0x5410); lo.w = prmt(w1.z, w1.w, 0x5410);
        *(uint4*)(aHi + x * 176 + t * 16) = hi;
        *(uint4*)(aLo + x * 176 + t * 16) = lo;
    }
    for (int u = tid; u < 128; u += 256) {
        uint4 z = make_uint4(0u,0u,0u,0u);
        *(uint4*)(aHi + u * 176 + 144) = z;
        *(uint4*)(aLo + u * 176 + 144) = z;
    }
    cp_wait0();
    __syncthreads();

    unsigned aHiB = smaddr(aHi), aLoB = smaddr(aLo), bB = smaddr(sB);
    float acc[4][2][4];
    #pragma unroll
    for (int g = 0; g < 4; g++)
        #pragma unroll
        for (int nf = 0; nf < 2; nf++)
            #pragma unroll
            for (int r = 0; r < 4; r++) acc[g][nf][r] = 0.f;
    int x0 = 16 * w;
    #pragma unroll
    for (int kf = 0; kf < 5; kf++) {
        unsigned aH[4], aL[4];
        unsigned aoff = (unsigned)((x0 + (lane & 15)) * 176 + kf * 32 + ((lane >> 4) << 4));
        ldsm4(aH, aHiB + aoff);
        ldsm4(aL, aLoB + aoff);
        #pragma unroll
        for (int n0g = 0; n0g < 4; n0g++) {
            unsigned bH[4], bL[4];
            unsigned boff = (unsigned)((16 * n0g + (lane & 15)) * 176 + kf * 32 + ((lane >> 4) << 4));
            ldsm4(bH, bB + boff);
            ldsm4(bL, bB + 11264 + boff);
            float* dA = acc[n0g][0];
            float* dB = acc[n0g][1];
            mma_bf16(dA, aH, bH[0], bH[2]);
            mma_bf16(dB, aH, bH[1], bH[3]);
            mma_bf16(dA, aH, bL[0], bL[2]);
            mma_bf16(dB, aH, bL[1], bL[3]);
            mma_bf16(dA, aL, bH[0], bH[2]);
            mma_bf16(dB, aL, bH[1], bH[3]);
        }
    }
    __syncthreads();
    float* sD = (float*)aHi;
    {
        int r = lane >> 2, c = (lane & 3) * 2;
        int px = x0 + r;
        #pragma unroll
        for (int n0g = 0; n0g < 4; n0g++)
            #pragma unroll
            for (int nf = 0; nf < 2; nf++) {
                int o = n0g * 16 + nf * 8 + c;
                sD[px * 65 + o]           = acc[n0g][nf][0];
                sD[px * 65 + o + 1]       = acc[n0g][nf][1];
                sD[(px + 8) * 65 + o]     = acc[n0g][nf][2];
                sD[(px + 8) * 65 + o + 1] = acc[n0g][nf][3];
            }
    }
    __syncthreads();
    for (int i = tid; i < 8192; i += 256) {
        int o = i >> 7, x = i & 127;
        out[((size_t)(b * 64 + o) * 128 + y) * 128 + x] += sD[x * 65 + o];
    }
}

// ---------------------------------------------------------------------------
extern "C" void kernel_launch(void* const* d_in, const int* in_sizes, int n_in,
                              void* d_out, int out_size) {
    const float* x1    = (const float*)d_in[0];
    const float* x2    = (const float*)d_in[1];
    const float* d1_w1 = (const float*)d_in[2];
    const float* d1_w2 = (const float*)d_in[3];
    const float* d2_w1 = (const float*)d_in[4];
    const float* d2_w2 = (const float*)d_in[5];
    const float* align_w = (const float*)d_in[6];
    const float* up_w1 = (const float*)d_in[7];
    const float* up_w2 = (const float*)d_in[8];
    const float* re_w1 = (const float*)d_in[9];
    const float* re_w2 = (const float*)d_in[10];
    float* out = (float*)d_out;

    static int smem_set = 0;
    if (!smem_set) {
        cudaFuncSetAttribute(align_mma, cudaFuncAttributeMaxDynamicSharedMemorySize, ALN_SMEM);
        cudaFuncSetAttribute(upconv_mma, cudaFuncAttributeMaxDynamicSharedMemorySize, UPC_SMEM);
        cudaFuncSetAttribute(reconv1_mma, cudaFuncAttributeMaxDynamicSharedMemorySize, RC1_SMEM);
        cudaFuncSetAttribute(reconv2_mma, cudaFuncAttributeMaxDynamicSharedMemorySize, RC2_SMEM);
        smem_set = 1;
    }

    packpool_kernel<<<550, 256>>>(align_w, up_w1, up_w2, re_w1, re_w2,
                                  x1, x2, d1_w1, d1_w2);
    dsc_kernel<<<4096, 256>>>(x1, x2, 0);
    mlp_kernel<<<32, 128>>>(d2_w1, d2_w2);
    dsc_kernel<<<4096, 256>>>(x1, x2, 1);
    align_mma<<<512, 256, ALN_SMEM>>>();
    upconv_mma<<<512, 512, UPC_SMEM>>>(out);
    reconv1_mma<<<1024, 512, RC1_SMEM>>>();
    reconv2_mma<<<2048, 256, RC2_SMEM>>>(out);
}

// round 13
// speedup vs baseline: 1.3244x; 1.0645x over previous
#include <cuda_runtime.h>
#include <cuda_bf16.h>
#include <math.h>
#include <stdint.h>

// ---------------------------------------------------------------------------
// DSFDecoder: B=16, C=128, H=W=64, OUT=64, CR=16, RE=8
// All GEMM-shaped work on mma.sync bf16 (split hi/lo, 3 terms).
// R13: upconv writes only packed hi/lo planes (no fp32 up tensor);
//      reconv2 reconstructs the residual from the planes.
// ---------------------------------------------------------------------------

#define PLANE 4096
#define CH    128
#define BATCH 16

typedef unsigned long long ull;

__device__ __forceinline__ unsigned smaddr(const void* p) {
    return (unsigned)__cvta_generic_to_shared(p);
}
__device__ __forceinline__ void cp16(unsigned d, const void* s) {
    asm volatile("cp.async.cg.shared.global [%0], [%1], 16;" :: "r"(d), "l"(s) : "memory");
}
__device__ __forceinline__ void cp16z(unsigned d, const void* s, int valid) {
    asm volatile("cp.async.cg.shared.global [%0], [%1], 16, %2;"
                 :: "r"(d), "l"(s), "r"(valid ? 16 : 0) : "memory");
}
__device__ __forceinline__ void cp_commit() {
    asm volatile("cp.async.commit_group;" ::: "memory");
}
__device__ __forceinline__ void cp_wait0() {
    asm volatile("cp.async.wait_group 0;" ::: "memory");
}
__device__ __forceinline__ unsigned prmt(unsigned a, unsigned b, unsigned sel) {
    unsigned r; asm("prmt.b32 %0, %1, %2, %3;" : "=r"(r) : "r"(a), "r"(b), "r"(sel));
    return r;
}
__device__ __forceinline__ void ldsm4(unsigned* r, unsigned addr) {
    asm volatile("ldmatrix.sync.aligned.m8n8.x4.shared.b16 {%0,%1,%2,%3}, [%4];"
                 : "=r"(r[0]), "=r"(r[1]), "=r"(r[2]), "=r"(r[3]) : "r"(addr));
}
__device__ __forceinline__ void ldsm4t(unsigned* r, unsigned addr) {
    asm volatile("ldmatrix.sync.aligned.m8n8.x4.trans.shared.b16 {%0,%1,%2,%3}, [%4];"
                 : "=r"(r[0]), "=r"(r[1]), "=r"(r[2]), "=r"(r[3]) : "r"(addr));
}
__device__ __forceinline__ void mma_bf16(float* d, const unsigned* a, unsigned b0, unsigned b1) {
    asm volatile(
        "mma.sync.aligned.m16n8k16.row.col.f32.bf16.bf16.f32 "
        "{%0,%1,%2,%3}, {%4,%5,%6,%7}, {%8,%9}, {%0,%1,%2,%3};"
        : "+f"(d[0]), "+f"(d[1]), "+f"(d[2]), "+f"(d[3])
        : "r"(a[0]), "r"(a[1]), "r"(a[2]), "r"(a[3]), "r"(b0), "r"(b1));
}
__device__ __forceinline__ unsigned packbf(float v) {
    __nv_bfloat16 h = __float2bfloat16(v);
    __nv_bfloat16 l = __float2bfloat16(v - __bfloat162float(h));
    return (unsigned)__bfloat16_as_ushort(l) | ((unsigned)__bfloat16_as_ushort(h) << 16);
}
__device__ __forceinline__ unsigned bfhi(float v) {
    return (unsigned)__bfloat16_as_ushort(__float2bfloat16(v));
}
__device__ __forceinline__ unsigned bflo(float v) {
    __nv_bfloat16 h = __float2bfloat16(v);
    return (unsigned)__bfloat16_as_ushort(__float2bfloat16(v - __bfloat162float(h)));
}

__device__ float g_t[2][BATCH * CH * PLANE];
__device__ unsigned g_abH[2 * BATCH * CH * 2048];
__device__ unsigned g_abL[2 * BATCH * CH * 2048];
__device__ unsigned g_fuH[BATCH * PLANE * 64];
__device__ unsigned g_fuL[BATCH * PLANE * 64];
__device__ __align__(16) unsigned char g_wpack[18 * 8 * 8192];
__device__ __align__(16) unsigned char g_awpk[8 * 2 * 128 * 80];
__device__ unsigned g_upH[BATCH * 16384 * 32];
__device__ unsigned g_upL[BATCH * 16384 * 32];
__device__ unsigned g_treb[BATCH * 16384 * 8];
__device__ __align__(16) unsigned char g_w1pack[9 * 4096];
__device__ __align__(16) unsigned char g_w2pack[2 * 11264];
__device__ float g_pool[2][BATCH * CH];
__device__ float g_wk[2][BATCH * CH * 9];

// ---------------- pack + poolmlp merged ----------------
__global__ void __launch_bounds__(256, 2) packpool_kernel(
        const float* __restrict__ aw, const float* __restrict__ w1,
        const float* __restrict__ w2, const float* __restrict__ rw1,
        const float* __restrict__ rw2,
        const float* __restrict__ x1, const float* __restrict__ x2,
        const float* __restrict__ m1w1, const float* __restrict__ m1w2) {
    __shared__ float smem_u[2048];
    int tid = threadIdx.x;
    if (blockIdx.x >= 518) {
        int bi = blockIdx.x - 518;
        int slot = bi >> 4;
        int b = bi & 15;
        int wid = tid >> 5, lane = tid & 31;
        const float* xb = (slot ? x2 : x1) + (size_t)b * CH * PLANE;
        float* sp = smem_u;
        float* sh = smem_u + 128;
        for (int k = 0; k < 16; k++) {
            int c = wid * 16 + k;
            const float4* v = (const float4*)(xb + (size_t)c * PLANE);
            float s = 0.f;
            #pragma unroll 4
            for (int i = lane; i < 1024; i += 32) {
                float4 q = v[i];
                s += q.x + q.y + q.z + q.w;
            }
            for (int off = 16; off; off >>= 1) s += __shfl_xor_sync(0xffffffffu, s, off);
            if (lane == 0) sp[c] = s * (1.f / 4096.f);
        }
        __syncthreads();
        if (tid < 16) {
            float acc = 0.f;
            const float4* w1v = (const float4*)(m1w1 + tid * 128);
            #pragma unroll
            for (int j = 0; j < 32; j++) {
                float4 q = w1v[j];
                acc += sp[4*j] * q.x + sp[4*j+1] * q.y + sp[4*j+2] * q.z + sp[4*j+3] * q.w;
            }
            sh[tid] = 0.5f * acc * (1.f + erff(acc * 0.70710678118654752f));
        }
        __syncthreads();
        if (tid < 128) {
            int c = tid;
            const float4* w2v = (const float4*)(m1w2 + c * 144);
            float lg[9];
            float mx = -1e30f;
            #pragma unroll
            for (int k = 0; k < 9; k++) {
                float4 a0 = w2v[k*4], a1 = w2v[k*4+1], a2 = w2v[k*4+2], a3 = w2v[k*4+3];
                float acc = a0.x*sh[0] + a0.y*sh[1] + a0.z*sh[2] + a0.w*sh[3]
                          + a1.x*sh[4] + a1.y*sh[5] + a1.z*sh[6] + a1.w*sh[7]
                          + a2.x*sh[8] + a2.y*sh[9] + a2.z*sh[10] + a2.w*sh[11]
                          + a3.x*sh[12] + a3.y*sh[13] + a3.z*sh[14] + a3.w*sh[15];
                lg[k] = acc;
                mx = fmaxf(mx, acc);
            }
            float ss = 0.f;
            #pragma unroll
            for (int k = 0; k < 9; k++) { lg[k] = expf(lg[k] - mx); ss += lg[k]; }
            float inv = 1.f / ss;
            #pragma unroll
            for (int k = 0; k < 9; k++) g_wk[slot][(b * 128 + c) * 9 + k] = lg[k] * inv;
        }
        return;
    }
    if (blockIdx.x == 512) {
        for (int i = tid; i < 9216; i += 256) {
            int t = i >> 10, rem = i & 1023;
            int row = rem >> 6, c = rem & 63;
            float v = (row < 8) ? rw1[(row * 64 + c) * 9 + t] : 0.f;
            unsigned off = row * 128 + c * 2;
            unsigned sw = off ^ ((off >> 3) & 0x70);
            *(__nv_bfloat16*)(g_w1pack + t * 4096 + sw) = __ushort_as_bfloat16((unsigned short)bfhi(v));
            *(__nv_bfloat16*)(g_w1pack + t * 4096 + 2048 + sw) = __ushort_as_bfloat16((unsigned short)bflo(v));
        }
        return;
    }
    if (blockIdx.x == 513) {
        for (int i = tid; i < 64 * 88; i += 256) {
            int o = i / 88, k = i - o * 88;
            float v = 0.f;
            if (k < 72) { int t = k >> 3, r = k & 7; v = rw2[(o * 8 + r) * 9 + t]; }
            *(__nv_bfloat16*)(g_w2pack + o * 176 + k * 2) = __ushort_as_bfloat16((unsigned short)bfhi(v));
            *(__nv_bfloat16*)(g_w2pack + 11264 + o * 176 + k * 2) = __ushort_as_bfloat16((unsigned short)bflo(v));
        }
        return;
    }
    if (blockIdx.x >= 514) {
        int bi = blockIdx.x - 514;
        for (int e = bi * 16384 + tid; e < (bi + 1) * 16384; e += 256) {
            int cc = e & 31, rem = e >> 5;
            int o = rem & 127, rem2 = rem >> 7;
            int pl = rem2 & 1, chunk = rem2 >> 1;
            float v = aw[o * 256 + chunk * 32 + cc];
            unsigned bits = pl ? bflo(v) : bfhi(v);
            *(__nv_bfloat16*)(g_awpk + ((chunk * 2 + pl) * 128 + o) * 80 + cc * 2) =
                __ushort_as_bfloat16((unsigned short)bits);
        }
        return;
    }
    int sub = blockIdx.x >> 7, ci = blockIdx.x & 127;
    float* s1 = smem_u;
    for (int i = tid; i < 1152; i += 256) {
        int c = i / 9, t = i - c * 9;
        s1[i] = w1[((size_t)(c * 4 + sub) * 128 + ci) * 9 + t];
    }
    __syncthreads();
    if (tid < 64) {
        int o = tid;
        float acc[9] = {0.f,0.f,0.f,0.f,0.f,0.f,0.f,0.f,0.f};
        for (int c = 0; c < 128; c++) {
            float wv = w2[o * 128 + c];
            #pragma unroll
            for (int t = 0; t < 9; t++) acc[t] += wv * s1[c * 9 + t];
        }
        int g = ci >> 6, cl = ci & 63;
        unsigned off = ((o >> 3) << 10) + ((o & 7) << 7) + (cl << 1);
        unsigned sw = off ^ ((off >> 3) & 0x70);
        #pragma unroll
        for (int t = 0; t < 9; t++) {
            float v = acc[t];
            unsigned char* base = g_wpack + ((size_t)((t * 2 + g) * 8 + sub * 2)) * 8192;
            *(__nv_bfloat16*)(base + sw) = __ushort_as_bfloat16((unsigned short)bfhi(v));
            *(__nv_bfloat16*)(base + 8192 + sw) = __ushort_as_bfloat16((unsigned short)bflo(v));
        }
    }
}

// ---------------- mlp2 ----------------
__global__ void mlp_kernel(const float* __restrict__ w1, const float* __restrict__ w2) {
    int slot = blockIdx.x >> 4;
    int b = blockIdx.x & 15;
    int tid = threadIdx.x;
    __shared__ float sp[128], sh[16];
    sp[tid] = g_pool[slot][b * 128 + tid];
    __syncthreads();
    if (tid < 16) {
        float acc = 0.f;
        const float4* w1v = (const float4*)(w1 + tid * 128);
        #pragma unroll
        for (int j = 0; j < 32; j++) {
            float4 q = w1v[j];
            acc += sp[4*j] * q.x + sp[4*j+1] * q.y + sp[4*j+2] * q.z + sp[4*j+3] * q.w;
        }
        sh[tid] = 0.5f * acc * (1.f + erff(acc * 0.70710678118654752f));
    }
    __syncthreads();
    int c = tid;
    const float4* w2v = (const float4*)(w2 + c * 144);
    float lg[9];
    float mx = -1e30f;
    #pragma unroll
    for (int k = 0; k < 9; k++) {
        float4 a0 = w2v[k*4], a1 = w2v[k*4+1], a2 = w2v[k*4+2], a3 = w2v[k*4+3];
        float acc = a0.x*sh[0] + a0.y*sh[1] + a0.z*sh[2] + a0.w*sh[3]
                  + a1.x*sh[4] + a1.y*sh[5] + a1.z*sh[6] + a1.w*sh[7]
                  + a2.x*sh[8] + a2.y*sh[9] + a2.z*sh[10] + a2.w*sh[11]
                  + a3.x*sh[12] + a3.y*sh[13] + a3.z*sh[14] + a3.w*sh[15];
        lg[k] = acc;
        mx = fmaxf(mx, acc);
    }
    float ss = 0.f;
    #pragma unroll
    for (int k = 0; k < 9; k++) { lg[k] = expf(lg[k] - mx); ss += lg[k]; }
    float inv = 1.f / ss;
    #pragma unroll
    for (int k = 0; k < 9; k++) g_wk[slot][(b * 128 + c) * 9 + k] = lg[k] * inv;
}

// ---------------- dsc ----------------
__global__ void __launch_bounds__(256, 4) dsc_kernel(const float* __restrict__ x1,
                                                     const float* __restrict__ x2,
                                                     int phase) {
    int slot = blockIdx.x >> 11;
    int bc = blockIdx.x & 2047;
    const float* xext = slot ? x2 : x1;
    const float* src = phase ? &g_t[slot][(size_t)bc * PLANE]
                             : xext + (size_t)bc * PLANE;
    float wk[9];
    #pragma unroll
    for (int k = 0; k < 9; k++) wk[k] = g_wk[slot][bc * 9 + k];
    __shared__ float sp[66][72];
    int tid = threadIdx.x;
    if (tid < 72) { sp[0][tid] = 0.f; sp[65][tid] = 0.f; }
    if (tid < 64) { sp[tid + 1][3] = 0.f; sp[tid + 1][68] = 0.f; }
    {
        int p = tid * 16;
        int h = p >> 6, w = p & 63;
        const float4* s4 = (const float4*)(src + p);
        float4* d = (float4*)&sp[h + 1][w + 4];
        d[0] = s4[0]; d[1] = s4[1]; d[2] = s4[2]; d[3] = s4[3];
    }
    __syncthreads();
    int h = tid >> 2, xb = (tid & 3) * 16;
    float r0[24], r1[24], r2[24];
    #pragma unroll
    for (int k = 0; k < 6; k++) {
        *(float4*)&r0[k * 4] = *(const float4*)&sp[h + 0][xb + k * 4];
        *(float4*)&r1[k * 4] = *(const float4*)&sp[h + 1][xb + k * 4];
        *(float4*)&r2[k * 4] = *(const float4*)&sp[h + 2][xb + k * 4];
    }
    float acc[16];
    #pragma unroll
    for (int j = 0; j < 16; j++) {
        float a = r1[j + 4];
        a += wk[0] * r0[j + 3]; a += wk[1] * r0[j + 4]; a += wk[2] * r0[j + 5];
        a += wk[3] * r1[j + 3]; a += wk[4] * r1[j + 4]; a += wk[5] * r1[j + 5];
        a += wk[6] * r2[j + 3]; a += wk[7] * r2[j + 4]; a += wk[8] * r2[j + 5];
        acc[j] = a;
    }
    if (phase) {
        unsigned hbuf[8], lbuf[8];
        #pragma unroll
        for (int j = 0; j < 8; j++) {
            hbuf[j] = bfhi(acc[2 * j]) | (bfhi(acc[2 * j + 1]) << 16);
            lbuf[j] = bflo(acc[2 * j]) | (bflo(acc[2 * j + 1]) << 16);
        }
        size_t rowoff = ((size_t)slot * 2048 + bc) * 2048 + tid * 8;
        *(uint4*)(g_abH + rowoff) = *(uint4*)hbuf;
        *(uint4*)(g_abH + rowoff + 4) = *(uint4*)(hbuf + 4);
        *(uint4*)(g_abL + rowoff) = *(uint4*)lbuf;
        *(uint4*)(g_abL + rowoff + 4) = *(uint4*)(lbuf + 4);
    } else {
        float* dst = &g_t[slot][(size_t)bc * PLANE];
        int p = tid * 16;
        float psum = 0.f;
        #pragma unroll
        for (int j = 0; j < 16; j++) { acc[j] = fmaxf(acc[j], 0.f); psum += acc[j]; }
        #pragma unroll
        for (int k = 0; k < 4; k++)
            *(float4*)&dst[p + k * 4] = make_float4(acc[k*4], acc[k*4+1], acc[k*4+2], acc[k*4+3]);
        for (int off = 16; off; off >>= 1) psum += __shfl_xor_sync(0xffffffffu, psum, off);
        __shared__ float red[8];
        if ((tid & 31) == 0) red[tid >> 5] = psum;
        __syncthreads();
        if (tid < 32) {
            float r = (tid < 8) ? red[tid] : 0.f;
            for (int off = 4; off; off >>= 1) r += __shfl_xor_sync(0xffffffffu, r, off);
            if (tid == 0) g_pool[slot][bc] = r * (1.f / 4096.f);
        }
    }
}

// ---------------- align via mma.sync ----------------
#define ALN_BUF 36864
#define ALN_SMEM (2 * ALN_BUF + 1024)
__global__ void __launch_bounds__(256, 2) align_mma() {
    extern __shared__ char dynraw[];
    char* base = (char*)((((uintptr_t)dynraw) + 1023) & ~(uintptr_t)1023);
    int tid = threadIdx.x;
    int w = tid >> 5, lane = tid & 31;
    int b = blockIdx.x >> 5;
    int pix0 = (blockIdx.x & 31) * 128;

    float acc[4][4][4];
    #pragma unroll
    for (int mt = 0; mt < 4; mt++)
        #pragma unroll
        for (int nt = 0; nt < 4; nt++)
            #pragma unroll
            for (int r = 0; r < 4; r++) acc[mt][nt][r] = 0.f;

    auto fill = [&](int chunk, int buf) {
        char* bb = base + buf * ALN_BUF;
        for (int i = tid; i < 1024; i += 256) {
            int pl = i >> 9, r = i & 511;
            int cc = r >> 4, j = r & 15;
            int gc = chunk * 32 + cc;
            size_t row = (size_t)((gc >> 7) * 2048 + b * 128 + (gc & 127));
            const unsigned* src = (pl ? g_abL : g_abH) + row * 2048 + (pix0 >> 1) + j * 4;
            unsigned off = (unsigned)(cc * 256 + j * 16);
            unsigned sw = off ^ ((off >> 4) & 0xF0);
            cp16(smaddr(bb + pl * 8192) + sw, src);
        }
        for (int i = tid; i < 1280; i += 256) {
            int pl = i >= 640, r = pl ? i - 640 : i;
            int o = r / 5, j = r - o * 5;
            const unsigned char* src = g_awpk + (size_t)chunk * 20480 + pl * 10240 + o * 80 + j * 16;
            cp16(smaddr(bb + 16384 + pl * 10240) + o * 80 + j * 16, src);
        }
    };

    fill(0, 0);
    cp_commit(); cp_wait0();
    __syncthreads();

    int m0 = (w & 1) * 64, n0 = (w >> 1) * 32;
    for (int chunk = 0; chunk < 8; chunk++) {
        int buf = chunk & 1;
        if (chunk < 7) { fill(chunk + 1, buf ^ 1); cp_commit(); }
        char* bb = base + buf * ALN_BUF;
        unsigned aHiB = smaddr(bb), aLoB = smaddr(bb + 8192);
        unsigned bHiB = smaddr(bb + 16384), bLoB = smaddr(bb + 26624);
        #pragma unroll
        for (int kt = 0; kt < 2; kt++) {
            int c0 = kt * 16;
            unsigned bH[2][4], bL[2][4];
            #pragma unroll
            for (int nh = 0; nh < 2; nh++) {
                unsigned boff = (unsigned)((n0 + nh * 16 + (lane & 15)) * 80 + c0 * 2 + ((lane >> 4) << 4));
                ldsm4(bH[nh], bHiB + boff);
                ldsm4(bL[nh], bLoB + boff);
            }
            #pragma unroll
            for (int mt = 0; mt < 4; mt++) {
                unsigned aoff = (unsigned)(((lane & 7) + ((lane >> 4) << 3) + c0) * 256
                                           + (m0 + mt * 16 + (((lane >> 3) & 1) << 3)) * 2);
                unsigned asw = aoff ^ ((aoff >> 4) & 0xF0);
                unsigned aH[4], aL[4];
                ldsm4t(aH, aHiB + asw);
                ldsm4t(aL, aLoB + asw);
                #pragma unroll
                for (int nh = 0; nh < 2; nh++) {
                    float* dA = acc[mt][2 * nh];
                    float* dB = acc[mt][2 * nh + 1];
                    mma_bf16(dA, aH, bH[nh][0], bH[nh][2]);
                    mma_bf16(dB, aH, bH[nh][1], bH[nh][3]);
                    mma_bf16(dA, aH, bL[nh][0], bL[nh][2]);
                    mma_bf16(dB, aH, bL[nh][1], bL[nh][3]);
                    mma_bf16(dA, aL, bH[nh][0], bH[nh][2]);
                    mma_bf16(dB, aL, bH[nh][1], bH[nh][3]);
                }
            }
        }
        if (chunk < 7) cp_wait0();
        __syncthreads();
    }

    unsigned* fH = g_fuH + (size_t)b * PLANE * 64;
    unsigned* fL = g_fuL + (size_t)b * PLANE * 64;
    #pragma unroll
    for (int mt = 0; mt < 4; mt++) {
        #pragma unroll
        for (int nt = 0; nt < 4; nt++) {
            float* d = acc[mt][nt];
            int row = pix0 + m0 + mt * 16 + (lane >> 2);
            int op = ((n0 + nt * 8) >> 1) + (lane & 3);
            fH[(size_t)row * 64 + op] = bfhi(d[0]) | (bfhi(d[1]) << 16);
            fL[(size_t)row * 64 + op] = bflo(d[0]) | (bflo(d[1]) << 16);
            fH[(size_t)(row + 8) * 64 + op] = bfhi(d[2]) | (bfhi(d[3]) << 16);
            fL[(size_t)(row + 8) * 64 + op] = bflo(d[2]) | (bflo(d[3]) << 16);
        }
    }
}

// ---------------- upconv via mma.sync, 512 threads, plane-only epilogue ---------
#define UPC_BUF 98304
#define UPC_SMEM (2 * UPC_BUF + 1024)
__global__ void __launch_bounds__(512, 1) upconv_mma() {
    extern __shared__ char dynraw[];
    char* base = (char*)((((uintptr_t)dynraw) + 1023) & ~(uintptr_t)1023);
    int tid = threadIdx.x;
    int w = tid >> 5, lane = tid & 31;
    int mi = w & 7, nh = w >> 3;
    int b = blockIdx.x >> 5;
    int y0 = (blockIdx.x & 31) * 2;

    const unsigned* fH = g_fuH + (size_t)b * PLANE * 64;
    const unsigned* fL = g_fuL + (size_t)b * PLANE * 64;
    int m = tid >> 2;
    int plane = (tid >> 1) & 1;
    int jh = tid & 1;
    int mrow = m >> 6, mx = m & 63;

    float acc[4][4][4];
    #pragma unroll
    for (int s = 0; s < 4; s++)
        #pragma unroll
        for (int nf = 0; nf < 4; nf++)
            #pragma unroll
            for (int r = 0; r < 4; r++) acc[s][nf][r] = 0.f;

    auto fill = [&](int q, int buf) {
        char* bb = base + buf * UPC_BUF;
        int tap = q >> 1, g = q & 1;
        int kh = tap / 3, kw = tap - kh * 3;
        {
            const unsigned char* bsrc = g_wpack + (size_t)q * 65536;
            unsigned bdst = smaddr(bb + 32768);
            #pragma unroll 4
            for (int i = tid; i < 4096; i += 512)
                cp16(bdst + i * 16, bsrc + i * 16);
        }
        {
            int yy = y0 + mrow + kh - 1;
            int xx = mx + kw - 1;
            int valid = (((unsigned)yy < 64u) && ((unsigned)xx < 64u)) ? 1 : 0;
            const unsigned* src = (plane ? fL : fH) + ((size_t)(yy * 64 + xx) * 64 + g * 32 + jh * 16);
            unsigned dstb = smaddr(bb + plane * 16384);
            unsigned db = (unsigned)(m * 128 + jh * 64);
            #pragma unroll
            for (int j = 0; j < 4; j++) {
                unsigned off = db + j * 16;
                unsigned sw = off ^ ((off >> 3) & 0x70);
                cp16z(dstb + sw, src + j * 4, valid);
            }
        }
    };

    fill(0, 0);
    cp_commit(); cp_wait0();
    __syncthreads();

    for (int q = 0; q < 18; q++) {
        int buf = q & 1;
        if (q < 17) { fill(q + 1, buf ^ 1); cp_commit(); }
        char* bb = base + buf * UPC_BUF;
        unsigned aHiB = smaddr(bb), aLoB = smaddr(bb + 16384);
        unsigned bB = smaddr(bb + 32768);
        #pragma unroll
        for (int kf = 0; kf < 4; kf++) {
            unsigned aH[4], aL[4];
            {
                unsigned arow = (unsigned)(16 * mi + (lane & 15));
                unsigned aoff = arow * 128 + kf * 32 + ((lane >> 4) << 4);
                unsigned asw = aoff ^ ((aoff >> 3) & 0x70);
                ldsm4(aH, aHiB + asw);
                ldsm4(aL, aLoB + asw);
            }
            #pragma unroll
            for (int s = 0; s < 4; s++) {
                #pragma unroll
                for (int ng = 0; ng < 2; ng++) {
                    unsigned brow = (unsigned)(16 * (nh * 2 + ng) + (lane & 15));
                    unsigned boff = brow * 128 + kf * 32 + ((lane >> 4) << 4);
                    unsigned bsw = boff ^ ((boff >> 3) & 0x70);
                    unsigned bH[4], bL[4];
                    ldsm4(bH, bB + s * 16384 + bsw);
                    ldsm4(bL, bB + s * 16384 + 8192 + bsw);
                    float* dA = acc[s][2 * ng];
                    float* dB = acc[s][2 * ng + 1];
                    mma_bf16(dA, aH, bH[0], bH[2]);
                    mma_bf16(dB, aH, bH[1], bH[3]);
                    mma_bf16(dA, aH, bL[0], bL[2]);
                    mma_bf16(dB, aH, bL[1], bL[3]);
                    mma_bf16(dA, aL, bH[0], bH[2]);
                    mma_bf16(dB, aL, bH[1], bH[3]);
                }
            }
        }
        if (q < 17) cp_wait0();
        __syncthreads();
    }

    // epilogue: direct register -> packed hi/lo plane stores (no smem, no sync)
    unsigned* uH = g_upH + (size_t)b * 16384 * 32;
    unsigned* uL = g_upL + (size_t)b * 16384 * 32;
    int m0 = 16 * mi + (lane >> 2);
    #pragma unroll
    for (int half = 0; half < 2; half++) {
        int mm = m0 + half * 8;
        int prow = mm >> 6, px = mm & 63;
        #pragma unroll
        for (int s = 0; s < 4; s++) {
            int y = 2 * (y0 + prow) + (s >> 1);
            int x2 = 2 * px + (s & 1);
            size_t rowbase = (size_t)(y * 128 + x2) * 32;
            #pragma unroll
            for (int nf = 0; nf < 4; nf++) {
                float* d = acc[s][nf];
                float v0 = d[half * 2], v1 = d[half * 2 + 1];
                int op = nh * 16 + nf * 4 + (lane & 3);
                uH[rowbase + op] = bfhi(v0) | (bfhi(v1) << 16);
                uL[rowbase + op] = bflo(v0) | (bflo(v1) << 16);
            }
        }
    }
}

// ---------------- reconv1 via mma, 512 threads, 2 rows/block ----------------
#define RC1_SMEM (66560 * 2 + 36864 + 1024)
__global__ void __launch_bounds__(512, 1) reconv1_mma() {
    extern __shared__ char dynraw[];
    char* base = (char*)((((uintptr_t)dynraw) + 1023) & ~(uintptr_t)1023);
    char* aHi = base;
    char* aLo = base + 66560;
    char* sB  = base + 133120;
    int tid = threadIdx.x;
    int w = tid >> 5, lane = tid & 31;
    int xt = w & 7, ys = w >> 3;
    int b = blockIdx.x >> 6;
    int y0 = (blockIdx.x & 63) * 2;
    const unsigned* uH = g_upH + (size_t)b * 16384 * 32;
    const unsigned* uL = g_upL + (size_t)b * 16384 * 32;

    {
        unsigned bdst = smaddr(sB);
        for (int i = tid; i < 2304; i += 512)
            cp16(bdst + i * 16, g_w1pack + i * 16);
    }
    unsigned aHiB = smaddr(aHi), aLoB = smaddr(aLo);
    for (int u = tid; u < 4160; u += 512) {
        int slot = u >> 3, j = u & 7;
        int r = slot / 130, xi = slot - r * 130;
        int gy = y0 + r - 1, gx = xi - 1;
        int valid = (((unsigned)gy < 128u) && ((unsigned)gx < 128u)) ? 1 : 0;
        size_t sidx = (size_t)(gy * 128 + gx) * 32 + j * 4;
        unsigned off = (unsigned)(slot * 128 + j * 16);
        unsigned sw = off ^ ((off >> 3) & 0x70);
        cp16z(aHiB + sw, uH + sidx, valid);
        cp16z(aLoB + sw, uL + sidx, valid);
    }
    cp_commit(); cp_wait0();
    __syncthreads();

    unsigned bB = smaddr(sB);
    float d[4] = {0.f, 0.f, 0.f, 0.f};
    int x0 = 16 * xt;
    for (int t = 0; t < 9; t++) {
        int kh = t / 3, kw = t - kh * 3;
        #pragma unroll
        for (int kf = 0; kf < 4; kf++) {
            unsigned bH[4], bL[4];
            unsigned boff = (unsigned)((lane & 15) * 128 + kf * 32 + ((lane >> 4) << 4));
            unsigned bsw = boff ^ ((boff >> 3) & 0x70);
            ldsm4(bH, bB + t * 4096 + bsw);
            ldsm4(bL, bB + t * 4096 + 2048 + bsw);
            int slot = (ys + kh) * 130 + x0 + (lane & 15) + kw;
            unsigned aoff = (unsigned)(slot * 128 + kf * 32 + ((lane >> 4) << 4));
            unsigned asw = aoff ^ ((aoff >> 3) & 0x70);
            unsigned aH[4], aL[4];
            ldsm4(aH, aHiB + asw);
            ldsm4(aL, aLoB + asw);
            mma_bf16(d, aH, bH[0], bH[2]);
            mma_bf16(d, aH, bL[0], bL[2]);
            mma_bf16(d, aL, bH[0], bH[2]);
        }
    }
    int r = lane >> 2, c = (lane & 3) * 2;
    int px = x0 + r;
    unsigned* tb = g_treb + ((size_t)b * 16384 + (y0 + ys) * 128) * 8;
    tb[px * 8 + c]           = packbf(fmaxf(d[0], 0.f));
    tb[px * 8 + c + 1]       = packbf(fmaxf(d[1], 0.f));
    tb[(px + 8) * 8 + c]     = packbf(fmaxf(d[2], 0.f));
    tb[(px + 8) * 8 + c + 1] = packbf(fmaxf(d[3], 0.f));
}

// ---------------- reconv2 via mma + residual reconstruction ----------------
#define RC2_SMEM (12480 + 22528 + 22528 + 22528 + 1024)
__global__ void __launch_bounds__(256, 2) reconv2_mma(float* __restrict__ out) {
    extern __shared__ char dynraw2[];
    char* base = (char*)((((uintptr_t)dynraw2) + 1023) & ~(uintptr_t)1023);
    unsigned* sTre = (unsigned*)base;
    char* aHi = base + 12480;
    char* aLo = base + 12480 + 22528;
    char* sB  = base + 12480 + 45056;
    int tid = threadIdx.x;
    int w = tid >> 5, lane = tid & 31;
    int b = blockIdx.x >> 7;
    int y = blockIdx.x & 127;
    const unsigned* tb = g_treb + (size_t)b * 16384 * 8;
    const unsigned* uH = g_upH + (size_t)b * 16384 * 32;
    const unsigned* uL = g_upL + (size_t)b * 16384 * 32;

    {
        unsigned bdst = smaddr(sB);
        for (int i = tid; i < 1408; i += 256)
            cp16(bdst + i * 16, g_w2pack + i * 16);
        cp_commit();
    }
    for (int u = tid; u < 780; u += 256) {
        int slot = u >> 1, hf = u & 1;
        int r = slot / 130, xi = slot - r * 130;
        int gy = y + r - 1, gx = xi - 1;
        uint4 v = make_uint4(0u,0u,0u,0u);
        if (((unsigned)gy < 128u) && ((unsigned)gx < 128u))
            v = *((const uint4*)(tb + (size_t)(gy * 128 + gx) * 8) + hf);
        *((uint4*)(sTre + slot * 8) + hf) = v;
    }
    __syncthreads();
    for (int u = tid; u < 1152; u += 256) {
        int x = u / 9, t = u - x * 9;
        int kh = t / 3, kw = t - kh * 3;
        const unsigned* src = sTre + (kh * 130 + x + kw) * 8;
        uint4 w0 = *(const uint4*)src;
        uint4 w1 = *(const uint4*)(src + 4);
        uint4 hi, lo;
        hi.x = prmt(w0.x, w0.y, 0x7632); hi.y = prmt(w0.z, w0.w, 0x7632);
        hi.z = prmt(w1.x, w1.y, 0x7632); hi.w = prmt(w1.z, w1.w, 0x7632);
        lo.x = prmt(w0.x, w0.y, 0x5410); lo.y = prmt(w0.z, w0.w, 0x5410);
        lo.z = prmt(w1.x, w1.y, 0x5410); lo.w = prmt(w1.z, w1.w, 0x5410);
        *(uint4*)(aHi + x * 176 + t * 16) = hi;
        *(uint4*)(aLo + x * 176 + t * 16) = lo;
    }
    for (int u = tid; u < 128; u += 256) {
        uint4 z = make_uint4(0u,0u,0u,0u);
        *(uint4*)(aHi + u * 176 + 144) = z;
        *(uint4*)(aLo + u * 176 + 144) = z;
    }
    cp_wait0();
    __syncthreads();

    unsigned aHiB = smaddr(aHi), aLoB = smaddr(aLo), bB = smaddr(sB);
    float acc[4][2][4];
    #pragma unroll
    for (int g = 0; g < 4; g++)
        #pragma unroll
        for (int nf = 0; nf < 2; nf++)
            #pragma unroll
            for (int r = 0; r < 4; r++) acc[g][nf][r] = 0.f;
    int x0 = 16 * w;
    #pragma unroll
    for (int kf = 0; kf < 5; kf++) {
        unsigned aH[4], aL[4];
        unsigned aoff = (unsigned)((x0 + (lane & 15)) * 176 + kf * 32 + ((lane >> 4) << 4));
        ldsm4(aH, aHiB + aoff);
        ldsm4(aL, aLoB + aoff);
        #pragma unroll
        for (int n0g = 0; n0g < 4; n0g++) {
            unsigned bH[4], bL[4];
            unsigned boff = (unsigned)((16 * n0g + (lane & 15)) * 176 + kf * 32 + ((lane >> 4) << 4));
            ldsm4(bH, bB + boff);
            ldsm4(bL, bB + 11264 + boff);
            float* dA = acc[n0g][0];
            float* dB = acc[n0g][1];
            mma_bf16(dA, aH, bH[0], bH[2]);
            mma_bf16(dB, aH, bH[1], bH[3]);
            mma_bf16(dA, aH, bL[0], bL[2]);
            mma_bf16(dB, aH, bL[1], bL[3]);
            mma_bf16(dA, aL, bH[0], bH[2]);
            mma_bf16(dB, aL, bH[1], bH[3]);
        }
    }
    __syncthreads();
    float* sD = (float*)aHi;
    {
        int r = lane >> 2, c = (lane & 3) * 2;
        int px = x0 + r;
        #pragma unroll
        for (int n0g = 0; n0g < 4; n0g++)
            #pragma unroll
            for (int nf = 0; nf < 2; nf++) {
                int o = n0g * 16 + nf * 8 + c;
                sD[px * 65 + o]           = acc[n0g][nf][0];
                sD[px * 65 + o + 1]       = acc[n0g][nf][1];
                sD[(px + 8) * 65 + o]     = acc[n0g][nf][2];
                sD[(px + 8) * 65 + o + 1] = acc[n0g][nf][3];
            }
    }
    __syncthreads();
    // add residual up = hi + lo (coalesced reads)
    for (int i = tid; i < 4096; i += 256) {
        int x = i >> 5, op = i & 31;
        size_t idx = (size_t)(y * 128 + x) * 32 + op;
        unsigned h = uH[idx], l = uL[idx];
        float v0 = __uint_as_float(h << 16) + __uint_as_float(l << 16);
        float v1 = __uint_as_float(h & 0xffff0000u) + __uint_as_float(l & 0xffff0000u);
        sD[x * 65 + 2 * op]     += v0;
        sD[x * 65 + 2 * op + 1] += v1;
    }
    __syncthreads();
    for (int i = tid; i < 8192; i += 256) {
        int o = i >> 7, x = i & 127;
        out[((size_t)(b * 64 + o) * 128 + y) * 128 + x] = sD[x * 65 + o];
    }
}

// ---------------------------------------------------------------------------
extern "C" void kernel_launch(void* const* d_in, const int* in_sizes, int n_in,
                              void* d_out, int out_size) {
    const float* x1    = (const float*)d_in[0];
    const float* x2    = (const float*)d_in[1];
    const float* d1_w1 = (const float*)d_in[2];
    const float* d1_w2 = (const float*)d_in[3];
    const float* d2_w1 = (const float*)d_in[4];
    const float* d2_w2 = (const float*)d_in[5];
    const float* align_w = (const float*)d_in[6];
    const float* up_w1 = (const float*)d_in[7];
    const float* up_w2 = (const float*)d_in[8];
    const float* re_w1 = (const float*)d_in[9];
    const float* re_w2 = (const float*)d_in[10];
    float* out = (float*)d_out;

    static int smem_set = 0;
    if (!smem_set) {
        cudaFuncSetAttribute(align_mma, cudaFuncAttributeMaxDynamicSharedMemorySize, ALN_SMEM);
        cudaFuncSetAttribute(upconv_mma, cudaFuncAttributeMaxDynamicSharedMemorySize, UPC_SMEM);
        cudaFuncSetAttribute(reconv1_mma, cudaFuncAttributeMaxDynamicSharedMemorySize, RC1_SMEM);
        cudaFuncSetAttribute(reconv2_mma, cudaFuncAttributeMaxDynamicSharedMemorySize, RC2_SMEM);
        smem_set = 1;
    }

    packpool_kernel<<<550, 256>>>(align_w, up_w1, up_w2, re_w1, re_w2,
                                  x1, x2, d1_w1, d1_w2);
    dsc_kernel<<<4096, 256>>>(x1, x2, 0);
    mlp_kernel<<<32, 128>>>(d2_w1, d2_w2);
    dsc_kernel<<<4096, 256>>>(x1, x2, 1);
    align_mma<<<512, 256, ALN_SMEM>>>();
    upconv_mma<<<512, 512, UPC_SMEM>>>();
    reconv1_mma<<<1024, 512, RC1_SMEM>>>();
    reconv2_mma<<<2048, 256, RC2_SMEM>>>(out);
}

// round 14
// speedup vs baseline: 1.3522x; 1.0209x over previous
#include <cuda_runtime.h>
#include <cuda_bf16.h>
#include <math.h>
#include <stdint.h>

// ---------------------------------------------------------------------------
// DSFDecoder: B=16, C=128, H=W=64, OUT=64, CR=16, RE=8
// All GEMM-shaped work on mma.sync bf16 (split hi/lo, 3 terms).
// R14: upconv A window resident in smem (2 fills instead of 18).
// ---------------------------------------------------------------------------

#define PLANE 4096
#define CH    128
#define BATCH 16

typedef unsigned long long ull;

__device__ __forceinline__ unsigned smaddr(const void* p) {
    return (unsigned)__cvta_generic_to_shared(p);
}
__device__ __forceinline__ void cp16(unsigned d, const void* s) {
    asm volatile("cp.async.cg.shared.global [%0], [%1], 16;" :: "r"(d), "l"(s) : "memory");
}
__device__ __forceinline__ void cp16z(unsigned d, const void* s, int valid) {
    asm volatile("cp.async.cg.shared.global [%0], [%1], 16, %2;"
                 :: "r"(d), "l"(s), "r"(valid ? 16 : 0) : "memory");
}
__device__ __forceinline__ void cp_commit() {
    asm volatile("cp.async.commit_group;" ::: "memory");
}
__device__ __forceinline__ void cp_wait0() {
    asm volatile("cp.async.wait_group 0;" ::: "memory");
}
__device__ __forceinline__ unsigned prmt(unsigned a, unsigned b, unsigned sel) {
    unsigned r; asm("prmt.b32 %0, %1, %2, %3;" : "=r"(r) : "r"(a), "r"(b), "r"(sel));
    return r;
}
__device__ __forceinline__ void ldsm4(unsigned* r, unsigned addr) {
    asm volatile("ldmatrix.sync.aligned.m8n8.x4.shared.b16 {%0,%1,%2,%3}, [%4];"
                 : "=r"(r[0]), "=r"(r[1]), "=r"(r[2]), "=r"(r[3]) : "r"(addr));
}
__device__ __forceinline__ void ldsm4t(unsigned* r, unsigned addr) {
    asm volatile("ldmatrix.sync.aligned.m8n8.x4.trans.shared.b16 {%0,%1,%2,%3}, [%4];"
                 : "=r"(r[0]), "=r"(r[1]), "=r"(r[2]), "=r"(r[3]) : "r"(addr));
}
__device__ __forceinline__ void mma_bf16(float* d, const unsigned* a, unsigned b0, unsigned b1) {
    asm volatile(
        "mma.sync.aligned.m16n8k16.row.col.f32.bf16.bf16.f32 "
        "{%0,%1,%2,%3}, {%4,%5,%6,%7}, {%8,%9}, {%0,%1,%2,%3};"
        : "+f"(d[0]), "+f"(d[1]), "+f"(d[2]), "+f"(d[3])
        : "r"(a[0]), "r"(a[1]), "r"(a[2]), "r"(a[3]), "r"(b0), "r"(b1));
}
__device__ __forceinline__ unsigned packbf(float v) {
    __nv_bfloat16 h = __float2bfloat16(v);
    __nv_bfloat16 l = __float2bfloat16(v - __bfloat162float(h));
    return (unsigned)__bfloat16_as_ushort(l) | ((unsigned)__bfloat16_as_ushort(h) << 16);
}
__device__ __forceinline__ unsigned bfhi(float v) {
    return (unsigned)__bfloat16_as_ushort(__float2bfloat16(v));
}
__device__ __forceinline__ unsigned bflo(float v) {
    __nv_bfloat16 h = __float2bfloat16(v);
    return (unsigned)__bfloat16_as_ushort(__float2bfloat16(v - __bfloat162float(h)));
}

__device__ float g_t[2][BATCH * CH * PLANE];
__device__ unsigned g_abH[2 * BATCH * CH * 2048];
__device__ unsigned g_abL[2 * BATCH * CH * 2048];
__device__ unsigned g_fuH[BATCH * PLANE * 64];
__device__ unsigned g_fuL[BATCH * PLANE * 64];
__device__ __align__(16) unsigned char g_wpack[18 * 8 * 8192];
__device__ __align__(16) unsigned char g_awpk[8 * 2 * 128 * 80];
__device__ unsigned g_upH[BATCH * 16384 * 32];
__device__ unsigned g_upL[BATCH * 16384 * 32];
__device__ unsigned g_treb[BATCH * 16384 * 8];
__device__ __align__(16) unsigned char g_w1pack[9 * 4096];
__device__ __align__(16) unsigned char g_w2pack[2 * 11264];
__device__ float g_pool[2][BATCH * CH];
__device__ float g_wk[2][BATCH * CH * 9];

// ---------------- pack + poolmlp merged ----------------
__global__ void __launch_bounds__(256, 2) packpool_kernel(
        const float* __restrict__ aw, const float* __restrict__ w1,
        const float* __restrict__ w2, const float* __restrict__ rw1,
        const float* __restrict__ rw2,
        const float* __restrict__ x1, const float* __restrict__ x2,
        const float* __restrict__ m1w1, const float* __restrict__ m1w2) {
    __shared__ float smem_u[2048];
    int tid = threadIdx.x;
    if (blockIdx.x >= 518) {
        int bi = blockIdx.x - 518;
        int slot = bi >> 4;
        int b = bi & 15;
        int wid = tid >> 5, lane = tid & 31;
        const float* xb = (slot ? x2 : x1) + (size_t)b * CH * PLANE;
        float* sp = smem_u;
        float* sh = smem_u + 128;
        for (int k = 0; k < 16; k++) {
            int c = wid * 16 + k;
            const float4* v = (const float4*)(xb + (size_t)c * PLANE);
            float s = 0.f;
            #pragma unroll 4
            for (int i = lane; i < 1024; i += 32) {
                float4 q = v[i];
                s += q.x + q.y + q.z + q.w;
            }
            for (int off = 16; off; off >>= 1) s += __shfl_xor_sync(0xffffffffu, s, off);
            if (lane == 0) sp[c] = s * (1.f / 4096.f);
        }
        __syncthreads();
        if (tid < 16) {
            float acc = 0.f;
            const float4* w1v = (const float4*)(m1w1 + tid * 128);
            #pragma unroll
            for (int j = 0; j < 32; j++) {
                float4 q = w1v[j];
                acc += sp[4*j] * q.x + sp[4*j+1] * q.y + sp[4*j+2] * q.z + sp[4*j+3] * q.w;
            }
            sh[tid] = 0.5f * acc * (1.f + erff(acc * 0.70710678118654752f));
        }
        __syncthreads();
        if (tid < 128) {
            int c = tid;
            const float4* w2v = (const float4*)(m1w2 + c * 144);
            float lg[9];
            float mx = -1e30f;
            #pragma unroll
            for (int k = 0; k < 9; k++) {
                float4 a0 = w2v[k*4], a1 = w2v[k*4+1], a2 = w2v[k*4+2], a3 = w2v[k*4+3];
                float acc = a0.x*sh[0] + a0.y*sh[1] + a0.z*sh[2] + a0.w*sh[3]
                          + a1.x*sh[4] + a1.y*sh[5] + a1.z*sh[6] + a1.w*sh[7]
                          + a2.x*sh[8] + a2.y*sh[9] + a2.z*sh[10] + a2.w*sh[11]
                          + a3.x*sh[12] + a3.y*sh[13] + a3.z*sh[14] + a3.w*sh[15];
                lg[k] = acc;
                mx = fmaxf(mx, acc);
            }
            float ss = 0.f;
            #pragma unroll
            for (int k = 0; k < 9; k++) { lg[k] = expf(lg[k] - mx); ss += lg[k]; }
            float inv = 1.f / ss;
            #pragma unroll
            for (int k = 0; k < 9; k++) g_wk[slot][(b * 128 + c) * 9 + k] = lg[k] * inv;
        }
        return;
    }
    if (blockIdx.x == 512) {
        for (int i = tid; i < 9216; i += 256) {
            int t = i >> 10, rem = i & 1023;
            int row = rem >> 6, c = rem & 63;
            float v = (row < 8) ? rw1[(row * 64 + c) * 9 + t] : 0.f;
            unsigned off = row * 128 + c * 2;
            unsigned sw = off ^ ((off >> 3) & 0x70);
            *(__nv_bfloat16*)(g_w1pack + t * 4096 + sw) = __ushort_as_bfloat16((unsigned short)bfhi(v));
            *(__nv_bfloat16*)(g_w1pack + t * 4096 + 2048 + sw) = __ushort_as_bfloat16((unsigned short)bflo(v));
        }
        return;
    }
    if (blockIdx.x == 513) {
        for (int i = tid; i < 64 * 88; i += 256) {
            int o = i / 88, k = i - o * 88;
            float v = 0.f;
            if (k < 72) { int t = k >> 3, r = k & 7; v = rw2[(o * 8 + r) * 9 + t]; }
            *(__nv_bfloat16*)(g_w2pack + o * 176 + k * 2) = __ushort_as_bfloat16((unsigned short)bfhi(v));
            *(__nv_bfloat16*)(g_w2pack + 11264 + o * 176 + k * 2) = __ushort_as_bfloat16((unsigned short)bflo(v));
        }
        return;
    }
    if (blockIdx.x >= 514) {
        int bi = blockIdx.x - 514;
        for (int e = bi * 16384 + tid; e < (bi + 1) * 16384; e += 256) {
            int cc = e & 31, rem = e >> 5;
            int o = rem & 127, rem2 = rem >> 7;
            int pl = rem2 & 1, chunk = rem2 >> 1;
            float v = aw[o * 256 + chunk * 32 + cc];
            unsigned bits = pl ? bflo(v) : bfhi(v);
            *(__nv_bfloat16*)(g_awpk + ((chunk * 2 + pl) * 128 + o) * 80 + cc * 2) =
                __ushort_as_bfloat16((unsigned short)bits);
        }
        return;
    }
    int sub = blockIdx.x >> 7, ci = blockIdx.x & 127;
    float* s1 = smem_u;
    for (int i = tid; i < 1152; i += 256) {
        int c = i / 9, t = i - c * 9;
        s1[i] = w1[((size_t)(c * 4 + sub) * 128 + ci) * 9 + t];
    }
    __syncthreads();
    if (tid < 64) {
        int o = tid;
        float acc[9] = {0.f,0.f,0.f,0.f,0.f,0.f,0.f,0.f,0.f};
        for (int c = 0; c < 128; c++) {
            float wv = w2[o * 128 + c];
            #pragma unroll
            for (int t = 0; t < 9; t++) acc[t] += wv * s1[c * 9 + t];
        }
        int g = ci >> 6, cl = ci & 63;
        unsigned off = ((o >> 3) << 10) + ((o & 7) << 7) + (cl << 1);
        unsigned sw = off ^ ((off >> 3) & 0x70);
        #pragma unroll
        for (int t = 0; t < 9; t++) {
            float v = acc[t];
            unsigned char* base = g_wpack + ((size_t)((t * 2 + g) * 8 + sub * 2)) * 8192;
            *(__nv_bfloat16*)(base + sw) = __ushort_as_bfloat16((unsigned short)bfhi(v));
            *(__nv_bfloat16*)(base + 8192 + sw) = __ushort_as_bfloat16((unsigned short)bflo(v));
        }
    }
}

// ---------------- mlp2 ----------------
__global__ void mlp_kernel(const float* __restrict__ w1, const float* __restrict__ w2) {
    int slot = blockIdx.x >> 4;
    int b = blockIdx.x & 15;
    int tid = threadIdx.x;
    __shared__ float sp[128], sh[16];
    sp[tid] = g_pool[slot][b * 128 + tid];
    __syncthreads();
    if (tid < 16) {
        float acc = 0.f;
        const float4* w1v = (const float4*)(w1 + tid * 128);
        #pragma unroll
        for (int j = 0; j < 32; j++) {
            float4 q = w1v[j];
            acc += sp[4*j] * q.x + sp[4*j+1] * q.y + sp[4*j+2] * q.z + sp[4*j+3] * q.w;
        }
        sh[tid] = 0.5f * acc * (1.f + erff(acc * 0.70710678118654752f));
    }
    __syncthreads();
    int c = tid;
    const float4* w2v = (const float4*)(w2 + c * 144);
    float lg[9];
    float mx = -1e30f;
    #pragma unroll
    for (int k = 0; k < 9; k++) {
        float4 a0 = w2v[k*4], a1 = w2v[k*4+1], a2 = w2v[k*4+2], a3 = w2v[k*4+3];
        float acc = a0.x*sh[0] + a0.y*sh[1] + a0.z*sh[2] + a0.w*sh[3]
                  + a1.x*sh[4] + a1.y*sh[5] + a1.z*sh[6] + a1.w*sh[7]
                  + a2.x*sh[8] + a2.y*sh[9] + a2.z*sh[10] + a2.w*sh[11]
                  + a3.x*sh[12] + a3.y*sh[13] + a3.z*sh[14] + a3.w*sh[15];
        lg[k] = acc;
        mx = fmaxf(mx, acc);
    }
    float ss = 0.f;
    #pragma unroll
    for (int k = 0; k < 9; k++) { lg[k] = expf(lg[k] - mx); ss += lg[k]; }
    float inv = 1.f / ss;
    #pragma unroll
    for (int k = 0; k < 9; k++) g_wk[slot][(b * 128 + c) * 9 + k] = lg[k] * inv;
}

// ---------------- dsc ----------------
__global__ void __launch_bounds__(256, 4) dsc_kernel(const float* __restrict__ x1,
                                                     const float* __restrict__ x2,
                                                     int phase) {
    int slot = blockIdx.x >> 11;
    int bc = blockIdx.x & 2047;
    const float* xext = slot ? x2 : x1;
    const float* src = phase ? &g_t[slot][(size_t)bc * PLANE]
                             : xext + (size_t)bc * PLANE;
    float wk[9];
    #pragma unroll
    for (int k = 0; k < 9; k++) wk[k] = g_wk[slot][bc * 9 + k];
    __shared__ float sp[66][72];
    int tid = threadIdx.x;
    if (tid < 72) { sp[0][tid] = 0.f; sp[65][tid] = 0.f; }
    if (tid < 64) { sp[tid + 1][3] = 0.f; sp[tid + 1][68] = 0.f; }
    {
        int p = tid * 16;
        int h = p >> 6, w = p & 63;
        const float4* s4 = (const float4*)(src + p);
        float4* d = (float4*)&sp[h + 1][w + 4];
        d[0] = s4[0]; d[1] = s4[1]; d[2] = s4[2]; d[3] = s4[3];
    }
    __syncthreads();
    int h = tid >> 2, xb = (tid & 3) * 16;
    float r0[24], r1[24], r2[24];
    #pragma unroll
    for (int k = 0; k < 6; k++) {
        *(float4*)&r0[k * 4] = *(const float4*)&sp[h + 0][xb + k * 4];
        *(float4*)&r1[k * 4] = *(const float4*)&sp[h + 1][xb + k * 4];
        *(float4*)&r2[k * 4] = *(const float4*)&sp[h + 2][xb + k * 4];
    }
    float acc[16];
    #pragma unroll
    for (int j = 0; j < 16; j++) {
        float a = r1[j + 4];
        a += wk[0] * r0[j + 3]; a += wk[1] * r0[j + 4]; a += wk[2] * r0[j + 5];
        a += wk[3] * r1[j + 3]; a += wk[4] * r1[j + 4]; a += wk[5] * r1[j + 5];
        a += wk[6] * r2[j + 3]; a += wk[7] * r2[j + 4]; a += wk[8] * r2[j + 5];
        acc[j] = a;
    }
    if (phase) {
        unsigned hbuf[8], lbuf[8];
        #pragma unroll
        for (int j = 0; j < 8; j++) {
            hbuf[j] = bfhi(acc[2 * j]) | (bfhi(acc[2 * j + 1]) << 16);
            lbuf[j] = bflo(acc[2 * j]) | (bflo(acc[2 * j + 1]) << 16);
        }
        size_t rowoff = ((size_t)slot * 2048 + bc) * 2048 + tid * 8;
        *(uint4*)(g_abH + rowoff) = *(uint4*)hbuf;
        *(uint4*)(g_abH + rowoff + 4) = *(uint4*)(hbuf + 4);
        *(uint4*)(g_abL + rowoff) = *(uint4*)lbuf;
        *(uint4*)(g_abL + rowoff + 4) = *(uint4*)(lbuf + 4);
    } else {
        float* dst = &g_t[slot][(size_t)bc * PLANE];
        int p = tid * 16;
        float psum = 0.f;
        #pragma unroll
        for (int j = 0; j < 16; j++) { acc[j] = fmaxf(acc[j], 0.f); psum += acc[j]; }
        #pragma unroll
        for (int k = 0; k < 4; k++)
            *(float4*)&dst[p + k * 4] = make_float4(acc[k*4], acc[k*4+1], acc[k*4+2], acc[k*4+3]);
        for (int off = 16; off; off >>= 1) psum += __shfl_xor_sync(0xffffffffu, psum, off);
        __shared__ float red[8];
        if ((tid & 31) == 0) red[tid >> 5] = psum;
        __syncthreads();
        if (tid < 32) {
            float r = (tid < 8) ? red[tid] : 0.f;
            for (int off = 4; off; off >>= 1) r += __shfl_xor_sync(0xffffffffu, r, off);
            if (tid == 0) g_pool[slot][bc] = r * (1.f / 4096.f);
        }
    }
}

// ---------------- align via mma.sync ----------------
#define ALN_BUF 36864
#define ALN_SMEM (2 * ALN_BUF + 1024)
__global__ void __launch_bounds__(256, 2) align_mma() {
    extern __shared__ char dynraw[];
    char* base = (char*)((((uintptr_t)dynraw) + 1023) & ~(uintptr_t)1023);
    int tid = threadIdx.x;
    int w = tid >> 5, lane = tid & 31;
    int b = blockIdx.x >> 5;
    int pix0 = (blockIdx.x & 31) * 128;

    float acc[4][4][4];
    #pragma unroll
    for (int mt = 0; mt < 4; mt++)
        #pragma unroll
        for (int nt = 0; nt < 4; nt++)
            #pragma unroll
            for (int r = 0; r < 4; r++) acc[mt][nt][r] = 0.f;

    auto fill = [&](int chunk, int buf) {
        char* bb = base + buf * ALN_BUF;
        for (int i = tid; i < 1024; i += 256) {
            int pl = i >> 9, r = i & 511;
            int cc = r >> 4, j = r & 15;
            int gc = chunk * 32 + cc;
            size_t row = (size_t)((gc >> 7) * 2048 + b * 128 + (gc & 127));
            const unsigned* src = (pl ? g_abL : g_abH) + row * 2048 + (pix0 >> 1) + j * 4;
            unsigned off = (unsigned)(cc * 256 + j * 16);
            unsigned sw = off ^ ((off >> 4) & 0xF0);
            cp16(smaddr(bb + pl * 8192) + sw, src);
        }
        for (int i = tid; i < 1280; i += 256) {
            int pl = i >= 640, r = pl ? i - 640 : i;
            int o = r / 5, j = r - o * 5;
            const unsigned char* src = g_awpk + (size_t)chunk * 20480 + pl * 10240 + o * 80 + j * 16;
            cp16(smaddr(bb + 16384 + pl * 10240) + o * 80 + j * 16, src);
        }
    };

    fill(0, 0);
    cp_commit(); cp_wait0();
    __syncthreads();

    int m0 = (w & 1) * 64, n0 = (w >> 1) * 32;
    for (int chunk = 0; chunk < 8; chunk++) {
        int buf = chunk & 1;
        if (chunk < 7) { fill(chunk + 1, buf ^ 1); cp_commit(); }
        char* bb = base + buf * ALN_BUF;
        unsigned aHiB = smaddr(bb), aLoB = smaddr(bb + 8192);
        unsigned bHiB = smaddr(bb + 16384), bLoB = smaddr(bb + 26624);
        #pragma unroll
        for (int kt = 0; kt < 2; kt++) {
            int c0 = kt * 16;
            unsigned bH[2][4], bL[2][4];
            #pragma unroll
            for (int nh = 0; nh < 2; nh++) {
                unsigned boff = (unsigned)((n0 + nh * 16 + (lane & 15)) * 80 + c0 * 2 + ((lane >> 4) << 4));
                ldsm4(bH[nh], bHiB + boff);
                ldsm4(bL[nh], bLoB + boff);
            }
            #pragma unroll
            for (int mt = 0; mt < 4; mt++) {
                unsigned aoff = (unsigned)(((lane & 7) + ((lane >> 4) << 3) + c0) * 256
                                           + (m0 + mt * 16 + (((lane >> 3) & 1) << 3)) * 2);
                unsigned asw = aoff ^ ((aoff >> 4) & 0xF0);
                unsigned aH[4], aL[4];
                ldsm4t(aH, aHiB + asw);
                ldsm4t(aL, aLoB + asw);
                #pragma unroll
                for (int nh = 0; nh < 2; nh++) {
                    float* dA = acc[mt][2 * nh];
                    float* dB = acc[mt][2 * nh + 1];
                    mma_bf16(dA, aH, bH[nh][0], bH[nh][2]);
                    mma_bf16(dB, aH, bH[nh][1], bH[nh][3]);
                    mma_bf16(dA, aH, bL[nh][0], bL[nh][2]);
                    mma_bf16(dB, aH, bL[nh][1], bL[nh][3]);
                    mma_bf16(dA, aL, bH[nh][0], bH[nh][2]);
                    mma_bf16(dB, aL, bH[nh][1], bH[nh][3]);
                }
            }
        }
        if (chunk < 7) cp_wait0();
        __syncthreads();
    }

    unsigned* fH = g_fuH + (size_t)b * PLANE * 64;
    unsigned* fL = g_fuL + (size_t)b * PLANE * 64;
    #pragma unroll
    for (int mt = 0; mt < 4; mt++) {
        #pragma unroll
        for (int nt = 0; nt < 4; nt++) {
            float* d = acc[mt][nt];
            int row = pix0 + m0 + mt * 16 + (lane >> 2);
            int op = ((n0 + nt * 8) >> 1) + (lane & 3);
            fH[(size_t)row * 64 + op] = bfhi(d[0]) | (bfhi(d[1]) << 16);
            fL[(size_t)row * 64 + op] = bflo(d[0]) | (bflo(d[1]) << 16);
            fH[(size_t)(row + 8) * 64 + op] = bfhi(d[2]) | (bfhi(d[3]) << 16);
            fL[(size_t)(row + 8) * 64 + op] = bflo(d[2]) | (bflo(d[3]) << 16);
        }
    }
}

// ---------------- upconv: resident A window, streamed B ----------------
// window: 4 rows x 66 slots x 64ch (one g-half), hi 33792B + lo 33792B
// B: 2 x 64KB double buffer.  total 198656 B
#define UPW_HI 0
#define UPW_LO 33792
#define UPW_B  67584
#define UPC_SMEM (198656 + 1024)
__global__ void __launch_bounds__(512, 1) upconv_mma() {
    extern __shared__ char dynraw[];
    char* base = (char*)((((uintptr_t)dynraw) + 1023) & ~(uintptr_t)1023);
    int tid = threadIdx.x;
    int w = tid >> 5, lane = tid & 31;
    int mi = w & 7, nh = w >> 3;
    int b = blockIdx.x >> 5;
    int y0 = (blockIdx.x & 31) * 2;

    const unsigned* fH = g_fuH + (size_t)b * PLANE * 64;
    const unsigned* fL = g_fuL + (size_t)b * PLANE * 64;

    float acc[4][4][4];
    #pragma unroll
    for (int s = 0; s < 4; s++)
        #pragma unroll
        for (int nf = 0; nf < 4; nf++)
            #pragma unroll
            for (int r = 0; r < 4; r++) acc[s][nf][r] = 0.f;

    unsigned winHi = smaddr(base + UPW_HI), winLo = smaddr(base + UPW_LO);

    auto fillWin = [&](int g) {
        // 264 slots x 8 cp16 x 2 planes = 4224
        for (int u = tid; u < 4224; u += 512) {
            int pl = u >= 2112;
            int rem = pl ? u - 2112 : u;
            int slot = rem >> 3, j = rem & 7;
            int r = slot / 66, xi = slot - r * 66;
            int gy = y0 + r - 1, gx = xi - 1;
            int valid = (((unsigned)gy < 64u) && ((unsigned)gx < 64u)) ? 1 : 0;
            const unsigned* src = (pl ? fL : fH) + ((size_t)(gy * 64 + gx) * 64 + g * 32 + j * 4);
            unsigned off = (unsigned)(slot * 128 + j * 16);
            unsigned sw = off ^ ((off >> 3) & 0x70);
            cp16z((pl ? winLo : winHi) + sw, src, valid);
        }
    };
    auto fillB = [&](int q, int buf) {
        int tap = q % 9, g = q / 9;
        const unsigned char* bsrc = g_wpack + (size_t)(tap * 2 + g) * 65536;
        unsigned bdst = smaddr(base + UPW_B + buf * 65536);
        #pragma unroll 4
        for (int i = tid; i < 4096; i += 512)
            cp16(bdst + i * 16, bsrc + i * 16);
    };

    fillWin(0);
    fillB(0, 0);
    cp_commit(); cp_wait0();
    __syncthreads();

    int mrowb = mi >> 2;                // pixel row within pair for this m-tile
    int mxb = (16 * mi) & 63;
    for (int q = 0; q < 18; q++) {
        int tap = q % 9;
        int kh = tap / 3, kw = tap - kh * 3;
        int buf = q & 1;
        if (q < 17 && q != 8) { fillB(q + 1, buf ^ 1); cp_commit(); }
        unsigned bB = smaddr(base + UPW_B + buf * 65536);
        #pragma unroll
        for (int kf = 0; kf < 4; kf++) {
            unsigned aH[4], aL[4];
            {
                int slot = (mrowb + kh) * 66 + mxb + (lane & 15) + kw;
                unsigned aoff = (unsigned)(slot * 128 + kf * 32 + ((lane >> 4) << 4));
                unsigned asw = aoff ^ ((aoff >> 3) & 0x70);
                ldsm4(aH, winHi + asw);
                ldsm4(aL, winLo + asw);
            }
            #pragma unroll
            for (int s = 0; s < 4; s++) {
                #pragma unroll
                for (int ng = 0; ng < 2; ng++) {
                    unsigned brow = (unsigned)(16 * (nh * 2 + ng) + (lane & 15));
                    unsigned boff = brow * 128 + kf * 32 + ((lane >> 4) << 4);
                    unsigned bsw = boff ^ ((boff >> 3) & 0x70);
                    unsigned bH[4], bL[4];
                    ldsm4(bH, bB + s * 16384 + bsw);
                    ldsm4(bL, bB + s * 16384 + 8192 + bsw);
                    float* dA = acc[s][2 * ng];
                    float* dB = acc[s][2 * ng + 1];
                    mma_bf16(dA, aH, bH[0], bH[2]);
                    mma_bf16(dB, aH, bH[1], bH[3]);
                    mma_bf16(dA, aH, bL[0], bL[2]);
                    mma_bf16(dB, aH, bL[1], bL[3]);
                    mma_bf16(dA, aL, bH[0], bH[2]);
                    mma_bf16(dB, aL, bH[1], bH[3]);
                }
            }
        }
        if (q == 8) {
            __syncthreads();           // all warps done with window g=0
            fillWin(1);
            fillB(9, buf ^ 1);
            cp_commit(); cp_wait0();
            __syncthreads();
        } else if (q < 17) {
            cp_wait0();
            __syncthreads();
        }
    }

    // epilogue: direct register -> packed hi/lo plane stores
    unsigned* uH = g_upH + (size_t)b * 16384 * 32;
    unsigned* uL = g_upL + (size_t)b * 16384 * 32;
    int m0 = 16 * mi + (lane >> 2);
    #pragma unroll
    for (int half = 0; half < 2; half++) {
        int mm = m0 + half * 8;
        int prow = mm >> 6, px = mm & 63;
        #pragma unroll
        for (int s = 0; s < 4; s++) {
            int y = 2 * (y0 + prow) + (s >> 1);
            int x2 = 2 * px + (s & 1);
            size_t rowbase = (size_t)(y * 128 + x2) * 32;
            #pragma unroll
            for (int nf = 0; nf < 4; nf++) {
                float* d = acc[s][nf];
                float v0 = d[half * 2], v1 = d[half * 2 + 1];
                int op = nh * 16 + nf * 4 + (lane & 3);
                uH[rowbase + op] = bfhi(v0) | (bfhi(v1) << 16);
                uL[rowbase + op] = bflo(v0) | (bflo(v1) << 16);
            }
        }
    }
}

// ---------------- reconv1 via mma, 512 threads, 2 rows/block ----------------
#define RC1_SMEM (66560 * 2 + 36864 + 1024)
__global__ void __launch_bounds__(512, 1) reconv1_mma() {
    extern __shared__ char dynraw[];
    char* base = (char*)((((uintptr_t)dynraw) + 1023) & ~(uintptr_t)1023);
    char* aHi = base;
    char* aLo = base + 66560;
    char* sB  = base + 133120;
    int tid = threadIdx.x;
    int w = tid >> 5, lane = tid & 31;
    int xt = w & 7, ys = w >> 3;
    int b = blockIdx.x >> 6;
    int y0 = (blockIdx.x & 63) * 2;
    const unsigned* uH = g_upH + (size_t)b * 16384 * 32;
    const unsigned* uL = g_upL + (size_t)b * 16384 * 32;

    {
        unsigned bdst = smaddr(sB);
        for (int i = tid; i < 2304; i += 512)
            cp16(bdst + i * 16, g_w1pack + i * 16);
    }
    unsigned aHiB = smaddr(aHi), aLoB = smaddr(aLo);
    for (int u = tid; u < 4160; u += 512) {
        int slot = u >> 3, j = u & 7;
        int r = slot / 130, xi = slot - r * 130;
        int gy = y0 + r - 1, gx = xi - 1;
        int valid = (((unsigned)gy < 128u) && ((unsigned)gx < 128u)) ? 1 : 0;
        size_t sidx = (size_t)(gy * 128 + gx) * 32 + j * 4;
        unsigned off = (unsigned)(slot * 128 + j * 16);
        unsigned sw = off ^ ((off >> 3) & 0x70);
        cp16z(aHiB + sw, uH + sidx, valid);
        cp16z(aLoB + sw, uL + sidx, valid);
    }
    cp_commit(); cp_wait0();
    __syncthreads();

    unsigned bB = smaddr(sB);
    float d[4] = {0.f, 0.f, 0.f, 0.f};
    int x0 = 16 * xt;
    for (int t = 0; t < 9; t++) {
        int kh = t / 3, kw = t - kh * 3;
        #pragma unroll
        for (int kf = 0; kf < 4; kf++) {
            unsigned bH[4], bL[4];
            unsigned boff = (unsigned)((lane & 15) * 128 + kf * 32 + ((lane >> 4) << 4));
            unsigned bsw = boff ^ ((boff >> 3) & 0x70);
            ldsm4(bH, bB + t * 4096 + bsw);
            ldsm4(bL, bB + t * 4096 + 2048 + bsw);
            int slot = (ys + kh) * 130 + x0 + (lane & 15) + kw;
            unsigned aoff = (unsigned)(slot * 128 + kf * 32 + ((lane >> 4) << 4));
            unsigned asw = aoff ^ ((aoff >> 3) & 0x70);
            unsigned aH[4], aL[4];
            ldsm4(aH, aHiB + asw);
            ldsm4(aL, aLoB + asw);
            mma_bf16(d, aH, bH[0], bH[2]);
            mma_bf16(d, aH, bL[0], bL[2]);
            mma_bf16(d, aL, bH[0], bH[2]);
        }
    }
    int r = lane >> 2, c = (lane & 3) * 2;
    int px = x0 + r;
    unsigned* tb = g_treb + ((size_t)b * 16384 + (y0 + ys) * 128) * 8;
    tb[px * 8 + c]           = packbf(fmaxf(d[0], 0.f));
    tb[px * 8 + c + 1]       = packbf(fmaxf(d[1], 0.f));
    tb[(px + 8) * 8 + c]     = packbf(fmaxf(d[2], 0.f));
    tb[(px + 8) * 8 + c + 1] = packbf(fmaxf(d[3], 0.f));
}

// ---------------- reconv2 via mma + residual reconstruction ----------------
#define RC2_SMEM (12480 + 22528 + 22528 + 22528 + 1024)
__global__ void __launch_bounds__(256, 2) reconv2_mma(float* __restrict__ out) {
    extern __shared__ char dynraw2[];
    char* base = (char*)((((uintptr_t)dynraw2) + 1023) & ~(uintptr_t)1023);
    unsigned* sTre = (unsigned*)base;
    char* aHi = base + 12480;
    char* aLo = base + 12480 + 22528;
    char* sB  = base + 12480 + 45056;
    int tid = threadIdx.x;
    int w = tid >> 5, lane = tid & 31;
    int b = blockIdx.x >> 7;
    int y = blockIdx.x & 127;
    const unsigned* tb = g_treb + (size_t)b * 16384 * 8;
    const unsigned* uH = g_upH + (size_t)b * 16384 * 32;
    const unsigned* uL = g_upL + (size_t)b * 16384 * 32;

    {
        unsigned bdst = smaddr(sB);
        for (int i = tid; i < 1408; i += 256)
            cp16(bdst + i * 16, g_w2pack + i * 16);
        cp_commit();
    }
    for (int u = tid; u < 780; u += 256) {
        int slot = u >> 1, hf = u & 1;
        int r = slot / 130, xi = slot - r * 130;
        int gy = y + r - 1, gx = xi - 1;
        uint4 v = make_uint4(0u,0u,0u,0u);
        if (((unsigned)gy < 128u) && ((unsigned)gx < 128u))
            v = *((const uint4*)(tb + (size_t)(gy * 128 + gx) * 8) + hf);
        *((uint4*)(sTre + slot * 8) + hf) = v;
    }
    __syncthreads();
    for (int u = tid; u < 1152; u += 256) {
        int x = u / 9, t = u - x * 9;
        int kh = t / 3, kw = t - kh * 3;
        const unsigned* src = sTre + (kh * 130 + x + kw) * 8;
        uint4 w0 = *(const uint4*)src;
        uint4 w1 = *(const uint4*)(src + 4);
        uint4 hi, lo;
        hi.x = prmt(w0.x, w0.y, 0x7632); hi.y = prmt(w0.z, w0.w, 0x7632);
        hi.z = prmt(w1.x, w1.y, 0x7632); hi.w = prmt(w1.z, w1.w, 0x7632);
        lo.x = prmt(w0.x, w0.y, 0x5410); lo.y = prmt(w0.z, w0.w, 0x5410);
        lo.z = prmt(w1.x, w1.y, 0x5410); lo.w = prmt(w1.z, w1.w, 0x5410);
        *(uint4*)(aHi + x * 176 + t * 16) = hi;
        *(uint4*)(aLo + x * 176 + t * 16) = lo;
    }
    for (int u = tid; u < 128; u += 256) {
        uint4 z = make_uint4(0u,0u,0u,0u);
        *(uint4*)(aHi + u * 176 + 144) = z;
        *(uint4*)(aLo + u * 176 + 144) = z;
    }
    cp_wait0();
    __syncthreads();

    unsigned aHiB = smaddr(aHi), aLoB = smaddr(aLo), bB = smaddr(sB);
    float acc[4][2][4];
    #pragma unroll
    for (int g = 0; g < 4; g++)
        #pragma unroll
        for (int nf = 0; nf < 2; nf++)
            #pragma unroll
            for (int r = 0; r < 4; r++) acc[g][nf][r] = 0.f;
    int x0 = 16 * w;
    #pragma unroll
    for (int kf = 0; kf < 5; kf++) {
        unsigned aH[4], aL[4];
        unsigned aoff = (unsigned)((x0 + (lane & 15)) * 176 + kf * 32 + ((lane >> 4) << 4));
        ldsm4(aH, aHiB + aoff);
        ldsm4(aL, aLoB + aoff);
        #pragma unroll
        for (int n0g = 0; n0g < 4; n0g++) {
            unsigned bH[4], bL[4];
            unsigned boff = (unsigned)((16 * n0g + (lane & 15)) * 176 + kf * 32 + ((lane >> 4) << 4));
            ldsm4(bH, bB + boff);
            ldsm4(bL, bB + 11264 + boff);
            float* dA = acc[n0g][0];
            float* dB = acc[n0g][1];
            mma_bf16(dA, aH, bH[0], bH[2]);
            mma_bf16(dB, aH, bH[1], bH[3]);
            mma_bf16(dA, aH, bL[0], bL[2]);
            mma_bf16(dB, aH, bL[1], bL[3]);
            mma_bf16(dA, aL, bH[0], bH[2]);
            mma_bf16(dB, aL, bH[1], bH[3]);
        }
    }
    __syncthreads();
    float* sD = (float*)aHi;
    {
        int r = lane >> 2, c = (lane & 3) * 2;
        int px = x0 + r;
        #pragma unroll
        for (int n0g = 0; n0g < 4; n0g++)
            #pragma unroll
            for (int nf = 0; nf < 2; nf++) {
                int o = n0g * 16 + nf * 8 + c;
                sD[px * 65 + o]           = acc[n0g][nf][0];
                sD[px * 65 + o + 1]       = acc[n0g][nf][1];
                sD[(px + 8) * 65 + o]     = acc[n0g][nf][2];
                sD[(px + 8) * 65 + o + 1] = acc[n0g][nf][3];
            }
    }
    __syncthreads();
    for (int i = tid; i < 4096; i += 256) {
        int x = i >> 5, op = i & 31;
        size_t idx = (size_t)(y * 128 + x) * 32 + op;
        unsigned h = uH[idx], l = uL[idx];
        float v0 = __uint_as_float(h << 16) + __uint_as_float(l << 16);
        float v1 = __uint_as_float(h & 0xffff0000u) + __uint_as_float(l & 0xffff0000u);
        sD[x * 65 + 2 * op]     += v0;
        sD[x * 65 + 2 * op + 1] += v1;
    }
    __syncthreads();
    for (int i = tid; i < 8192; i += 256) {
        int o = i >> 7, x = i & 127;
        out[((size_t)(b * 64 + o) * 128 + y) * 128 + x] = sD[x * 65 + o];
    }
}

// ---------------------------------------------------------------------------
extern "C" void kernel_launch(void* const* d_in, const int* in_sizes, int n_in,
                              void* d_out, int out_size) {
    const float* x1    = (const float*)d_in[0];
    const float* x2    = (const float*)d_in[1];
    const float* d1_w1 = (const float*)d_in[2];
    const float* d1_w2 = (const float*)d_in[3];
    const float* d2_w1 = (const float*)d_in[4];
    const float* d2_w2 = (const float*)d_in[5];
    const float* align_w = (const float*)d_in[6];
    const float* up_w1 = (const float*)d_in[7];
    const float* up_w2 = (const float*)d_in[8];
    const float* re_w1 = (const float*)d_in[9];
    const float* re_w2 = (const float*)d_in[10];
    float* out = (float*)d_out;

    static int smem_set = 0;
    if (!smem_set) {
        cudaFuncSetAttribute(align_mma, cudaFuncAttributeMaxDynamicSharedMemorySize, ALN_SMEM);
        cudaFuncSetAttribute(upconv_mma, cudaFuncAttributeMaxDynamicSharedMemorySize, UPC_SMEM);
        cudaFuncSetAttribute(reconv1_mma, cudaFuncAttributeMaxDynamicSharedMemorySize, RC1_SMEM);
        cudaFuncSetAttribute(reconv2_mma, cudaFuncAttributeMaxDynamicSharedMemorySize, RC2_SMEM);
        smem_set = 1;
    }

    packpool_kernel<<<550, 256>>>(align_w, up_w1, up_w2, re_w1, re_w2,
                                  x1, x2, d1_w1, d1_w2);
    dsc_kernel<<<4096, 256>>>(x1, x2, 0);
    mlp_kernel<<<32, 128>>>(d2_w1, d2_w2);
    dsc_kernel<<<4096, 256>>>(x1, x2, 1);
    align_mma<<<512, 256, ALN_SMEM>>>();
    upconv_mma<<<512, 512, UPC_SMEM>>>();
    reconv1_mma<<<1024, 512, RC1_SMEM>>>();
    reconv2_mma<<<2048, 256, RC2_SMEM>>>(out);
}